// round 11
// baseline (speedup 1.0000x reference)
#include <cuda_runtime.h>
#include <cuda_fp16.h>
#include <math.h>
#include <stdint.h>

#define B_  32
#define S_  1024
#define F0_ 2048
#define D_  768
#define L_  100
#define H_  8
#define HD_ 96
#define DF_ 10
#define C_  1000
#define BL_ (B_*L_)   // 3200
#define BS_ (B_*S_)   // 32768
#define NKV_ 1536
#define LP_ 128       // L padded to 128

// ---------------- scratch (static __device__, zero-initialized) ----------------
static __device__ __align__(128) float g_t  [L_*D_];
static __device__ __align__(128) float g_x2 [(size_t)BL_*D_];
static __device__ __align__(128) float g_t2 [(size_t)BL_*D_];
static __device__ __align__(128) float g_x3 [(size_t)BL_*D_];
static __device__ __align__(128) float g_h  [(size_t)BL_*D_];
static __device__ __align__(128) float g_yt [C_];
static __device__ __align__(128) float g_bkv[NKV_];
static __device__ __align__(128) float g_inv[B_*H_*LP_];          // 1/rowsum of exp
static __device__ __align__(128) float g_dpT[(size_t)C_*2*D_];    // transposed dup_pool
static __device__ __align__(128) float g_ascdump[(size_t)B_*L_*S_];

// fp16 planes
static __device__ __align__(128) __half g_q16 [H_*LP_*HD_];            // padded q, scale folded
static __device__ __align__(128) __half g_s16 [(size_t)B_*H_*LP_*S_];  // exp(scores)
static __device__ __align__(128) __half g_kv16[(size_t)BS_*NKV_];      // k | v fp16, pitch 1536
static __device__ __align__(128) __half g_xh  [(size_t)BS_*F0_];
static __device__ __align__(128) __half g_memh[(size_t)BS_*D_];
static __device__ __align__(128) __half g_aoh [(size_t)BL_*D_];
static __device__ __align__(128) __half g_t2h [(size_t)BL_*D_];
static __device__ __align__(128) __half g_f1h [(size_t)BL_*D_];
static __device__ __align__(128) __half g_wemb[(size_t)D_*F0_];
static __device__ __align__(128) __half g_wkv [(size_t)NKV_*D_];
static __device__ __align__(128) __half g_wo  [(size_t)D_*D_];
static __device__ __align__(128) __half g_w1  [(size_t)D_*D_];
static __device__ __align__(128) __half g_w2  [(size_t)D_*D_];

// ============================================================================
// PTX helpers (sm_80-era baseline; safe on non-'a' compute_103 PTX target)
// ============================================================================
__device__ __forceinline__ uint32_t smem_u32(const void* p) {
    uint32_t a;
    asm("{ .reg .u64 t; cvta.to.shared.u64 t, %1; cvt.u32.u64 %0, t; }" : "=r"(a) : "l"(p));
    return a;
}
#define LDSM4(r, addr)                                                            \
    asm volatile("ldmatrix.sync.aligned.m8n8.x4.shared.b16 {%0,%1,%2,%3}, [%4];"  \
        : "=r"((r)[0]), "=r"((r)[1]), "=r"((r)[2]), "=r"((r)[3]) : "r"(addr))
#define MMAF16(c, a, b0, b1)                                                      \
    asm volatile("mma.sync.aligned.m16n8k16.row.col.f32.f16.f16.f32 "             \
        "{%0,%1,%2,%3}, {%4,%5,%6,%7}, {%8,%9}, {%0,%1,%2,%3};"                   \
        : "+f"((c)[0]), "+f"((c)[1]), "+f"((c)[2]), "+f"((c)[3])                  \
        : "r"((a)[0]), "r"((a)[1]), "r"((a)[2]), "r"((a)[3]), "r"(b0), "r"(b1))
#define CP16(dst, src)                                                            \
    asm volatile("cp.async.cg.shared.global [%0], [%1], 16;" :: "r"(dst), "l"(src))
#define CP_COMMIT() asm volatile("cp.async.commit_group;" ::: "memory")
#define CP_WAIT(n)  asm volatile("cp.async.wait_group %0;" :: "n"(n) : "memory")

// swizzle for 64B logical rows packed 2-per-128B line (conflict-free ldmatrix)
__device__ __forceinline__ uint32_t swz_addr(uint32_t base, int r, int kb) {
    uint32_t line = (uint32_t)r >> 1;
    uint32_t slot = ((((uint32_t)r & 1u) << 2) | (uint32_t)kb) ^ (line & 7u);
    return base + line * 128u + slot * 16u;
}

// fast exp on FMA pipe: exp(x) = 2^(x*log2e), deg-5 Taylor; clamped so fp16 store
// cannot overflow (2^15.5 = 46341 < 65504)
__device__ __forceinline__ float fexp(float x) {
    float p = x * 1.4426950408889634f;
    p = fmaxf(fminf(p, 15.5f), -120.0f);
    float nf = rintf(p);
    float f = p - nf;
    float r = 0.0013333558146428443f;
    r = fmaf(r, f, 0.009618129107628477f);
    r = fmaf(r, f, 0.05550410866482158f);
    r = fmaf(r, f, 0.2402265069591007f);
    r = fmaf(r, f, 0.6931471805599453f);
    r = fmaf(r, f, 1.0f);
    return r * __int_as_float(((int)nf + 127) << 23);
}

// ============================================================================
// Generalized 1-pass fp16 HMMA GEMM: C = act(A * B^T + bias [+ res])
// MT: CTA M-tile (128 or 64). N-tile fixed 128. 128 threads, 2x2 warps.
// Strided A/B/C; per-blockIdx.z offsets: h=z&7, b=z>>3:
//   A += h*oAh;  B += b*oBb + h*oBh;  C/Chi += z*oC.
// EXP: apply fexp in epilogue (for fused exp(scores)).
// ============================================================================
template<int MT>
__device__ __forceinline__ void load_stage(uint32_t sbase,
    const __half* __restrict__ Ah, const __half* __restrict__ Bw,
    int bm, int bn, int lda, int ldb, int k0, int tid)
{
    if (MT == 128 || tid < MT) {
        const __half* pa = Ah + (size_t)(bm + tid) * lda + k0;
        #pragma unroll
        for (int kb = 0; kb < 4; kb++)
            CP16(swz_addr(sbase, tid, kb), pa + kb * 8);
    }
    const __half* pb = Bw + (size_t)(bn + tid) * ldb + k0;
    #pragma unroll
    for (int kb = 0; kb < 4; kb++)
        CP16(swz_addr(sbase + (uint32_t)MT * 64u, tid, kb), pb + kb * 8);
    CP_COMMIT();
}

template<int MT, bool RELU, int RES, bool BIAS, bool EXP>
__global__ void __launch_bounds__(128, 2)
gemm16(const __half* __restrict__ Ah, const __half* __restrict__ Bw,
       const float* __restrict__ bias, const float* __restrict__ Res,
       float* __restrict__ C, __half* __restrict__ Chi,
       int K, int lda, int ldb, int ldc, int resMod,
       size_t oAh, size_t oBb, size_t oBh, size_t oC)
{
    constexpr int NMT = MT / 32;                    // mt tiles per warp
    constexpr uint32_t STG = (uint32_t)MT * 64u + 8192u;
    extern __shared__ char smem[];
    const uint32_t sb = smem_u32(smem);
    const int tid = threadIdx.x, lane = tid & 31, wid = tid >> 5;
    const int wm = wid & 1, wn = wid >> 1;          // 2x2 warps
    const int bm = blockIdx.y * MT, bn = blockIdx.x * 128;
    const int z = blockIdx.z, hz = z & 7, bz = z >> 3;
    Ah += (size_t)hz * oAh;
    Bw += (size_t)bz * oBb + (size_t)hz * oBh;
    const size_t coff = (size_t)z * oC;
    const int nc = K >> 5;

    float c[NMT][8][4];
    #pragma unroll
    for (int mt = 0; mt < NMT; mt++)
        #pragma unroll
        for (int nt = 0; nt < 8; nt++)
            #pragma unroll
            for (int q = 0; q < 4; q++) c[mt][nt][q] = 0.0f;

    uint32_t offA[NMT][2], offB[2][2][2];
    {
        const int aR = lane & 15, aKb = lane >> 4;
        const int bR = (lane & 7) | ((lane >> 4) << 3);
        const int bKb = (lane >> 3) & 1;
        #pragma unroll
        for (int mt = 0; mt < NMT; mt++)
            #pragma unroll
            for (int ks = 0; ks < 2; ks++)
                offA[mt][ks] = swz_addr(0, wm * (MT / 2) + mt * 16 + aR, ks * 2 + aKb);
        #pragma unroll
        for (int nh = 0; nh < 2; nh++)
            #pragma unroll
            for (int p = 0; p < 2; p++)
                #pragma unroll
                for (int ks = 0; ks < 2; ks++)
                    offB[nh][p][ks] = (uint32_t)MT * 64u +
                        swz_addr(0, wn * 64 + nh * 32 + p * 16 + bR, ks * 2 + bKb);
    }

    #pragma unroll
    for (int s = 0; s < 3; s++)
        load_stage<MT>(sb + s * STG, Ah, Bw, bm, bn, lda, ldb, s * 32, tid);

    for (int i = 0; i < nc; i++) {
        CP_WAIT(2);
        __syncthreads();
        if (i + 3 < nc)
            load_stage<MT>(sb + (uint32_t)((i + 3) & 3) * STG, Ah, Bw,
                           bm, bn, lda, ldb, (i + 3) * 32, tid);
        else
            CP_COMMIT();     // keep group count exact (no tail race)
        const uint32_t st = sb + (uint32_t)(i & 3) * STG;
        #pragma unroll
        for (int ks = 0; ks < 2; ks++) {
            uint32_t aF[NMT][4];
            #pragma unroll
            for (int mt = 0; mt < NMT; mt++) LDSM4(aF[mt], st + offA[mt][ks]);
            #pragma unroll
            for (int nh = 0; nh < 2; nh++) {
                uint32_t bf[2][4];
                #pragma unroll
                for (int p = 0; p < 2; p++) LDSM4(bf[p], st + offB[nh][p][ks]);
                #pragma unroll
                for (int mt = 0; mt < NMT; mt++)
                    #pragma unroll
                    for (int nt = 0; nt < 4; nt++)
                        MMAF16(c[mt][nh * 4 + nt], aF[mt],
                               bf[nt >> 1][(nt & 1) * 2], bf[nt >> 1][(nt & 1) * 2 + 1]);
            }
        }
    }

    #pragma unroll
    for (int mt = 0; mt < NMT; mt++) {
        #pragma unroll
        for (int hh = 0; hh < 2; hh++) {
            const int m = bm + wm * (MT / 2) + mt * 16 + (lane >> 2) + hh * 8;
            const float* resRow = (RES == 1) ? (Res + (size_t)m * ldc)
                                : (RES == 2) ? (Res + (size_t)(m % resMod) * ldc)
                                : nullptr;
            #pragma unroll
            for (int nt = 0; nt < 8; nt++) {
                const int n = bn + wn * 64 + nt * 8 + (lane & 3) * 2;
                float vx = c[mt][nt][hh * 2 + 0];
                float vy = c[mt][nt][hh * 2 + 1];
                if (BIAS) { vx += bias[n]; vy += bias[n + 1]; }
                if (RES != 0) { vx += resRow[n]; vy += resRow[n + 1]; }
                if (RELU) { vx = fmaxf(vx, 0.f); vy = fmaxf(vy, 0.f); }
                if (EXP)  { vx = fexp(vx); vy = fexp(vy); }
                if (C) *(float2*)(C + coff + (size_t)m * ldc + n) = make_float2(vx, vy);
                if (Chi)
                    *(__half2*)(Chi + coff + (size_t)m * ldc + n) = __floats2half2_rn(vx, vy);
            }
        }
    }
}

// ============================================================================
// attn_v: ao[b,l,h*96+:] = (exp[bh,l,:] @ V[b,:,h*96+:]) * inv[bh,l]
// ============================================================================
#define AVS_A 8192u
#define AVS_V 6144u
#define AV_SMEM (4u*AVS_A + 2u*AVS_V)   // 45056

__global__ void __launch_bounds__(128, 2)
attn_v_mma(const __half* __restrict__ probs, const __half* __restrict__ kv16,
           const float* __restrict__ inv, __half* __restrict__ aoh)
{
    extern __shared__ char smem[];
    const uint32_t sb = smem_u32(smem);
    const int tid = threadIdx.x, lane = tid & 31, wid = tid >> 5;
    const int wm = wid & 1, wn = wid >> 1;
    const int bh = blockIdx.x, b = bh >> 3, h = bh & 7;
    const __half* A = probs + (size_t)bh * LP_ * S_;
    const __half* V = kv16 + (size_t)b * S_ * NKV_ + D_ + h * HD_;

    float c[4][6][4];
    #pragma unroll
    for (int mt = 0; mt < 4; mt++)
        #pragma unroll
        for (int nt = 0; nt < 6; nt++)
            #pragma unroll
            for (int q = 0; q < 4; q++) c[mt][nt][q] = 0.0f;

    uint32_t offA[4][2], offB[3][2];
    {
        const int aR = lane & 15, aKb = lane >> 4;
        #pragma unroll
        for (int mt = 0; mt < 4; mt++)
            #pragma unroll
            for (int ks = 0; ks < 2; ks++)
                offA[mt][ks] = swz_addr(0, wm * 64 + mt * 16 + aR, ks * 2 + aKb);
        const int bR = (lane & 7) | ((lane >> 4) << 3);
        const int bKb = (lane >> 3) & 1;
        #pragma unroll
        for (int nb = 0; nb < 3; nb++)
            #pragma unroll
            for (int ks = 0; ks < 2; ks++)
                offB[nb][ks] = swz_addr(0, wn * 48 + nb * 16 + bR, ks * 2 + bKb);
    }

    int qs[6], qh[6];
    #pragma unroll
    for (int q = 0; q < 6; q++) {
        const int idx = tid + q * 128;
        qs[q] = (idx / 48) * 2;
        qh[q] = (idx % 48) * 2;
    }

    uint32_t vlo[6], vhi[6];
    const int nChunks = S_ / 32;

    #pragma unroll
    for (int s = 0; s < 3; s++) {
        const __half* pa = A + (size_t)tid * S_ + s * 32;
        const uint32_t dst = sb + (uint32_t)s * AVS_A;
        #pragma unroll
        for (int kb = 0; kb < 4; kb++) CP16(swz_addr(dst, tid, kb), pa + kb * 8);
        CP_COMMIT();
    }
    {
        #pragma unroll
        for (int q = 0; q < 6; q++) {
            const __half* p = V + (size_t)qs[q] * NKV_ + qh[q];
            const uint32_t v0 = *(const uint32_t*)p;
            const uint32_t v1 = *(const uint32_t*)(p + NKV_);
            vlo[q] = __byte_perm(v0, v1, 0x5410);
            vhi[q] = __byte_perm(v0, v1, 0x7632);
        }
        char* vbuf = smem + 4 * AVS_A;
        #pragma unroll
        for (int q = 0; q < 6; q++) {
            const uint32_t o0 = swz_addr(0, qh[q],     qs[q] >> 3) + ((qs[q] * 2) & 15);
            const uint32_t o1 = swz_addr(0, qh[q] + 1, qs[q] >> 3) + ((qs[q] * 2) & 15);
            *(uint32_t*)(vbuf + o0) = vlo[q];
            *(uint32_t*)(vbuf + o1) = vhi[q];
        }
    }
    CP_WAIT(2);
    __syncthreads();

    for (int i = 0; i < nChunks; i++) {
        if (i + 1 < nChunks) {
            const int k0 = (i + 1) * 32;
            #pragma unroll
            for (int q = 0; q < 6; q++) {
                const __half* p = V + (size_t)(k0 + qs[q]) * NKV_ + qh[q];
                const uint32_t v0 = *(const uint32_t*)p;
                const uint32_t v1 = *(const uint32_t*)(p + NKV_);
                vlo[q] = __byte_perm(v0, v1, 0x5410);
                vhi[q] = __byte_perm(v0, v1, 0x7632);
            }
        }
        const uint32_t stA = sb + (uint32_t)(i & 3) * AVS_A;
        const uint32_t stV = sb + 4u * AVS_A + (uint32_t)(i & 1) * AVS_V;
        #pragma unroll
        for (int ks = 0; ks < 2; ks++) {
            uint32_t aF[4][4], bf[3][4];
            #pragma unroll
            for (int mt = 0; mt < 4; mt++) LDSM4(aF[mt], stA + offA[mt][ks]);
            #pragma unroll
            for (int nb = 0; nb < 3; nb++) LDSM4(bf[nb], stV + offB[nb][ks]);
            #pragma unroll
            for (int mt = 0; mt < 4; mt++)
                #pragma unroll
                for (int nt = 0; nt < 6; nt++)
                    MMAF16(c[mt][nt], aF[mt],
                           bf[nt >> 1][(nt & 1) * 2], bf[nt >> 1][(nt & 1) * 2 + 1]);
        }
        if (i + 3 < nChunks) {
            const __half* pa = A + (size_t)tid * S_ + (i + 3) * 32;
            const uint32_t dst = sb + (uint32_t)((i + 3) & 3) * AVS_A;
            #pragma unroll
            for (int kb = 0; kb < 4; kb++) CP16(swz_addr(dst, tid, kb), pa + kb * 8);
        }
        CP_COMMIT();
        if (i + 1 < nChunks) {
            char* vbuf = smem + 4 * AVS_A + ((i + 1) & 1) * AVS_V;
            #pragma unroll
            for (int q = 0; q < 6; q++) {
                const uint32_t o0 = swz_addr(0, qh[q],     qs[q] >> 3) + ((qs[q] * 2) & 15);
                const uint32_t o1 = swz_addr(0, qh[q] + 1, qs[q] >> 3) + ((qs[q] * 2) & 15);
                *(uint32_t*)(vbuf + o0) = vlo[q];
                *(uint32_t*)(vbuf + o1) = vhi[q];
            }
            CP_WAIT(2);
            __syncthreads();
        }
    }

    #pragma unroll
    for (int mt = 0; mt < 4; mt++) {
        #pragma unroll
        for (int hh = 0; hh < 2; hh++) {
            const int m = wm * 64 + mt * 16 + (lane >> 2) + hh * 8;
            if (m < L_) {
                const float sc = inv[bh * LP_ + m];
                __half* orow = aoh + ((size_t)b * L_ + m) * D_ + h * HD_;
                #pragma unroll
                for (int nt = 0; nt < 6; nt++) {
                    const int n = wn * 48 + nt * 8 + (lane & 3) * 2;
                    *(__half2*)(orow + n) = __floats2half2_rn(
                        c[mt][nt][hh * 2] * sc, c[mt][nt][hh * 2 + 1] * sc);
                }
            }
        }
    }
}

// ---------------- converters ----------------
__global__ void cvt_h16(const float* __restrict__ in, __half* __restrict__ out, int n4)
{
    int i = blockIdx.x * 256 + threadIdx.x;
    if (i >= n4) return;
    float4 f = ((const float4*)in)[i];
    ((__half2*)out)[i * 2 + 0] = __floats2half2_rn(f.x, f.y);
    ((__half2*)out)[i * 2 + 1] = __floats2half2_rn(f.z, f.w);
}
__global__ void concat_bias(const float* __restrict__ bk, const float* __restrict__ bv,
                            float* __restrict__ bkv)
{
    int i = blockIdx.x * 256 + threadIdx.x;
    if (i < D_) bkv[i] = bk[i];
    else if (i < NKV_) bkv[i] = bv[i - D_];
}
// transpose dup_pool: dp[l][d][f] -> dpT[l*10+f][d], d in [0,1536)
__global__ void transpose_dp(const float* __restrict__ dp, float* __restrict__ dpT)
{
    __shared__ float sm[384 * DF_];
    const int l = blockIdx.x, d0 = blockIdx.y * 384;
    const float* src = dp + (size_t)l * (2 * D_) * DF_ + (size_t)d0 * DF_;
    for (int i = threadIdx.x; i < 384 * DF_; i += 256) sm[i] = src[i];
    __syncthreads();
    for (int i = threadIdx.x; i < 384 * DF_; i += 256) {
        const int f = i / 384, d = i - f * 384;
        dpT[(size_t)(l * DF_ + f) * (2 * D_) + d0 + d] = sm[d * DF_ + f];
    }
}

// ---------------- block reduction ----------------
__device__ __forceinline__ float blockSum256(float v, float* sm) {
    #pragma unroll
    for (int o = 16; o > 0; o >>= 1) v += __shfl_xor_sync(0xffffffffu, v, o);
    const int w = threadIdx.x >> 5, lane = threadIdx.x & 31;
    if (lane == 0) sm[w] = v;
    __syncthreads();
    float r = (lane < 8) ? sm[lane] : 0.0f;
    #pragma unroll
    for (int o = 4; o > 0; o >>= 1) r += __shfl_xor_sync(0xffffffffu, r, o);
    r = __shfl_sync(0xffffffffu, r, 0);
    __syncthreads();
    return r;
}

// ---------------- row LayerNorm; optional fp16 output ----------------
__global__ void ln_rows(const float* __restrict__ X, const float* __restrict__ gg,
                        const float* __restrict__ bb, float* __restrict__ O, float alpha,
                        __half* __restrict__ Oh)
{
    __shared__ float sm[8];
    const int row = blockIdx.x;
    const float* x = X + (size_t)row * D_;
    float v[3];
    float s = 0.0f, sq = 0.0f;
    #pragma unroll
    for (int j = 0; j < 3; j++) {
        v[j] = alpha * x[threadIdx.x + j * 256];
        s += v[j]; sq += v[j] * v[j];
    }
    s  = blockSum256(s, sm);
    sq = blockSum256(sq, sm);
    const float mean = s * (1.0f / D_);
    const float var  = sq * (1.0f / D_) - mean * mean;
    const float inv  = rsqrtf(var + 1e-5f);
    float* o = O + (size_t)row * D_;
    #pragma unroll
    for (int j = 0; j < 3; j++) {
        const int i = threadIdx.x + j * 256;
        const float ov = (v[j] - mean) * inv * gg[i] + bb[i];
        o[i] = ov;
        if (Oh) Oh[(size_t)row * D_ + i] = __float2half_rn(ov);
    }
}

// ---------------- q projection -> fp16 padded [H][128][96], scale folded ----------------
__global__ void qproj(const float* __restrict__ t, const float* __restrict__ Wq,
                      const float* __restrict__ bq, __half* __restrict__ q16)
{
    const int l = blockIdx.x;
    const int e = blockIdx.y * 128 + threadIdx.x;
    __shared__ float ts[D_];
    for (int i = threadIdx.x; i < D_; i += 128) ts[i] = t[(size_t)l * D_ + i];
    __syncthreads();
    const float* w = Wq + (size_t)e * D_;
    float acc = 0.0f;
    #pragma unroll 8
    for (int d = 0; d < D_; d++) acc = fmaf(ts[d], w[d], acc);
    const float val = (acc + bq[e]) * 0.10206207261596575f;   // 1/sqrt(96)
    const int hh = e / HD_, eh = e - hh * HD_;
    q16[(size_t)hh * LP_ * HD_ + (size_t)l * HD_ + eh] = __float2half_rn(val);
}

// ---------------- row sums of exp + head-mean a_score (no prob write-back) ----
__global__ void sum_mean(const __half* __restrict__ s16, float* __restrict__ invO,
                         float* __restrict__ ascore)
{
    __shared__ float sm[8];
    const int l = blockIdx.x, b = blockIdx.y;
    const int tid = threadIdx.x;
    float am[4] = {0.f, 0.f, 0.f, 0.f};
    for (int h = 0; h < H_; h++) {
        const int bh = b * H_ + h;
        const __half* row = s16 + ((size_t)bh * LP_ + l) * S_;
        float v[4];
        float ssum = 0.0f;
        #pragma unroll
        for (int j = 0; j < 4; j++) { v[j] = __half2float(row[tid + j * 256]); ssum += v[j]; }
        ssum = blockSum256(ssum, sm);
        const float inv = 1.0f / ssum;
        if (tid == 0) invO[bh * LP_ + l] = inv;
        #pragma unroll
        for (int j = 0; j < 4; j++) am[j] += v[j] * inv * (1.0f / H_);
    }
    float* ao = ascore + ((size_t)b * L_ + l) * S_;
    #pragma unroll
    for (int j = 0; j < 4; j++) ao[tid + j * 256] = am[j];
}

// ---------------- GroupFC terms on transposed pool (coalesced) ----------------
__global__ void yterm_kernel(const float* __restrict__ y, const float* __restrict__ dpT,
                             const float* __restrict__ dbias, float* __restrict__ yt)
{
    const int l = blockIdx.x;
    const int w = threadIdx.x >> 5, lane = threadIdx.x & 31;    // 10 warps
    const float* row = dpT + (size_t)(l * DF_ + w) * (2 * D_) + D_;
    const float* yr = y + (size_t)l * D_;
    float acc = 0.0f;
    for (int d = lane; d < D_; d += 32) acc = fmaf(yr[d], row[d], acc);
    #pragma unroll
    for (int o = 16; o > 0; o >>= 1) acc += __shfl_xor_sync(0xffffffffu, acc, o);
    if (lane == 0) yt[l * DF_ + w] = acc + dbias[l * DF_ + w];
}

__global__ void logits_kernel(const float* __restrict__ hh, const float* __restrict__ dpT,
                              const float* __restrict__ yt, float* __restrict__ out)
{
    const int l = blockIdx.x, b = blockIdx.y;
    const int w = threadIdx.x >> 5, lane = threadIdx.x & 31;    // 10 warps
    __shared__ float hs[D_];
    for (int i = threadIdx.x; i < D_; i += 320) hs[i] = hh[((size_t)b * L_ + l) * D_ + i];
    __syncthreads();
    const float* row = dpT + (size_t)(l * DF_ + w) * (2 * D_);
    float acc = 0.0f;
    for (int d = lane; d < D_; d += 32) acc = fmaf(hs[d], row[d], acc);
    #pragma unroll
    for (int o = 16; o > 0; o >>= 1) acc += __shfl_xor_sync(0xffffffffu, acc, o);
    if (lane == 0) out[(size_t)b * C_ + l * DF_ + w] = acc + yt[l * DF_ + w];
}

// ---------------- host launch ----------------
#define GM_SMEM_128 65536u
#define GM_SMEM_64  49152u

extern "C" void kernel_launch(void* const* d_in, const int* in_sizes, int n_in,
                              void* d_out, int out_size)
{
    const float* x       = (const float*)d_in[0];
    const float* y       = (const float*)d_in[1];
    const float* embed_W = (const float*)d_in[2];
    const float* embed_b = (const float*)d_in[3];
    const float* Wq      = (const float*)d_in[4];
    const float* Wk      = (const float*)d_in[5];
    const float* Wv      = (const float*)d_in[6];
    const float* bq      = (const float*)d_in[7];
    const float* bk      = (const float*)d_in[8];
    const float* bv      = (const float*)d_in[9];
    const float* Wo      = (const float*)d_in[10];
    const float* bo      = (const float*)d_in[11];
    const float* ln1_g   = (const float*)d_in[12];
    const float* ln1_b   = (const float*)d_in[13];
    const float* ln2_g   = (const float*)d_in[14];
    const float* ln2_b   = (const float*)d_in[15];
    const float* ln3_g   = (const float*)d_in[16];
    const float* ln3_b   = (const float*)d_in[17];
    const float* W1      = (const float*)d_in[18];
    const float* b1      = (const float*)d_in[19];
    const float* W2      = (const float*)d_in[20];
    const float* b2      = (const float*)d_in[21];
    const float* dp      = (const float*)d_in[22];
    const float* dbias   = (const float*)d_in[23];
    float* out = (float*)d_out;

    float *pt, *px2, *pt2, *px3, *ph, *pyt, *pbkv, *pinv, *pdpT, *pdump;
    __half *pq16, *ps16, *pkv16, *pxh, *pmemh, *paoh, *pt2h, *pf1h;
    __half *pwemb, *pwkv, *pwo, *pw1, *pw2;
    cudaGetSymbolAddress((void**)&pt,    g_t);
    cudaGetSymbolAddress((void**)&px2,   g_x2);
    cudaGetSymbolAddress((void**)&pt2,   g_t2);
    cudaGetSymbolAddress((void**)&px3,   g_x3);
    cudaGetSymbolAddress((void**)&ph,    g_h);
    cudaGetSymbolAddress((void**)&pyt,   g_yt);
    cudaGetSymbolAddress((void**)&pbkv,  g_bkv);
    cudaGetSymbolAddress((void**)&pinv,  g_inv);
    cudaGetSymbolAddress((void**)&pdpT,  g_dpT);
    cudaGetSymbolAddress((void**)&pdump, g_ascdump);
    cudaGetSymbolAddress((void**)&pq16,  g_q16);
    cudaGetSymbolAddress((void**)&ps16,  g_s16);
    cudaGetSymbolAddress((void**)&pkv16, g_kv16);
    cudaGetSymbolAddress((void**)&pxh,   g_xh);
    cudaGetSymbolAddress((void**)&pmemh, g_memh);
    cudaGetSymbolAddress((void**)&paoh,  g_aoh);
    cudaGetSymbolAddress((void**)&pt2h,  g_t2h);
    cudaGetSymbolAddress((void**)&pf1h,  g_f1h);
    cudaGetSymbolAddress((void**)&pwemb, g_wemb);
    cudaGetSymbolAddress((void**)&pwkv,  g_wkv);
    cudaGetSymbolAddress((void**)&pwo,   g_wo);
    cudaGetSymbolAddress((void**)&pw1,   g_w1);
    cudaGetSymbolAddress((void**)&pw2,   g_w2);

    cudaFuncSetAttribute(gemm16<128, true, 0, true, false>,  cudaFuncAttributeMaxDynamicSharedMemorySize, GM_SMEM_128);
    cudaFuncSetAttribute(gemm16<128, false, 0, true, false>, cudaFuncAttributeMaxDynamicSharedMemorySize, GM_SMEM_128);
    cudaFuncSetAttribute(gemm16<128, false, 0, false, true>, cudaFuncAttributeMaxDynamicSharedMemorySize, GM_SMEM_128);
    cudaFuncSetAttribute(gemm16<64, false, 2, true, false>,  cudaFuncAttributeMaxDynamicSharedMemorySize, GM_SMEM_64);
    cudaFuncSetAttribute(gemm16<64, true, 0, true, false>,   cudaFuncAttributeMaxDynamicSharedMemorySize, GM_SMEM_64);
    cudaFuncSetAttribute(gemm16<64, false, 1, true, false>,  cudaFuncAttributeMaxDynamicSharedMemorySize, GM_SMEM_64);
    cudaFuncSetAttribute(attn_v_mma, cudaFuncAttributeMaxDynamicSharedMemorySize, AV_SMEM);

    float* asc = (out_size >= B_ * C_ + B_ * L_ * S_) ? (out + B_ * C_) : pdump;

    // ---- launches 1-5: only what embed needs (embed is launch #6 -> ncu -s 5 -c 1) ----
    cvt_h16<<<(BS_ * F0_ / 4 + 255) / 256, 256>>>(x, pxh, BS_ * F0_ / 4);          // 1
    cvt_h16<<<(D_ * F0_ / 4 + 255) / 256, 256>>>(embed_W, pwemb, D_ * F0_ / 4);    // 2
    cvt_h16<<<(D_ * D_ / 4 + 255) / 256, 256>>>(Wk, pwkv, D_ * D_ / 4);            // 3
    cvt_h16<<<(D_ * D_ / 4 + 255) / 256, 256>>>(Wv, pwkv + (size_t)D_ * D_, D_ * D_ / 4); // 4
    concat_bias<<<(NKV_ + 255) / 256, 256>>>(bk, bv, pbkv);                        // 5

    // ---- 6: mem = relu(x @ We^T + eb) -> fp16  [PROFILED KERNEL] ----
    gemm16<128, true, 0, true, false><<<dim3(D_ / 128, BS_ / 128, 1), 128, GM_SMEM_128>>>(
        pxh, pwemb, embed_b, nullptr, nullptr, pmemh,
        F0_, F0_, F0_, D_, 0, 0, 0, 0, 0);

    // ---- remaining conversions / preamble ----
    cvt_h16<<<(D_ * D_ / 4 + 255) / 256, 256>>>(Wo, pwo, D_ * D_ / 4);
    cvt_h16<<<(D_ * D_ / 4 + 255) / 256, 256>>>(W1, pw1, D_ * D_ / 4);
    cvt_h16<<<(D_ * D_ / 4 + 255) / 256, 256>>>(W2, pw2, D_ * D_ / 4);
    transpose_dp<<<dim3(L_, 4), 256>>>(dp, pdpT);
    ln_rows<<<L_, 256>>>(y, ln1_g, ln1_b, pt, 2.0f, nullptr);              // t = LN(2y)
    qproj<<<dim3(L_, D_ / 128), 128>>>(pt, Wq, bq, pq16);
    yterm_kernel<<<L_, 320>>>(y, pdpT, dbias, pyt);

    // ---- fused K|V GEMM -> fp16 kv (pitch 1536) ----
    gemm16<128, false, 0, true, false><<<dim3(NKV_ / 128, BS_ / 128, 1), 128, GM_SMEM_128>>>(
        pmemh, pwkv, pbkv, nullptr, nullptr, pkv16,
        D_, D_, D_, NKV_, 0, 0, 0, 0, 0);

    // ---- scores + fused exp: per (b,h) GEMM -> exp(s) fp16 ----
    gemm16<128, false, 0, false, true><<<dim3(S_ / 128, 1, B_ * H_), 128, GM_SMEM_128>>>(
        pq16, pkv16, nullptr, nullptr, nullptr, ps16,
        HD_, HD_, NKV_, S_, 0,
        (size_t)LP_ * HD_, (size_t)S_ * NKV_, (size_t)HD_, (size_t)LP_ * S_);

    // ---- row sums + head-mean a_score ----
    sum_mean<<<dim3(L_, B_), 256>>>(ps16, pinv, asc);

    // ---- (exp @ V) * inv -> ao fp16 ----
    attn_v_mma<<<B_ * H_, 128, AV_SMEM>>>(ps16, pkv16, pinv, paoh);

    // ---- out-proj + residual t[l], LN2 ----
    gemm16<64, false, 2, true, false><<<dim3(D_ / 128, BL_ / 64, 1), 128, GM_SMEM_64>>>(
        paoh, pwo, bo, pt, px2, nullptr,
        D_, D_, D_, D_, L_, 0, 0, 0, 0);
    ln_rows<<<BL_, 256>>>(px2, ln2_g, ln2_b, pt2, 1.0f, pt2h);

    // ---- FFN ----
    gemm16<64, true, 0, true, false><<<dim3(D_ / 128, BL_ / 64, 1), 128, GM_SMEM_64>>>(
        pt2h, pw1, b1, nullptr, nullptr, pf1h,
        D_, D_, D_, D_, 0, 0, 0, 0, 0);
    gemm16<64, false, 1, true, false><<<dim3(D_ / 128, BL_ / 64, 1), 128, GM_SMEM_64>>>(
        pf1h, pw2, b2, pt2, px3, nullptr,
        D_, D_, D_, D_, 0, 0, 0, 0, 0);
    ln_rows<<<BL_, 256>>>(px3, ln3_g, ln3_b, ph, 1.0f, nullptr);

    // ---- GroupFC logits ----
    logits_kernel<<<dim3(L_, B_), 320>>>(ph, pdpT, pyt, out);
}

// round 12
// speedup vs baseline: 1.2096x; 1.2096x over previous
#include <cuda_runtime.h>
#include <cuda_fp16.h>
#include <math.h>
#include <stdint.h>

#define B_  32
#define S_  1024
#define F0_ 2048
#define D_  768
#define L_  100
#define H_  8
#define HD_ 96
#define DF_ 10
#define C_  1000
#define BL_ (B_*L_)   // 3200
#define BS_ (B_*S_)   // 32768
#define NKV_ 1536
#define LP_ 128       // L padded to 128

// ---------------- scratch (static __device__, zero-initialized) ----------------
static __device__ __align__(128) float g_t  [L_*D_];
static __device__ __align__(128) float g_x2 [(size_t)BL_*D_];
static __device__ __align__(128) float g_t2 [(size_t)BL_*D_];
static __device__ __align__(128) float g_x3 [(size_t)BL_*D_];
static __device__ __align__(128) float g_h  [(size_t)BL_*D_];
static __device__ __align__(128) float g_yt [C_];
static __device__ __align__(128) float g_bkv[NKV_];
static __device__ __align__(128) float g_inv[B_*H_*LP_];          // 1/rowsum of exp
static __device__ __align__(128) float g_dpT[(size_t)C_*2*D_];    // transposed dup_pool
static __device__ __align__(128) float g_ascdump[(size_t)B_*L_*S_];

// fp16 planes
static __device__ __align__(128) __half g_q16 [H_*LP_*HD_];            // padded q, scale folded
static __device__ __align__(128) __half g_s16 [(size_t)B_*H_*LP_*S_];  // exp(scores)
static __device__ __align__(128) __half g_kv16[(size_t)BS_*NKV_];      // k | v fp16, pitch 1536
static __device__ __align__(128) __half g_xh  [(size_t)BS_*F0_];
static __device__ __align__(128) __half g_memh[(size_t)BS_*D_];
static __device__ __align__(128) __half g_aoh [(size_t)BL_*D_];
static __device__ __align__(128) __half g_t2h [(size_t)BL_*D_];
static __device__ __align__(128) __half g_f1h [(size_t)BL_*D_];
static __device__ __align__(128) __half g_wemb[(size_t)D_*F0_];
static __device__ __align__(128) __half g_wkv [(size_t)NKV_*D_];
static __device__ __align__(128) __half g_wo  [(size_t)D_*D_];
static __device__ __align__(128) __half g_w1  [(size_t)D_*D_];
static __device__ __align__(128) __half g_w2  [(size_t)D_*D_];

// ============================================================================
// PTX helpers (sm_80-era baseline; safe on non-'a' compute_103 PTX target)
// ============================================================================
__device__ __forceinline__ uint32_t smem_u32(const void* p) {
    uint32_t a;
    asm("{ .reg .u64 t; cvta.to.shared.u64 t, %1; cvt.u32.u64 %0, t; }" : "=r"(a) : "l"(p));
    return a;
}
#define LDSM4(r, addr)                                                            \
    asm volatile("ldmatrix.sync.aligned.m8n8.x4.shared.b16 {%0,%1,%2,%3}, [%4];"  \
        : "=r"((r)[0]), "=r"((r)[1]), "=r"((r)[2]), "=r"((r)[3]) : "r"(addr))
#define MMAF16(c, a, b0, b1)                                                      \
    asm volatile("mma.sync.aligned.m16n8k16.row.col.f32.f16.f16.f32 "             \
        "{%0,%1,%2,%3}, {%4,%5,%6,%7}, {%8,%9}, {%0,%1,%2,%3};"                   \
        : "+f"((c)[0]), "+f"((c)[1]), "+f"((c)[2]), "+f"((c)[3])                  \
        : "r"((a)[0]), "r"((a)[1]), "r"((a)[2]), "r"((a)[3]), "r"(b0), "r"(b1))
#define CP16(dst, src)                                                            \
    asm volatile("cp.async.cg.shared.global [%0], [%1], 16;" :: "r"(dst), "l"(src))
#define CP_COMMIT() asm volatile("cp.async.commit_group;" ::: "memory")
#define CP_WAIT(n)  asm volatile("cp.async.wait_group %0;" :: "n"(n) : "memory")

// swizzle for 64B logical rows packed 2-per-128B line (conflict-free ldmatrix)
__device__ __forceinline__ uint32_t swz_addr(uint32_t base, int r, int kb) {
    uint32_t line = (uint32_t)r >> 1;
    uint32_t slot = ((((uint32_t)r & 1u) << 2) | (uint32_t)kb) ^ (line & 7u);
    return base + line * 128u + slot * 16u;
}

// fast exp on FMA pipe; clamped so fp16 store cannot overflow
__device__ __forceinline__ float fexp(float x) {
    float p = x * 1.4426950408889634f;
    p = fmaxf(fminf(p, 15.5f), -120.0f);
    float nf = rintf(p);
    float f = p - nf;
    float r = 0.0013333558146428443f;
    r = fmaf(r, f, 0.009618129107628477f);
    r = fmaf(r, f, 0.05550410866482158f);
    r = fmaf(r, f, 0.2402265069591007f);
    r = fmaf(r, f, 0.6931471805599453f);
    r = fmaf(r, f, 1.0f);
    return r * __int_as_float(((int)nf + 127) << 23);
}

// ============================================================================
// 1-pass fp16 HMMA GEMM, 256 threads (2x4 warps, 64x32 warp tiles), 2 CTAs/SM
// => 16 warps/SM for issue coverage. CTA tile 128x128, 4-stage cp.async.
// C = act(A * B^T + bias [+ res]);  strided; per-blockIdx.z offsets.
// ============================================================================
#define STG_BYTES 16384u
#define GM_SMEM (4u * STG_BYTES)   // 65536

__device__ __forceinline__ void load_stage(uint32_t sbase,
    const __half* __restrict__ Ah, const __half* __restrict__ Bw,
    int bm, int bn, int lda, int ldb, int k0, int tid)
{
    const int row = tid >> 1, kb0 = (tid & 1) * 2;
    const __half* pa = Ah + (size_t)(bm + row) * lda + k0 + kb0 * 8;
    CP16(swz_addr(sbase, row, kb0),     pa);
    CP16(swz_addr(sbase, row, kb0 + 1), pa + 8);
    const __half* pb = Bw + (size_t)(bn + row) * ldb + k0 + kb0 * 8;
    CP16(swz_addr(sbase + 8192u, row, kb0),     pb);
    CP16(swz_addr(sbase + 8192u, row, kb0 + 1), pb + 8);
    CP_COMMIT();
}

template<bool RELU, int RES, bool BIAS, bool EXP>
__global__ void __launch_bounds__(256, 2)
gemm16(const __half* __restrict__ Ah, const __half* __restrict__ Bw,
       const float* __restrict__ bias, const float* __restrict__ Res,
       float* __restrict__ C, __half* __restrict__ Chi,
       int K, int lda, int ldb, int ldc, int resMod,
       size_t oAh, size_t oBb, size_t oBh, size_t oC)
{
    extern __shared__ char smem[];
    const uint32_t sb = smem_u32(smem);
    const int tid = threadIdx.x, lane = tid & 31, wid = tid >> 5;
    const int wm = wid >> 2, wn = wid & 3;          // 2 x 4 warps, 64x32 tiles
    const int bm = blockIdx.y * 128, bn = blockIdx.x * 128;
    const int z = blockIdx.z, hz = z & 7, bz = z >> 3;
    Ah += (size_t)hz * oAh;
    Bw += (size_t)bz * oBb + (size_t)hz * oBh;
    const size_t coff = (size_t)z * oC;
    const int nc = K >> 5;

    float c[4][4][4];
    #pragma unroll
    for (int mt = 0; mt < 4; mt++)
        #pragma unroll
        for (int nt = 0; nt < 4; nt++)
            #pragma unroll
            for (int q = 0; q < 4; q++) c[mt][nt][q] = 0.0f;

    uint32_t offA[4][2], offB[2][2];
    {
        const int aR = lane & 15, aKb = lane >> 4;
        const int bR = (lane & 7) | ((lane >> 4) << 3);
        const int bKb = (lane >> 3) & 1;
        #pragma unroll
        for (int mt = 0; mt < 4; mt++)
            #pragma unroll
            for (int ks = 0; ks < 2; ks++)
                offA[mt][ks] = swz_addr(0, wm * 64 + mt * 16 + aR, ks * 2 + aKb);
        #pragma unroll
        for (int p = 0; p < 2; p++)
            #pragma unroll
            for (int ks = 0; ks < 2; ks++)
                offB[p][ks] = 8192u +
                    swz_addr(0, wn * 32 + p * 16 + bR, ks * 2 + bKb);
    }

    #pragma unroll
    for (int s = 0; s < 3; s++)
        load_stage(sb + s * STG_BYTES, Ah, Bw, bm, bn, lda, ldb, s * 32, tid);

    for (int i = 0; i < nc; i++) {
        CP_WAIT(2);
        __syncthreads();
        if (i + 3 < nc)
            load_stage(sb + (uint32_t)((i + 3) & 3) * STG_BYTES, Ah, Bw,
                       bm, bn, lda, ldb, (i + 3) * 32, tid);
        else
            CP_COMMIT();     // keep group count exact (no tail race)
        const uint32_t st = sb + (uint32_t)(i & 3) * STG_BYTES;
        #pragma unroll
        for (int ks = 0; ks < 2; ks++) {
            uint32_t aF[4][4], bf[2][4];
            #pragma unroll
            for (int mt = 0; mt < 4; mt++) LDSM4(aF[mt], st + offA[mt][ks]);
            #pragma unroll
            for (int p = 0; p < 2; p++) LDSM4(bf[p], st + offB[p][ks]);
            #pragma unroll
            for (int mt = 0; mt < 4; mt++)
                #pragma unroll
                for (int nt = 0; nt < 4; nt++)
                    MMAF16(c[mt][nt], aF[mt],
                           bf[nt >> 1][(nt & 1) * 2], bf[nt >> 1][(nt & 1) * 2 + 1]);
        }
    }

    #pragma unroll
    for (int mt = 0; mt < 4; mt++) {
        #pragma unroll
        for (int hh = 0; hh < 2; hh++) {
            const int m = bm + wm * 64 + mt * 16 + (lane >> 2) + hh * 8;
            const float* resRow = (RES == 1) ? (Res + (size_t)m * ldc)
                                : (RES == 2) ? (Res + (size_t)(m % resMod) * ldc)
                                : nullptr;
            #pragma unroll
            for (int nt = 0; nt < 4; nt++) {
                const int n = bn + wn * 32 + nt * 8 + (lane & 3) * 2;
                float vx = c[mt][nt][hh * 2 + 0];
                float vy = c[mt][nt][hh * 2 + 1];
                if (BIAS) { vx += bias[n]; vy += bias[n + 1]; }
                if (RES != 0) { vx += resRow[n]; vy += resRow[n + 1]; }
                if (RELU) { vx = fmaxf(vx, 0.f); vy = fmaxf(vy, 0.f); }
                if (EXP)  { vx = fexp(vx); vy = fexp(vy); }
                if (C) *(float2*)(C + coff + (size_t)m * ldc + n) = make_float2(vx, vy);
                if (Chi)
                    *(__half2*)(Chi + coff + (size_t)m * ldc + n) = __floats2half2_rn(vx, vy);
            }
        }
    }
}

// ============================================================================
// attn_v: ao[b,l,h*96+:] = (exp[bh,l,:] @ V[b,:,h*96+:]) * inv[bh,l]
// ============================================================================
#define AVS_A 8192u
#define AVS_V 6144u
#define AV_SMEM (4u*AVS_A + 2u*AVS_V)   // 45056

__global__ void __launch_bounds__(128, 2)
attn_v_mma(const __half* __restrict__ probs, const __half* __restrict__ kv16,
           const float* __restrict__ inv, __half* __restrict__ aoh)
{
    extern __shared__ char smem[];
    const uint32_t sb = smem_u32(smem);
    const int tid = threadIdx.x, lane = tid & 31, wid = tid >> 5;
    const int wm = wid & 1, wn = wid >> 1;
    const int bh = blockIdx.x, b = bh >> 3, h = bh & 7;
    const __half* A = probs + (size_t)bh * LP_ * S_;
    const __half* V = kv16 + (size_t)b * S_ * NKV_ + D_ + h * HD_;

    float c[4][6][4];
    #pragma unroll
    for (int mt = 0; mt < 4; mt++)
        #pragma unroll
        for (int nt = 0; nt < 6; nt++)
            #pragma unroll
            for (int q = 0; q < 4; q++) c[mt][nt][q] = 0.0f;

    uint32_t offA[4][2], offB[3][2];
    {
        const int aR = lane & 15, aKb = lane >> 4;
        #pragma unroll
        for (int mt = 0; mt < 4; mt++)
            #pragma unroll
            for (int ks = 0; ks < 2; ks++)
                offA[mt][ks] = swz_addr(0, wm * 64 + mt * 16 + aR, ks * 2 + aKb);
        const int bR = (lane & 7) | ((lane >> 4) << 3);
        const int bKb = (lane >> 3) & 1;
        #pragma unroll
        for (int nb = 0; nb < 3; nb++)
            #pragma unroll
            for (int ks = 0; ks < 2; ks++)
                offB[nb][ks] = swz_addr(0, wn * 48 + nb * 16 + bR, ks * 2 + bKb);
    }

    int qs[6], qh[6];
    #pragma unroll
    for (int q = 0; q < 6; q++) {
        const int idx = tid + q * 128;
        qs[q] = (idx / 48) * 2;
        qh[q] = (idx % 48) * 2;
    }

    uint32_t vlo[6], vhi[6];
    const int nChunks = S_ / 32;

    #pragma unroll
    for (int s = 0; s < 3; s++) {
        const __half* pa = A + (size_t)tid * S_ + s * 32;
        const uint32_t dst = sb + (uint32_t)s * AVS_A;
        #pragma unroll
        for (int kb = 0; kb < 4; kb++) CP16(swz_addr(dst, tid, kb), pa + kb * 8);
        CP_COMMIT();
    }
    {
        #pragma unroll
        for (int q = 0; q < 6; q++) {
            const __half* p = V + (size_t)qs[q] * NKV_ + qh[q];
            const uint32_t v0 = *(const uint32_t*)p;
            const uint32_t v1 = *(const uint32_t*)(p + NKV_);
            vlo[q] = __byte_perm(v0, v1, 0x5410);
            vhi[q] = __byte_perm(v0, v1, 0x7632);
        }
        char* vbuf = smem + 4 * AVS_A;
        #pragma unroll
        for (int q = 0; q < 6; q++) {
            const uint32_t o0 = swz_addr(0, qh[q],     qs[q] >> 3) + ((qs[q] * 2) & 15);
            const uint32_t o1 = swz_addr(0, qh[q] + 1, qs[q] >> 3) + ((qs[q] * 2) & 15);
            *(uint32_t*)(vbuf + o0) = vlo[q];
            *(uint32_t*)(vbuf + o1) = vhi[q];
        }
    }
    CP_WAIT(2);
    __syncthreads();

    for (int i = 0; i < nChunks; i++) {
        if (i + 1 < nChunks) {
            const int k0 = (i + 1) * 32;
            #pragma unroll
            for (int q = 0; q < 6; q++) {
                const __half* p = V + (size_t)(k0 + qs[q]) * NKV_ + qh[q];
                const uint32_t v0 = *(const uint32_t*)p;
                const uint32_t v1 = *(const uint32_t*)(p + NKV_);
                vlo[q] = __byte_perm(v0, v1, 0x5410);
                vhi[q] = __byte_perm(v0, v1, 0x7632);
            }
        }
        const uint32_t stA = sb + (uint32_t)(i & 3) * AVS_A;
        const uint32_t stV = sb + 4u * AVS_A + (uint32_t)(i & 1) * AVS_V;
        #pragma unroll
        for (int ks = 0; ks < 2; ks++) {
            uint32_t aF[4][4], bf[3][4];
            #pragma unroll
            for (int mt = 0; mt < 4; mt++) LDSM4(aF[mt], stA + offA[mt][ks]);
            #pragma unroll
            for (int nb = 0; nb < 3; nb++) LDSM4(bf[nb], stV + offB[nb][ks]);
            #pragma unroll
            for (int mt = 0; mt < 4; mt++)
                #pragma unroll
                for (int nt = 0; nt < 6; nt++)
                    MMAF16(c[mt][nt], aF[mt],
                           bf[nt >> 1][(nt & 1) * 2], bf[nt >> 1][(nt & 1) * 2 + 1]);
        }
        if (i + 3 < nChunks) {
            const __half* pa = A + (size_t)tid * S_ + (i + 3) * 32;
            const uint32_t dst = sb + (uint32_t)((i + 3) & 3) * AVS_A;
            #pragma unroll
            for (int kb = 0; kb < 4; kb++) CP16(swz_addr(dst, tid, kb), pa + kb * 8);
        }
        CP_COMMIT();
        if (i + 1 < nChunks) {
            char* vbuf = smem + 4 * AVS_A + ((i + 1) & 1) * AVS_V;
            #pragma unroll
            for (int q = 0; q < 6; q++) {
                const uint32_t o0 = swz_addr(0, qh[q],     qs[q] >> 3) + ((qs[q] * 2) & 15);
                const uint32_t o1 = swz_addr(0, qh[q] + 1, qs[q] >> 3) + ((qs[q] * 2) & 15);
                *(uint32_t*)(vbuf + o0) = vlo[q];
                *(uint32_t*)(vbuf + o1) = vhi[q];
            }
            CP_WAIT(2);
            __syncthreads();
        }
    }

    #pragma unroll
    for (int mt = 0; mt < 4; mt++) {
        #pragma unroll
        for (int hh = 0; hh < 2; hh++) {
            const int m = wm * 64 + mt * 16 + (lane >> 2) + hh * 8;
            if (m < L_) {
                const float sc = inv[bh * LP_ + m];
                __half* orow = aoh + ((size_t)b * L_ + m) * D_ + h * HD_;
                #pragma unroll
                for (int nt = 0; nt < 6; nt++) {
                    const int n = wn * 48 + nt * 8 + (lane & 3) * 2;
                    *(__half2*)(orow + n) = __floats2half2_rn(
                        c[mt][nt][hh * 2] * sc, c[mt][nt][hh * 2 + 1] * sc);
                }
            }
        }
    }
}

// ---------------- converters ----------------
__global__ void cvt_h16(const float* __restrict__ in, __half* __restrict__ out, int n4)
{
    int i = blockIdx.x * 256 + threadIdx.x;
    if (i >= n4) return;
    float4 f = ((const float4*)in)[i];
    ((__half2*)out)[i * 2 + 0] = __floats2half2_rn(f.x, f.y);
    ((__half2*)out)[i * 2 + 1] = __floats2half2_rn(f.z, f.w);
}
__global__ void concat_bias(const float* __restrict__ bk, const float* __restrict__ bv,
                            float* __restrict__ bkv)
{
    int i = blockIdx.x * 256 + threadIdx.x;
    if (i < D_) bkv[i] = bk[i];
    else if (i < NKV_) bkv[i] = bv[i - D_];
}
// transpose dup_pool: dp[l][d][f] -> dpT[l*10+f][d], d in [0,1536)
__global__ void transpose_dp(const float* __restrict__ dp, float* __restrict__ dpT)
{
    __shared__ float sm[384 * DF_];
    const int l = blockIdx.x, d0 = blockIdx.y * 384;
    const float* src = dp + (size_t)l * (2 * D_) * DF_ + (size_t)d0 * DF_;
    for (int i = threadIdx.x; i < 384 * DF_; i += 256) sm[i] = src[i];
    __syncthreads();
    for (int i = threadIdx.x; i < 384 * DF_; i += 256) {
        const int f = i / 384, d = i - f * 384;
        dpT[(size_t)(l * DF_ + f) * (2 * D_) + d0 + d] = sm[d * DF_ + f];
    }
}

// ---------------- block reduction ----------------
__device__ __forceinline__ float blockSum256(float v, float* sm) {
    #pragma unroll
    for (int o = 16; o > 0; o >>= 1) v += __shfl_xor_sync(0xffffffffu, v, o);
    const int w = threadIdx.x >> 5, lane = threadIdx.x & 31;
    if (lane == 0) sm[w] = v;
    __syncthreads();
    float r = (lane < 8) ? sm[lane] : 0.0f;
    #pragma unroll
    for (int o = 4; o > 0; o >>= 1) r += __shfl_xor_sync(0xffffffffu, r, o);
    r = __shfl_sync(0xffffffffu, r, 0);
    __syncthreads();
    return r;
}

// ---------------- row LayerNorm; optional fp16 output ----------------
__global__ void ln_rows(const float* __restrict__ X, const float* __restrict__ gg,
                        const float* __restrict__ bb, float* __restrict__ O, float alpha,
                        __half* __restrict__ Oh)
{
    __shared__ float sm[8];
    const int row = blockIdx.x;
    const float* x = X + (size_t)row * D_;
    float v[3];
    float s = 0.0f, sq = 0.0f;
    #pragma unroll
    for (int j = 0; j < 3; j++) {
        v[j] = alpha * x[threadIdx.x + j * 256];
        s += v[j]; sq += v[j] * v[j];
    }
    s  = blockSum256(s, sm);
    sq = blockSum256(sq, sm);
    const float mean = s * (1.0f / D_);
    const float var  = sq * (1.0f / D_) - mean * mean;
    const float inv  = rsqrtf(var + 1e-5f);
    float* o = O + (size_t)row * D_;
    #pragma unroll
    for (int j = 0; j < 3; j++) {
        const int i = threadIdx.x + j * 256;
        const float ov = (v[j] - mean) * inv * gg[i] + bb[i];
        o[i] = ov;
        if (Oh) Oh[(size_t)row * D_ + i] = __float2half_rn(ov);
    }
}

// ---------------- q projection -> fp16 padded [H][128][96], scale folded ----------------
__global__ void qproj(const float* __restrict__ t, const float* __restrict__ Wq,
                      const float* __restrict__ bq, __half* __restrict__ q16)
{
    const int l = blockIdx.x;
    const int e = blockIdx.y * 128 + threadIdx.x;
    __shared__ float ts[D_];
    for (int i = threadIdx.x; i < D_; i += 128) ts[i] = t[(size_t)l * D_ + i];
    __syncthreads();
    const float* w = Wq + (size_t)e * D_;
    float acc = 0.0f;
    #pragma unroll 8
    for (int d = 0; d < D_; d++) acc = fmaf(ts[d], w[d], acc);
    const float val = (acc + bq[e]) * 0.10206207261596575f;   // 1/sqrt(96)
    const int hh = e / HD_, eh = e - hh * HD_;
    q16[(size_t)hh * LP_ * HD_ + (size_t)l * HD_ + eh] = __float2half_rn(val);
}

// ---------------- row sums of exp + head-mean a_score ----------------
__global__ void sum_mean(const __half* __restrict__ s16, float* __restrict__ invO,
                         float* __restrict__ ascore)
{
    __shared__ float sm[8];
    const int l = blockIdx.x, b = blockIdx.y;
    const int tid = threadIdx.x;
    float am[4] = {0.f, 0.f, 0.f, 0.f};
    for (int h = 0; h < H_; h++) {
        const int bh = b * H_ + h;
        const __half* row = s16 + ((size_t)bh * LP_ + l) * S_;
        float v[4];
        float ssum = 0.0f;
        #pragma unroll
        for (int j = 0; j < 4; j++) { v[j] = __half2float(row[tid + j * 256]); ssum += v[j]; }
        ssum = blockSum256(ssum, sm);
        const float inv = 1.0f / ssum;
        if (tid == 0) invO[bh * LP_ + l] = inv;
        #pragma unroll
        for (int j = 0; j < 4; j++) am[j] += v[j] * inv * (1.0f / H_);
    }
    float* ao = ascore + ((size_t)b * L_ + l) * S_;
    #pragma unroll
    for (int j = 0; j < 4; j++) ao[tid + j * 256] = am[j];
}

// ---------------- GroupFC terms on transposed pool (coalesced) ----------------
__global__ void yterm_kernel(const float* __restrict__ y, const float* __restrict__ dpT,
                             const float* __restrict__ dbias, float* __restrict__ yt)
{
    const int l = blockIdx.x;
    const int w = threadIdx.x >> 5, lane = threadIdx.x & 31;    // 10 warps
    const float* row = dpT + (size_t)(l * DF_ + w) * (2 * D_) + D_;
    const float* yr = y + (size_t)l * D_;
    float acc = 0.0f;
    for (int d = lane; d < D_; d += 32) acc = fmaf(yr[d], row[d], acc);
    #pragma unroll
    for (int o = 16; o > 0; o >>= 1) acc += __shfl_xor_sync(0xffffffffu, acc, o);
    if (lane == 0) yt[l * DF_ + w] = acc + dbias[l * DF_ + w];
}

__global__ void logits_kernel(const float* __restrict__ hh, const float* __restrict__ dpT,
                              const float* __restrict__ yt, float* __restrict__ out)
{
    const int l = blockIdx.x, b = blockIdx.y;
    const int w = threadIdx.x >> 5, lane = threadIdx.x & 31;    // 10 warps
    __shared__ float hs[D_];
    for (int i = threadIdx.x; i < D_; i += 320) hs[i] = hh[((size_t)b * L_ + l) * D_ + i];
    __syncthreads();
    const float* row = dpT + (size_t)(l * DF_ + w) * (2 * D_);
    float acc = 0.0f;
    for (int d = lane; d < D_; d += 32) acc = fmaf(hs[d], row[d], acc);
    #pragma unroll
    for (int o = 16; o > 0; o >>= 1) acc += __shfl_xor_sync(0xffffffffu, acc, o);
    if (lane == 0) out[(size_t)b * C_ + l * DF_ + w] = acc + yt[l * DF_ + w];
}

// ---------------- host launch ----------------
extern "C" void kernel_launch(void* const* d_in, const int* in_sizes, int n_in,
                              void* d_out, int out_size)
{
    const float* x       = (const float*)d_in[0];
    const float* y       = (const float*)d_in[1];
    const float* embed_W = (const float*)d_in[2];
    const float* embed_b = (const float*)d_in[3];
    const float* Wq      = (const float*)d_in[4];
    const float* Wk      = (const float*)d_in[5];
    const float* Wv      = (const float*)d_in[6];
    const float* bq      = (const float*)d_in[7];
    const float* bk      = (const float*)d_in[8];
    const float* bv      = (const float*)d_in[9];
    const float* Wo      = (const float*)d_in[10];
    const float* bo      = (const float*)d_in[11];
    const float* ln1_g   = (const float*)d_in[12];
    const float* ln1_b   = (const float*)d_in[13];
    const float* ln2_g   = (const float*)d_in[14];
    const float* ln2_b   = (const float*)d_in[15];
    const float* ln3_g   = (const float*)d_in[16];
    const float* ln3_b   = (const float*)d_in[17];
    const float* W1      = (const float*)d_in[18];
    const float* b1      = (const float*)d_in[19];
    const float* W2      = (const float*)d_in[20];
    const float* b2      = (const float*)d_in[21];
    const float* dp      = (const float*)d_in[22];
    const float* dbias   = (const float*)d_in[23];
    float* out = (float*)d_out;

    float *pt, *px2, *pt2, *px3, *ph, *pyt, *pbkv, *pinv, *pdpT, *pdump;
    __half *pq16, *ps16, *pkv16, *pxh, *pmemh, *paoh, *pt2h, *pf1h;
    __half *pwemb, *pwkv, *pwo, *pw1, *pw2;
    cudaGetSymbolAddress((void**)&pt,    g_t);
    cudaGetSymbolAddress((void**)&px2,   g_x2);
    cudaGetSymbolAddress((void**)&pt2,   g_t2);
    cudaGetSymbolAddress((void**)&px3,   g_x3);
    cudaGetSymbolAddress((void**)&ph,    g_h);
    cudaGetSymbolAddress((void**)&pyt,   g_yt);
    cudaGetSymbolAddress((void**)&pbkv,  g_bkv);
    cudaGetSymbolAddress((void**)&pinv,  g_inv);
    cudaGetSymbolAddress((void**)&pdpT,  g_dpT);
    cudaGetSymbolAddress((void**)&pdump, g_ascdump);
    cudaGetSymbolAddress((void**)&pq16,  g_q16);
    cudaGetSymbolAddress((void**)&ps16,  g_s16);
    cudaGetSymbolAddress((void**)&pkv16, g_kv16);
    cudaGetSymbolAddress((void**)&pxh,   g_xh);
    cudaGetSymbolAddress((void**)&pmemh, g_memh);
    cudaGetSymbolAddress((void**)&paoh,  g_aoh);
    cudaGetSymbolAddress((void**)&pt2h,  g_t2h);
    cudaGetSymbolAddress((void**)&pf1h,  g_f1h);
    cudaGetSymbolAddress((void**)&pwemb, g_wemb);
    cudaGetSymbolAddress((void**)&pwkv,  g_wkv);
    cudaGetSymbolAddress((void**)&pwo,   g_wo);
    cudaGetSymbolAddress((void**)&pw1,   g_w1);
    cudaGetSymbolAddress((void**)&pw2,   g_w2);

    cudaFuncSetAttribute(gemm16<true, 0, true, false>,  cudaFuncAttributeMaxDynamicSharedMemorySize, GM_SMEM);
    cudaFuncSetAttribute(gemm16<false, 0, true, false>, cudaFuncAttributeMaxDynamicSharedMemorySize, GM_SMEM);
    cudaFuncSetAttribute(gemm16<false, 0, false, true>, cudaFuncAttributeMaxDynamicSharedMemorySize, GM_SMEM);
    cudaFuncSetAttribute(gemm16<false, 2, true, false>, cudaFuncAttributeMaxDynamicSharedMemorySize, GM_SMEM);
    cudaFuncSetAttribute(gemm16<false, 1, true, false>, cudaFuncAttributeMaxDynamicSharedMemorySize, GM_SMEM);
    cudaFuncSetAttribute(attn_v_mma, cudaFuncAttributeMaxDynamicSharedMemorySize, AV_SMEM);

    float* asc = (out_size >= B_ * C_ + B_ * L_ * S_) ? (out + B_ * C_) : pdump;

    // ---- launches 1-5: prerequisites of embed (embed is launch #6 for ncu -s 5) ----
    cvt_h16<<<(BS_ * F0_ / 4 + 255) / 256, 256>>>(x, pxh, BS_ * F0_ / 4);          // 1
    cvt_h16<<<(D_ * F0_ / 4 + 255) / 256, 256>>>(embed_W, pwemb, D_ * F0_ / 4);    // 2
    cvt_h16<<<(D_ * D_ / 4 + 255) / 256, 256>>>(Wk, pwkv, D_ * D_ / 4);            // 3
    cvt_h16<<<(D_ * D_ / 4 + 255) / 256, 256>>>(Wv, pwkv + (size_t)D_ * D_, D_ * D_ / 4); // 4
    concat_bias<<<(NKV_ + 255) / 256, 256>>>(bk, bv, pbkv);                        // 5

    // ---- 6: mem = relu(x @ We^T + eb) -> fp16 ----
    gemm16<true, 0, true, false><<<dim3(D_ / 128, BS_ / 128, 1), 256, GM_SMEM>>>(
        pxh, pwemb, embed_b, nullptr, nullptr, pmemh,
        F0_, F0_, F0_, D_, 0, 0, 0, 0, 0);

    // ---- remaining conversions / preamble ----
    cvt_h16<<<(D_ * D_ / 4 + 255) / 256, 256>>>(Wo, pwo, D_ * D_ / 4);
    cvt_h16<<<(D_ * D_ / 4 + 255) / 256, 256>>>(W1, pw1, D_ * D_ / 4);
    cvt_h16<<<(D_ * D_ / 4 + 255) / 256, 256>>>(W2, pw2, D_ * D_ / 4);
    transpose_dp<<<dim3(L_, 4), 256>>>(dp, pdpT);
    ln_rows<<<L_, 256>>>(y, ln1_g, ln1_b, pt, 2.0f, nullptr);              // t = LN(2y)
    qproj<<<dim3(L_, D_ / 128), 128>>>(pt, Wq, bq, pq16);
    yterm_kernel<<<L_, 320>>>(y, pdpT, dbias, pyt);

    // ---- fused K|V GEMM -> fp16 kv (pitch 1536) ----
    gemm16<false, 0, true, false><<<dim3(NKV_ / 128, BS_ / 128, 1), 256, GM_SMEM>>>(
        pmemh, pwkv, pbkv, nullptr, nullptr, pkv16,
        D_, D_, D_, NKV_, 0, 0, 0, 0, 0);

    // ---- scores + fused exp: per (b,h) GEMM -> exp(s) fp16 ----
    gemm16<false, 0, false, true><<<dim3(S_ / 128, 1, B_ * H_), 256, GM_SMEM>>>(
        pq16, pkv16, nullptr, nullptr, nullptr, ps16,
        HD_, HD_, NKV_, S_, 0,
        (size_t)LP_ * HD_, (size_t)S_ * NKV_, (size_t)HD_, (size_t)LP_ * S_);

    // ---- row sums + head-mean a_score ----
    sum_mean<<<dim3(L_, B_), 256>>>(ps16, pinv, asc);

    // ---- (exp @ V) * inv -> ao fp16 ----
    attn_v_mma<<<B_ * H_, 128, AV_SMEM>>>(ps16, pkv16, pinv, paoh);

    // ---- out-proj + residual t[l], LN2 (full 128-tiles again) ----
    gemm16<false, 2, true, false><<<dim3(D_ / 128, BL_ / 128, 1), 256, GM_SMEM>>>(
        paoh, pwo, bo, pt, px2, nullptr,
        D_, D_, D_, D_, L_, 0, 0, 0, 0);
    ln_rows<<<BL_, 256>>>(px2, ln2_g, ln2_b, pt2, 1.0f, pt2h);

    // ---- FFN ----
    gemm16<true, 0, true, false><<<dim3(D_ / 128, BL_ / 128, 1), 256, GM_SMEM>>>(
        pt2h, pw1, b1, nullptr, nullptr, pf1h,
        D_, D_, D_, D_, 0, 0, 0, 0, 0);
    gemm16<false, 1, true, false><<<dim3(D_ / 128, BL_ / 128, 1), 256, GM_SMEM>>>(
        pf1h, pw2, b2, pt2, px3, nullptr,
        D_, D_, D_, D_, 0, 0, 0, 0, 0);
    ln_rows<<<BL_, 256>>>(px3, ln3_g, ln3_b, ph, 1.0f, nullptr);

    // ---- GroupFC logits ----
    logits_kernel<<<dim3(L_, B_), 320>>>(ph, pdpT, pyt, out);
}

// round 13
// speedup vs baseline: 1.2098x; 1.0002x over previous
#include <cuda_runtime.h>
#include <cuda_fp16.h>
#include <math.h>
#include <stdint.h>

#define B_  32
#define S_  1024
#define F0_ 2048
#define D_  768
#define L_  100
#define H_  8
#define HD_ 96
#define DF_ 10
#define C_  1000
#define BL_ (B_*L_)   // 3200
#define BS_ (B_*S_)   // 32768
#define NKV_ 1536
#define LP_ 128       // L padded to 128

// ---------------- scratch (static __device__, zero-initialized) ----------------
static __device__ __align__(128) float g_t  [L_*D_];
static __device__ __align__(128) float g_x2 [(size_t)BL_*D_];
static __device__ __align__(128) float g_t2 [(size_t)BL_*D_];
static __device__ __align__(128) float g_x3 [(size_t)BL_*D_];
static __device__ __align__(128) float g_h  [(size_t)BL_*D_];
static __device__ __align__(128) float g_yt [C_];
static __device__ __align__(128) float g_bkv[NKV_];
static __device__ __align__(128) float g_inv[B_*H_*LP_];          // 1/rowsum of exp
static __device__ __align__(128) float g_dpT[(size_t)C_*2*D_];    // transposed dup_pool
static __device__ __align__(128) float g_ascdump[(size_t)B_*L_*S_];

// fp16 planes
static __device__ __align__(128) __half g_q16 [H_*LP_*HD_];            // padded q, scale folded
static __device__ __align__(128) __half g_s16 [(size_t)B_*H_*LP_*S_];  // exp(scores)
static __device__ __align__(128) __half g_kv16[(size_t)BS_*NKV_];      // k | v fp16, pitch 1536
static __device__ __align__(128) __half g_xh  [(size_t)BS_*F0_];
static __device__ __align__(128) __half g_memh[(size_t)BS_*D_];
static __device__ __align__(128) __half g_aoh [(size_t)BL_*D_];
static __device__ __align__(128) __half g_t2h [(size_t)BL_*D_];
static __device__ __align__(128) __half g_f1h [(size_t)BL_*D_];
static __device__ __align__(128) __half g_wemb[(size_t)D_*F0_];
static __device__ __align__(128) __half g_wkv [(size_t)NKV_*D_];
static __device__ __align__(128) __half g_wo  [(size_t)D_*D_];
static __device__ __align__(128) __half g_w1  [(size_t)D_*D_];
static __device__ __align__(128) __half g_w2  [(size_t)D_*D_];

// ============================================================================
// PTX helpers (sm_80-era baseline; safe on non-'a' compute_103 PTX target)
// ============================================================================
__device__ __forceinline__ uint32_t smem_u32(const void* p) {
    uint32_t a;
    asm("{ .reg .u64 t; cvta.to.shared.u64 t, %1; cvt.u32.u64 %0, t; }" : "=r"(a) : "l"(p));
    return a;
}
#define LDSM4(r, addr)                                                            \
    asm volatile("ldmatrix.sync.aligned.m8n8.x4.shared.b16 {%0,%1,%2,%3}, [%4];"  \
        : "=r"((r)[0]), "=r"((r)[1]), "=r"((r)[2]), "=r"((r)[3]) : "r"(addr))
#define MMAF16(c, a, b0, b1)                                                      \
    asm volatile("mma.sync.aligned.m16n8k16.row.col.f32.f16.f16.f32 "             \
        "{%0,%1,%2,%3}, {%4,%5,%6,%7}, {%8,%9}, {%0,%1,%2,%3};"                   \
        : "+f"((c)[0]), "+f"((c)[1]), "+f"((c)[2]), "+f"((c)[3])                  \
        : "r"((a)[0]), "r"((a)[1]), "r"((a)[2]), "r"((a)[3]), "r"(b0), "r"(b1))
#define CP16(dst, src)                                                            \
    asm volatile("cp.async.cg.shared.global [%0], [%1], 16;" :: "r"(dst), "l"(src))
#define CP_COMMIT() asm volatile("cp.async.commit_group;" ::: "memory")
#define CP_WAIT(n)  asm volatile("cp.async.wait_group %0;" :: "n"(n) : "memory")

// swizzle for 64B logical rows packed 2-per-128B line (conflict-free ldmatrix)
__device__ __forceinline__ uint32_t swz_addr(uint32_t base, int r, int kb) {
    uint32_t line = (uint32_t)r >> 1;
    uint32_t slot = ((((uint32_t)r & 1u) << 2) | (uint32_t)kb) ^ (line & 7u);
    return base + line * 128u + slot * 16u;
}

// fast exp on FMA pipe; clamped so fp16 store cannot overflow
__device__ __forceinline__ float fexp(float x) {
    float p = x * 1.4426950408889634f;
    p = fmaxf(fminf(p, 15.5f), -120.0f);
    float nf = rintf(p);
    float f = p - nf;
    float r = 0.0013333558146428443f;
    r = fmaf(r, f, 0.009618129107628477f);
    r = fmaf(r, f, 0.05550410866482158f);
    r = fmaf(r, f, 0.2402265069591007f);
    r = fmaf(r, f, 0.6931471805599453f);
    r = fmaf(r, f, 1.0f);
    return r * __int_as_float(((int)nf + 127) << 23);
}

// ============================================================================
// 1-pass fp16 HMMA GEMM, 256 threads (2x4 warps, 64x32 warp tiles), 2 CTAs/SM
// (16 warps/SM). CTA tile 128x128, 4-stage cp.async.  [UNCHANGED from R12]
// ============================================================================
#define STG_BYTES 16384u
#define GM_SMEM (4u * STG_BYTES)   // 65536

__device__ __forceinline__ void load_stage(uint32_t sbase,
    const __half* __restrict__ Ah, const __half* __restrict__ Bw,
    int bm, int bn, int lda, int ldb, int k0, int tid)
{
    const int row = tid >> 1, kb0 = (tid & 1) * 2;
    const __half* pa = Ah + (size_t)(bm + row) * lda + k0 + kb0 * 8;
    CP16(swz_addr(sbase, row, kb0),     pa);
    CP16(swz_addr(sbase, row, kb0 + 1), pa + 8);
    const __half* pb = Bw + (size_t)(bn + row) * ldb + k0 + kb0 * 8;
    CP16(swz_addr(sbase + 8192u, row, kb0),     pb);
    CP16(swz_addr(sbase + 8192u, row, kb0 + 1), pb + 8);
    CP_COMMIT();
}

template<bool RELU, int RES, bool BIAS, bool EXP>
__global__ void __launch_bounds__(256, 2)
gemm16(const __half* __restrict__ Ah, const __half* __restrict__ Bw,
       const float* __restrict__ bias, const float* __restrict__ Res,
       float* __restrict__ C, __half* __restrict__ Chi,
       int K, int lda, int ldb, int ldc, int resMod,
       size_t oAh, size_t oBb, size_t oBh, size_t oC)
{
    extern __shared__ char smem[];
    const uint32_t sb = smem_u32(smem);
    const int tid = threadIdx.x, lane = tid & 31, wid = tid >> 5;
    const int wm = wid >> 2, wn = wid & 3;          // 2 x 4 warps, 64x32 tiles
    const int bm = blockIdx.y * 128, bn = blockIdx.x * 128;
    const int z = blockIdx.z, hz = z & 7, bz = z >> 3;
    Ah += (size_t)hz * oAh;
    Bw += (size_t)bz * oBb + (size_t)hz * oBh;
    const size_t coff = (size_t)z * oC;
    const int nc = K >> 5;

    float c[4][4][4];
    #pragma unroll
    for (int mt = 0; mt < 4; mt++)
        #pragma unroll
        for (int nt = 0; nt < 4; nt++)
            #pragma unroll
            for (int q = 0; q < 4; q++) c[mt][nt][q] = 0.0f;

    uint32_t offA[4][2], offB[2][2];
    {
        const int aR = lane & 15, aKb = lane >> 4;
        const int bR = (lane & 7) | ((lane >> 4) << 3);
        const int bKb = (lane >> 3) & 1;
        #pragma unroll
        for (int mt = 0; mt < 4; mt++)
            #pragma unroll
            for (int ks = 0; ks < 2; ks++)
                offA[mt][ks] = swz_addr(0, wm * 64 + mt * 16 + aR, ks * 2 + aKb);
        #pragma unroll
        for (int p = 0; p < 2; p++)
            #pragma unroll
            for (int ks = 0; ks < 2; ks++)
                offB[p][ks] = 8192u +
                    swz_addr(0, wn * 32 + p * 16 + bR, ks * 2 + bKb);
    }

    #pragma unroll
    for (int s = 0; s < 3; s++)
        load_stage(sb + s * STG_BYTES, Ah, Bw, bm, bn, lda, ldb, s * 32, tid);

    for (int i = 0; i < nc; i++) {
        CP_WAIT(2);
        __syncthreads();
        if (i + 3 < nc)
            load_stage(sb + (uint32_t)((i + 3) & 3) * STG_BYTES, Ah, Bw,
                       bm, bn, lda, ldb, (i + 3) * 32, tid);
        else
            CP_COMMIT();     // keep group count exact (no tail race)
        const uint32_t st = sb + (uint32_t)(i & 3) * STG_BYTES;
        #pragma unroll
        for (int ks = 0; ks < 2; ks++) {
            uint32_t aF[4][4], bf[2][4];
            #pragma unroll
            for (int mt = 0; mt < 4; mt++) LDSM4(aF[mt], st + offA[mt][ks]);
            #pragma unroll
            for (int p = 0; p < 2; p++) LDSM4(bf[p], st + offB[p][ks]);
            #pragma unroll
            for (int mt = 0; mt < 4; mt++)
                #pragma unroll
                for (int nt = 0; nt < 4; nt++)
                    MMAF16(c[mt][nt], aF[mt],
                           bf[nt >> 1][(nt & 1) * 2], bf[nt >> 1][(nt & 1) * 2 + 1]);
        }
    }

    #pragma unroll
    for (int mt = 0; mt < 4; mt++) {
        #pragma unroll
        for (int hh = 0; hh < 2; hh++) {
            const int m = bm + wm * 64 + mt * 16 + (lane >> 2) + hh * 8;
            const float* resRow = (RES == 1) ? (Res + (size_t)m * ldc)
                                : (RES == 2) ? (Res + (size_t)(m % resMod) * ldc)
                                : nullptr;
            #pragma unroll
            for (int nt = 0; nt < 4; nt++) {
                const int n = bn + wn * 32 + nt * 8 + (lane & 3) * 2;
                float vx = c[mt][nt][hh * 2 + 0];
                float vy = c[mt][nt][hh * 2 + 1];
                if (BIAS) { vx += bias[n]; vy += bias[n + 1]; }
                if (RES != 0) { vx += resRow[n]; vy += resRow[n + 1]; }
                if (RELU) { vx = fmaxf(vx, 0.f); vy = fmaxf(vy, 0.f); }
                if (EXP)  { vx = fexp(vx); vy = fexp(vy); }
                if (C) *(float2*)(C + coff + (size_t)m * ldc + n) = make_float2(vx, vy);
                if (Chi)
                    *(__half2*)(Chi + coff + (size_t)m * ldc + n) = __floats2half2_rn(vx, vy);
            }
        }
    }
}

// ============================================================================
// attn_v: ao[b,l,h*96+:] = (exp[bh,l,:] @ V[b,:,h*96+:]) * inv[bh,l]  [UNCHANGED]
// ============================================================================
#define AVS_A 8192u
#define AVS_V 6144u
#define AV_SMEM (4u*AVS_A + 2u*AVS_V)   // 45056

__global__ void __launch_bounds__(128, 2)
attn_v_mma(const __half* __restrict__ probs, const __half* __restrict__ kv16,
           const float* __restrict__ inv, __half* __restrict__ aoh)
{
    extern __shared__ char smem[];
    const uint32_t sb = smem_u32(smem);
    const int tid = threadIdx.x, lane = tid & 31, wid = tid >> 5;
    const int wm = wid & 1, wn = wid >> 1;
    const int bh = blockIdx.x, b = bh >> 3, h = bh & 7;
    const __half* A = probs + (size_t)bh * LP_ * S_;
    const __half* V = kv16 + (size_t)b * S_ * NKV_ + D_ + h * HD_;

    float c[4][6][4];
    #pragma unroll
    for (int mt = 0; mt < 4; mt++)
        #pragma unroll
        for (int nt = 0; nt < 6; nt++)
            #pragma unroll
            for (int q = 0; q < 4; q++) c[mt][nt][q] = 0.0f;

    uint32_t offA[4][2], offB[3][2];
    {
        const int aR = lane & 15, aKb = lane >> 4;
        #pragma unroll
        for (int mt = 0; mt < 4; mt++)
            #pragma unroll
            for (int ks = 0; ks < 2; ks++)
                offA[mt][ks] = swz_addr(0, wm * 64 + mt * 16 + aR, ks * 2 + aKb);
        const int bR = (lane & 7) | ((lane >> 4) << 3);
        const int bKb = (lane >> 3) & 1;
        #pragma unroll
        for (int nb = 0; nb < 3; nb++)
            #pragma unroll
            for (int ks = 0; ks < 2; ks++)
                offB[nb][ks] = swz_addr(0, wn * 48 + nb * 16 + bR, ks * 2 + bKb);
    }

    int qs[6], qh[6];
    #pragma unroll
    for (int q = 0; q < 6; q++) {
        const int idx = tid + q * 128;
        qs[q] = (idx / 48) * 2;
        qh[q] = (idx % 48) * 2;
    }

    uint32_t vlo[6], vhi[6];
    const int nChunks = S_ / 32;

    #pragma unroll
    for (int s = 0; s < 3; s++) {
        const __half* pa = A + (size_t)tid * S_ + s * 32;
        const uint32_t dst = sb + (uint32_t)s * AVS_A;
        #pragma unroll
        for (int kb = 0; kb < 4; kb++) CP16(swz_addr(dst, tid, kb), pa + kb * 8);
        CP_COMMIT();
    }
    {
        #pragma unroll
        for (int q = 0; q < 6; q++) {
            const __half* p = V + (size_t)qs[q] * NKV_ + qh[q];
            const uint32_t v0 = *(const uint32_t*)p;
            const uint32_t v1 = *(const uint32_t*)(p + NKV_);
            vlo[q] = __byte_perm(v0, v1, 0x5410);
            vhi[q] = __byte_perm(v0, v1, 0x7632);
        }
        char* vbuf = smem + 4 * AVS_A;
        #pragma unroll
        for (int q = 0; q < 6; q++) {
            const uint32_t o0 = swz_addr(0, qh[q],     qs[q] >> 3) + ((qs[q] * 2) & 15);
            const uint32_t o1 = swz_addr(0, qh[q] + 1, qs[q] >> 3) + ((qs[q] * 2) & 15);
            *(uint32_t*)(vbuf + o0) = vlo[q];
            *(uint32_t*)(vbuf + o1) = vhi[q];
        }
    }
    CP_WAIT(2);
    __syncthreads();

    for (int i = 0; i < nChunks; i++) {
        if (i + 1 < nChunks) {
            const int k0 = (i + 1) * 32;
            #pragma unroll
            for (int q = 0; q < 6; q++) {
                const __half* p = V + (size_t)(k0 + qs[q]) * NKV_ + qh[q];
                const uint32_t v0 = *(const uint32_t*)p;
                const uint32_t v1 = *(const uint32_t*)(p + NKV_);
                vlo[q] = __byte_perm(v0, v1, 0x5410);
                vhi[q] = __byte_perm(v0, v1, 0x7632);
            }
        }
        const uint32_t stA = sb + (uint32_t)(i & 3) * AVS_A;
        const uint32_t stV = sb + 4u * AVS_A + (uint32_t)(i & 1) * AVS_V;
        #pragma unroll
        for (int ks = 0; ks < 2; ks++) {
            uint32_t aF[4][4], bf[3][4];
            #pragma unroll
            for (int mt = 0; mt < 4; mt++) LDSM4(aF[mt], stA + offA[mt][ks]);
            #pragma unroll
            for (int nb = 0; nb < 3; nb++) LDSM4(bf[nb], stV + offB[nb][ks]);
            #pragma unroll
            for (int mt = 0; mt < 4; mt++)
                #pragma unroll
                for (int nt = 0; nt < 6; nt++)
                    MMAF16(c[mt][nt], aF[mt],
                           bf[nt >> 1][(nt & 1) * 2], bf[nt >> 1][(nt & 1) * 2 + 1]);
        }
        if (i + 3 < nChunks) {
            const __half* pa = A + (size_t)tid * S_ + (i + 3) * 32;
            const uint32_t dst = sb + (uint32_t)((i + 3) & 3) * AVS_A;
            #pragma unroll
            for (int kb = 0; kb < 4; kb++) CP16(swz_addr(dst, tid, kb), pa + kb * 8);
        }
        CP_COMMIT();
        if (i + 1 < nChunks) {
            char* vbuf = smem + 4 * AVS_A + ((i + 1) & 1) * AVS_V;
            #pragma unroll
            for (int q = 0; q < 6; q++) {
                const uint32_t o0 = swz_addr(0, qh[q],     qs[q] >> 3) + ((qs[q] * 2) & 15);
                const uint32_t o1 = swz_addr(0, qh[q] + 1, qs[q] >> 3) + ((qs[q] * 2) & 15);
                *(uint32_t*)(vbuf + o0) = vlo[q];
                *(uint32_t*)(vbuf + o1) = vhi[q];
            }
            CP_WAIT(2);
            __syncthreads();
        }
    }

    #pragma unroll
    for (int mt = 0; mt < 4; mt++) {
        #pragma unroll
        for (int hh = 0; hh < 2; hh++) {
            const int m = wm * 64 + mt * 16 + (lane >> 2) + hh * 8;
            if (m < L_) {
                const float sc = inv[bh * LP_ + m];
                __half* orow = aoh + ((size_t)b * L_ + m) * D_ + h * HD_;
                #pragma unroll
                for (int nt = 0; nt < 6; nt++) {
                    const int n = wn * 48 + nt * 8 + (lane & 3) * 2;
                    *(__half2*)(orow + n) = __floats2half2_rn(
                        c[mt][nt][hh * 2] * sc, c[mt][nt][hh * 2 + 1] * sc);
                }
            }
        }
    }
}

// ---------------- converters ----------------
// x: 16,777,216 float4 = 8192 blocks x 256 thr x 8 f4 (exact)
__global__ void cvt_x16(const float* __restrict__ in, __half* __restrict__ out)
{
    const size_t base = (size_t)blockIdx.x * 256 + threadIdx.x;
    #pragma unroll
    for (int j = 0; j < 8; j++) {
        const size_t i = base + (size_t)j * 2097152;
        float4 f = ((const float4*)in)[i];
        ((__half2*)out)[2 * i]     = __floats2half2_rn(f.x, f.y);
        ((__half2*)out)[2 * i + 1] = __floats2half2_rn(f.z, f.w);
    }
}
__global__ void cvt_h16(const float* __restrict__ in, __half* __restrict__ out, int n4)
{
    int i = blockIdx.x * 256 + threadIdx.x;
    if (i >= n4) return;
    float4 f = ((const float4*)in)[i];
    ((__half2*)out)[i * 2 + 0] = __floats2half2_rn(f.x, f.y);
    ((__half2*)out)[i * 2 + 1] = __floats2half2_rn(f.z, f.w);
}
// 5x (768x768) weight cvts in one launch: 147456 f4 each = 144 blocks x 256 x 4
__global__ void cvt5(const float* __restrict__ s0, const float* __restrict__ s1,
                     const float* __restrict__ s2, const float* __restrict__ s3,
                     const float* __restrict__ s4,
                     __half* __restrict__ d0, __half* __restrict__ d1,
                     __half* __restrict__ d2, __half* __restrict__ d3,
                     __half* __restrict__ d4)
{
    const int m = blockIdx.y;
    const float* src = (m == 0) ? s0 : (m == 1) ? s1 : (m == 2) ? s2 : (m == 3) ? s3 : s4;
    __half* dst      = (m == 0) ? d0 : (m == 1) ? d1 : (m == 2) ? d2 : (m == 3) ? d3 : d4;
    const int base = blockIdx.x * 256 + threadIdx.x;
    #pragma unroll
    for (int j = 0; j < 4; j++) {
        const int i = base + j * 36864;
        float4 f = ((const float4*)src)[i];
        ((__half2*)dst)[2 * i]     = __floats2half2_rn(f.x, f.y);
        ((__half2*)dst)[2 * i + 1] = __floats2half2_rn(f.z, f.w);
    }
}
__global__ void concat_bias(const float* __restrict__ bk, const float* __restrict__ bv,
                            float* __restrict__ bkv)
{
    int i = blockIdx.x * 256 + threadIdx.x;
    if (i < D_) bkv[i] = bk[i];
    else if (i < NKV_) bkv[i] = bv[i - D_];
}
// transpose dup_pool: dp[l][d][f] -> dpT[l*10+f][d], d in [0,1536)
__global__ void transpose_dp(const float* __restrict__ dp, float* __restrict__ dpT)
{
    __shared__ float sm[384 * DF_];
    const int l = blockIdx.x, d0 = blockIdx.y * 384;
    const float* src = dp + (size_t)l * (2 * D_) * DF_ + (size_t)d0 * DF_;
    for (int i = threadIdx.x; i < 384 * DF_; i += 256) sm[i] = src[i];
    __syncthreads();
    for (int i = threadIdx.x; i < 384 * DF_; i += 256) {
        const int f = i / 384, d = i - f * 384;
        dpT[(size_t)(l * DF_ + f) * (2 * D_) + d0 + d] = sm[d * DF_ + f];
    }
}

// ---------------- block reduction ----------------
__device__ __forceinline__ float blockSum256(float v, float* sm) {
    #pragma unroll
    for (int o = 16; o > 0; o >>= 1) v += __shfl_xor_sync(0xffffffffu, v, o);
    const int w = threadIdx.x >> 5, lane = threadIdx.x & 31;
    if (lane == 0) sm[w] = v;
    __syncthreads();
    float r = (lane < 8) ? sm[lane] : 0.0f;
    #pragma unroll
    for (int o = 4; o > 0; o >>= 1) r += __shfl_xor_sync(0xffffffffu, r, o);
    r = __shfl_sync(0xffffffffu, r, 0);
    __syncthreads();
    return r;
}

// ---------------- row LayerNorm; optional fp16 output ----------------
__global__ void ln_rows(const float* __restrict__ X, const float* __restrict__ gg,
                        const float* __restrict__ bb, float* __restrict__ O, float alpha,
                        __half* __restrict__ Oh)
{
    __shared__ float sm[8];
    const int row = blockIdx.x;
    const float* x = X + (size_t)row * D_;
    float v[3];
    float s = 0.0f, sq = 0.0f;
    #pragma unroll
    for (int j = 0; j < 3; j++) {
        v[j] = alpha * x[threadIdx.x + j * 256];
        s += v[j]; sq += v[j] * v[j];
    }
    s  = blockSum256(s, sm);
    sq = blockSum256(sq, sm);
    const float mean = s * (1.0f / D_);
    const float var  = sq * (1.0f / D_) - mean * mean;
    const float inv  = rsqrtf(var + 1e-5f);
    float* o = O + (size_t)row * D_;
    #pragma unroll
    for (int j = 0; j < 3; j++) {
        const int i = threadIdx.x + j * 256;
        const float ov = (v[j] - mean) * inv * gg[i] + bb[i];
        o[i] = ov;
        if (Oh) Oh[(size_t)row * D_ + i] = __float2half_rn(ov);
    }
}

// ---------------- q projection -> fp16 padded [H][128][96], scale folded ----------------
__global__ void qproj(const float* __restrict__ t, const float* __restrict__ Wq,
                      const float* __restrict__ bq, __half* __restrict__ q16)
{
    const int l = blockIdx.x;
    const int e = blockIdx.y * 128 + threadIdx.x;
    __shared__ float ts[D_];
    for (int i = threadIdx.x; i < D_; i += 128) ts[i] = t[(size_t)l * D_ + i];
    __syncthreads();
    const float* w = Wq + (size_t)e * D_;
    float acc = 0.0f;
    #pragma unroll 8
    for (int d = 0; d < D_; d++) acc = fmaf(ts[d], w[d], acc);
    const float val = (acc + bq[e]) * 0.10206207261596575f;   // 1/sqrt(96)
    const int hh = e / HD_, eh = e - hh * HD_;
    q16[(size_t)hh * LP_ * HD_ + (size_t)l * HD_ + eh] = __float2half_rn(val);
}

// ---------------- sum_mean, warp-per-head: inv + a_score in one pass, 1 sync ----
__global__ void __launch_bounds__(256)
sum_mean(const __half* __restrict__ s16, float* __restrict__ invO,
         float* __restrict__ ascore)
{
    __shared__ float shf[8 * 1025];       // [h][s] padded stride 1025 (conflict-free)
    const int l = blockIdx.x, b = blockIdx.y;
    const int w = threadIdx.x >> 5, lane = threadIdx.x & 31;
    const int bh = b * H_ + w;

    // each lane loads 32 contiguous halves (4 x int4) of its head's row
    const int4* r4 = (const int4*)(s16 + ((size_t)bh * LP_ + l) * S_);
    int4 t[4];
    #pragma unroll
    for (int j = 0; j < 4; j++) t[j] = r4[lane + j * 32];

    float vals[32];
    float ssum = 0.0f;
    #pragma unroll
    for (int j = 0; j < 4; j++) {
        const __half2* hp = (const __half2*)&t[j];
        #pragma unroll
        for (int k = 0; k < 4; k++) {
            float2 f = __half22float2(hp[k]);
            vals[j * 8 + k * 2]     = f.x;
            vals[j * 8 + k * 2 + 1] = f.y;
            ssum += f.x + f.y;
        }
    }
    #pragma unroll
    for (int o = 16; o > 0; o >>= 1) ssum += __shfl_xor_sync(0xffffffffu, ssum, o);
    const float inv = 1.0f / ssum;
    if (lane == 0) invO[bh * LP_ + l] = inv;
    const float inv8 = inv * 0.125f;

    float* rowm = &shf[w * 1025];
    #pragma unroll
    for (int j = 0; j < 4; j++) {
        const int p0 = 8 * (lane + j * 32);
        #pragma unroll
        for (int k = 0; k < 8; k++) rowm[p0 + k] = vals[j * 8 + k] * inv8;
    }
    __syncthreads();

    float* ao = ascore + ((size_t)b * L_ + l) * S_;
    #pragma unroll
    for (int j = 0; j < 4; j++) {
        const int sp = threadIdx.x + j * 256;
        float a = 0.0f;
        #pragma unroll
        for (int hh = 0; hh < 8; hh++) a += shf[hh * 1025 + sp];
        ao[sp] = a;
    }
}

// ---------------- GroupFC terms on transposed pool (coalesced) ----------------
__global__ void yterm_kernel(const float* __restrict__ y, const float* __restrict__ dpT,
                             const float* __restrict__ dbias, float* __restrict__ yt)
{
    const int l = blockIdx.x;
    const int w = threadIdx.x >> 5, lane = threadIdx.x & 31;    // 10 warps
    const float* row = dpT + (size_t)(l * DF_ + w) * (2 * D_) + D_;
    const float* yr = y + (size_t)l * D_;
    float acc = 0.0f;
    for (int d = lane; d < D_; d += 32) acc = fmaf(yr[d], row[d], acc);
    #pragma unroll
    for (int o = 16; o > 0; o >>= 1) acc += __shfl_xor_sync(0xffffffffu, acc, o);
    if (lane == 0) yt[l * DF_ + w] = acc + dbias[l * DF_ + w];
}

__global__ void logits_kernel(const float* __restrict__ hh, const float* __restrict__ dpT,
                              const float* __restrict__ yt, float* __restrict__ out)
{
    const int l = blockIdx.x, b = blockIdx.y;
    const int w = threadIdx.x >> 5, lane = threadIdx.x & 31;    // 10 warps
    __shared__ float hs[D_];
    for (int i = threadIdx.x; i < D_; i += 320) hs[i] = hh[((size_t)b * L_ + l) * D_ + i];
    __syncthreads();
    const float* row = dpT + (size_t)(l * DF_ + w) * (2 * D_);
    float acc = 0.0f;
    for (int d = lane; d < D_; d += 32) acc = fmaf(hs[d], row[d], acc);
    #pragma unroll
    for (int o = 16; o > 0; o >>= 1) acc += __shfl_xor_sync(0xffffffffu, acc, o);
    if (lane == 0) out[(size_t)b * C_ + l * DF_ + w] = acc + yt[l * DF_ + w];
}

// ---------------- host launch ----------------
extern "C" void kernel_launch(void* const* d_in, const int* in_sizes, int n_in,
                              void* d_out, int out_size)
{
    const float* x       = (const float*)d_in[0];
    const float* y       = (const float*)d_in[1];
    const float* embed_W = (const float*)d_in[2];
    const float* embed_b = (const float*)d_in[3];
    const float* Wq      = (const float*)d_in[4];
    const float* Wk      = (const float*)d_in[5];
    const float* Wv      = (const float*)d_in[6];
    const float* bq      = (const float*)d_in[7];
    const float* bk      = (const float*)d_in[8];
    const float* bv      = (const float*)d_in[9];
    const float* Wo      = (const float*)d_in[10];
    const float* bo      = (const float*)d_in[11];
    const float* ln1_g   = (const float*)d_in[12];
    const float* ln1_b   = (const float*)d_in[13];
    const float* ln2_g   = (const float*)d_in[14];
    const float* ln2_b   = (const float*)d_in[15];
    const float* ln3_g   = (const float*)d_in[16];
    const float* ln3_b   = (const float*)d_in[17];
    const float* W1      = (const float*)d_in[18];
    const float* b1      = (const float*)d_in[19];
    const float* W2      = (const float*)d_in[20];
    const float* b2      = (const float*)d_in[21];
    const float* dp      = (const float*)d_in[22];
    const float* dbias   = (const float*)d_in[23];
    float* out = (float*)d_out;

    float *pt, *px2, *pt2, *px3, *ph, *pyt, *pbkv, *pinv, *pdpT, *pdump;
    __half *pq16, *ps16, *pkv16, *pxh, *pmemh, *paoh, *pt2h, *pf1h;
    __half *pwemb, *pwkv, *pwo, *pw1, *pw2;
    cudaGetSymbolAddress((void**)&pt,    g_t);
    cudaGetSymbolAddress((void**)&px2,   g_x2);
    cudaGetSymbolAddress((void**)&pt2,   g_t2);
    cudaGetSymbolAddress((void**)&px3,   g_x3);
    cudaGetSymbolAddress((void**)&ph,    g_h);
    cudaGetSymbolAddress((void**)&pyt,   g_yt);
    cudaGetSymbolAddress((void**)&pbkv,  g_bkv);
    cudaGetSymbolAddress((void**)&pinv,  g_inv);
    cudaGetSymbolAddress((void**)&pdpT,  g_dpT);
    cudaGetSymbolAddress((void**)&pdump, g_ascdump);
    cudaGetSymbolAddress((void**)&pq16,  g_q16);
    cudaGetSymbolAddress((void**)&ps16,  g_s16);
    cudaGetSymbolAddress((void**)&pkv16, g_kv16);
    cudaGetSymbolAddress((void**)&pxh,   g_xh);
    cudaGetSymbolAddress((void**)&pmemh, g_memh);
    cudaGetSymbolAddress((void**)&paoh,  g_aoh);
    cudaGetSymbolAddress((void**)&pt2h,  g_t2h);
    cudaGetSymbolAddress((void**)&pf1h,  g_f1h);
    cudaGetSymbolAddress((void**)&pwemb, g_wemb);
    cudaGetSymbolAddress((void**)&pwkv,  g_wkv);
    cudaGetSymbolAddress((void**)&pwo,   g_wo);
    cudaGetSymbolAddress((void**)&pw1,   g_w1);
    cudaGetSymbolAddress((void**)&pw2,   g_w2);

    cudaFuncSetAttribute(gemm16<true, 0, true, false>,  cudaFuncAttributeMaxDynamicSharedMemorySize, GM_SMEM);
    cudaFuncSetAttribute(gemm16<false, 0, true, false>, cudaFuncAttributeMaxDynamicSharedMemorySize, GM_SMEM);
    cudaFuncSetAttribute(gemm16<false, 0, false, true>, cudaFuncAttributeMaxDynamicSharedMemorySize, GM_SMEM);
    cudaFuncSetAttribute(gemm16<false, 2, true, false>, cudaFuncAttributeMaxDynamicSharedMemorySize, GM_SMEM);
    cudaFuncSetAttribute(gemm16<false, 1, true, false>, cudaFuncAttributeMaxDynamicSharedMemorySize, GM_SMEM);
    cudaFuncSetAttribute(attn_v_mma, cudaFuncAttributeMaxDynamicSharedMemorySize, AV_SMEM);

    float* asc = (out_size >= B_ * C_ + B_ * L_ * S_) ? (out + B_ * C_) : pdump;

    // side stream + fork/join events (created once; identical work every call)
    static cudaStream_t sS = nullptr;
    static cudaEvent_t evF = nullptr, evJ = nullptr;
    if (sS == nullptr) {
        cudaStreamCreateWithFlags(&sS, cudaStreamNonBlocking);
        cudaEventCreateWithFlags(&evF, cudaEventDisableTiming);
        cudaEventCreateWithFlags(&evJ, cudaEventDisableTiming);
    }

    // ---- fork: preamble on side stream, overlapped with cvt-x + embed ----
    cudaEventRecord(evF, 0);
    cudaStreamWaitEvent(sS, evF, 0);
    cvt5<<<dim3(144, 5), 256, 0, sS>>>(Wk, Wv, Wo, W1, W2,
                                       pwkv, pwkv + (size_t)D_ * D_, pwo, pw1, pw2);
    concat_bias<<<(NKV_ + 255) / 256, 256, 0, sS>>>(bk, bv, pbkv);
    transpose_dp<<<dim3(L_, 4), 256, 0, sS>>>(dp, pdpT);
    ln_rows<<<L_, 256, 0, sS>>>(y, ln1_g, ln1_b, pt, 2.0f, nullptr);       // t = LN(2y)
    qproj<<<dim3(L_, D_ / 128), 128, 0, sS>>>(pt, Wq, bq, pq16);
    yterm_kernel<<<L_, 320, 0, sS>>>(y, pdpT, dbias, pyt);
    cudaEventRecord(evJ, sS);

    // ---- main stream: embed critical path ----
    cvt_x16<<<8192, 256>>>(x, pxh);
    cvt_h16<<<(D_ * F0_ / 4 + 255) / 256, 256>>>(embed_W, pwemb, D_ * F0_ / 4);
    gemm16<true, 0, true, false><<<dim3(D_ / 128, BS_ / 128, 1), 256, GM_SMEM>>>(
        pxh, pwemb, embed_b, nullptr, nullptr, pmemh,
        F0_, F0_, F0_, D_, 0, 0, 0, 0, 0);

    // ---- join: everything below may need side-stream results ----
    cudaStreamWaitEvent(0, evJ, 0);

    // ---- fused K|V GEMM -> fp16 kv (pitch 1536) ----
    gemm16<false, 0, true, false><<<dim3(NKV_ / 128, BS_ / 128, 1), 256, GM_SMEM>>>(
        pmemh, pwkv, pbkv, nullptr, nullptr, pkv16,
        D_, D_, D_, NKV_, 0, 0, 0, 0, 0);

    // ---- scores + fused exp: per (b,h) GEMM -> exp(s) fp16 ----
    gemm16<false, 0, false, true><<<dim3(S_ / 128, 1, B_ * H_), 256, GM_SMEM>>>(
        pq16, pkv16, nullptr, nullptr, nullptr, ps16,
        HD_, HD_, NKV_, S_, 0,
        (size_t)LP_ * HD_, (size_t)S_ * NKV_, (size_t)HD_, (size_t)LP_ * S_);

    // ---- row sums + head-mean a_score (warp-per-head, 1 sync) ----
    sum_mean<<<dim3(L_, B_), 256>>>(ps16, pinv, asc);

    // ---- (exp @ V) * inv -> ao fp16 ----
    attn_v_mma<<<B_ * H_, 128, AV_SMEM>>>(ps16, pkv16, pinv, paoh);

    // ---- out-proj + residual t[l], LN2 ----
    gemm16<false, 2, true, false><<<dim3(D_ / 128, BL_ / 128, 1), 256, GM_SMEM>>>(
        paoh, pwo, bo, pt, px2, nullptr,
        D_, D_, D_, D_, L_, 0, 0, 0, 0);
    ln_rows<<<BL_, 256>>>(px2, ln2_g, ln2_b, pt2, 1.0f, pt2h);

    // ---- FFN ----
    gemm16<true, 0, true, false><<<dim3(D_ / 128, BL_ / 128, 1), 256, GM_SMEM>>>(
        pt2h, pw1, b1, nullptr, nullptr, pf1h,
        D_, D_, D_, D_, 0, 0, 0, 0, 0);
    gemm16<false, 1, true, false><<<dim3(D_ / 128, BL_ / 128, 1), 256, GM_SMEM>>>(
        pf1h, pw2, b2, pt2, px3, nullptr,
        D_, D_, D_, D_, 0, 0, 0, 0, 0);
    ln_rows<<<BL_, 256>>>(px3, ln3_g, ln3_b, ph, 1.0f, nullptr);

    // ---- GroupFC logits ----
    logits_kernel<<<dim3(L_, B_), 320>>>(ph, pdpT, pyt, out);
}

// round 14
// speedup vs baseline: 1.2233x; 1.0111x over previous
#include <cuda_runtime.h>
#include <cuda_fp16.h>
#include <math.h>
#include <stdint.h>

#define B_  32
#define S_  1024
#define F0_ 2048
#define D_  768
#define L_  100
#define H_  8
#define HD_ 96
#define DF_ 10
#define C_  1000
#define BL_ (B_*L_)   // 3200
#define BS_ (B_*S_)   // 32768
#define NKV_ 1536
#define LP_ 128       // L padded to 128

// ---------------- scratch (static __device__, zero-initialized) ----------------
static __device__ __align__(128) float g_t  [L_*D_];
static __device__ __align__(128) float g_x2 [(size_t)BL_*D_];
static __device__ __align__(128) float g_t2 [(size_t)BL_*D_];
static __device__ __align__(128) float g_x3 [(size_t)BL_*D_];
static __device__ __align__(128) float g_h  [(size_t)BL_*D_];
static __device__ __align__(128) float g_yt [C_];
static __device__ __align__(128) float g_bkv[NKV_];
static __device__ __align__(128) float g_inv[B_*H_*LP_];          // 1/rowsum of exp
static __device__ __align__(128) float g_dpT[(size_t)C_*2*D_];    // transposed dup_pool
static __device__ __align__(128) float g_ascdump[(size_t)B_*L_*S_];

// fp16 planes
static __device__ __align__(128) __half g_q16 [H_*LP_*HD_];
static __device__ __align__(128) __half g_s16 [(size_t)B_*H_*LP_*S_];  // exp(scores)
static __device__ __align__(128) __half g_kv16[(size_t)BS_*NKV_];      // k | v fp16, pitch 1536
static __device__ __align__(128) __half g_xh  [(size_t)BS_*F0_];
static __device__ __align__(128) __half g_memh[(size_t)BS_*D_];
static __device__ __align__(128) __half g_aoh [(size_t)BL_*D_];
static __device__ __align__(128) __half g_t2h [(size_t)BL_*D_];
static __device__ __align__(128) __half g_f1h [(size_t)BL_*D_];
static __device__ __align__(128) __half g_wemb[(size_t)D_*F0_];
static __device__ __align__(128) __half g_wkv [(size_t)NKV_*D_];
static __device__ __align__(128) __half g_wo  [(size_t)D_*D_];
static __device__ __align__(128) __half g_w1  [(size_t)D_*D_];
static __device__ __align__(128) __half g_w2  [(size_t)D_*D_];

// ============================================================================
// PTX helpers (sm_80-era baseline; safe on non-'a' compute_103 PTX target)
// ============================================================================
__device__ __forceinline__ uint32_t smem_u32(const void* p) {
    uint32_t a;
    asm("{ .reg .u64 t; cvta.to.shared.u64 t, %1; cvt.u32.u64 %0, t; }" : "=r"(a) : "l"(p));
    return a;
}
#define LDSM4(r, addr)                                                            \
    asm volatile("ldmatrix.sync.aligned.m8n8.x4.shared.b16 {%0,%1,%2,%3}, [%4];"  \
        : "=r"((r)[0]), "=r"((r)[1]), "=r"((r)[2]), "=r"((r)[3]) : "r"(addr))
#define LDSM2(r, addr)                                                            \
    asm volatile("ldmatrix.sync.aligned.m8n8.x2.shared.b16 {%0,%1}, [%2];"        \
        : "=r"((r)[0]), "=r"((r)[1]) : "r"(addr))
#define MMAF16(c, a, b0, b1)                                                      \
    asm volatile("mma.sync.aligned.m16n8k16.row.col.f32.f16.f16.f32 "             \
        "{%0,%1,%2,%3}, {%4,%5,%6,%7}, {%8,%9}, {%0,%1,%2,%3};"                   \
        : "+f"((c)[0]), "+f"((c)[1]), "+f"((c)[2]), "+f"((c)[3])                  \
        : "r"((a)[0]), "r"((a)[1]), "r"((a)[2]), "r"((a)[3]), "r"(b0), "r"(b1))
#define CP16(dst, src)                                                            \
    asm volatile("cp.async.cg.shared.global [%0], [%1], 16;" :: "r"(dst), "l"(src))
#define CP_COMMIT() asm volatile("cp.async.commit_group;" ::: "memory")
#define CP_WAIT(n)  asm volatile("cp.async.wait_group %0;" :: "n"(n) : "memory")

// swizzle for 64B logical rows packed 2-per-128B line (conflict-free ldmatrix)
__device__ __forceinline__ uint32_t swz_addr(uint32_t base, int r, int kb) {
    uint32_t line = (uint32_t)r >> 1;
    uint32_t slot = ((((uint32_t)r & 1u) << 2) | (uint32_t)kb) ^ (line & 7u);
    return base + line * 128u + slot * 16u;
}

// fast exp on FMA pipe; clamped so fp16 store cannot overflow
__device__ __forceinline__ float fexp(float x) {
    float p = x * 1.4426950408889634f;
    p = fmaxf(fminf(p, 15.5f), -120.0f);
    float nf = rintf(p);
    float f = p - nf;
    float r = 0.0013333558146428443f;
    r = fmaf(r, f, 0.009618129107628477f);
    r = fmaf(r, f, 0.05550410866482158f);
    r = fmaf(r, f, 0.2402265069591007f);
    r = fmaf(r, f, 0.6931471805599453f);
    r = fmaf(r, f, 1.0f);
    return r * __int_as_float(((int)nf + 127) << 23);
}

// ============================================================================
// 1-pass fp16 HMMA GEMM, 256 threads (2x4 warps, 64x32 warp tiles), 2 CTAs/SM
// (16 warps/SM). CTA tile 128x128, 4-stage cp.async.  [UNCHANGED]
// ============================================================================
#define STG_BYTES 16384u
#define GM_SMEM (4u * STG_BYTES)   // 65536

__device__ __forceinline__ void load_stage(uint32_t sbase,
    const __half* __restrict__ Ah, const __half* __restrict__ Bw,
    int bm, int bn, int lda, int ldb, int k0, int tid)
{
    const int row = tid >> 1, kb0 = (tid & 1) * 2;
    const __half* pa = Ah + (size_t)(bm + row) * lda + k0 + kb0 * 8;
    CP16(swz_addr(sbase, row, kb0),     pa);
    CP16(swz_addr(sbase, row, kb0 + 1), pa + 8);
    const __half* pb = Bw + (size_t)(bn + row) * ldb + k0 + kb0 * 8;
    CP16(swz_addr(sbase + 8192u, row, kb0),     pb);
    CP16(swz_addr(sbase + 8192u, row, kb0 + 1), pb + 8);
    CP_COMMIT();
}

template<bool RELU, int RES, bool BIAS, bool EXP>
__global__ void __launch_bounds__(256, 2)
gemm16(const __half* __restrict__ Ah, const __half* __restrict__ Bw,
       const float* __restrict__ bias, const float* __restrict__ Res,
       float* __restrict__ C, __half* __restrict__ Chi,
       int K, int lda, int ldb, int ldc, int resMod,
       size_t oAh, size_t oBb, size_t oBh, size_t oC)
{
    extern __shared__ char smem[];
    const uint32_t sb = smem_u32(smem);
    const int tid = threadIdx.x, lane = tid & 31, wid = tid >> 5;
    const int wm = wid >> 2, wn = wid & 3;          // 2 x 4 warps, 64x32 tiles
    const int bm = blockIdx.y * 128, bn = blockIdx.x * 128;
    const int z = blockIdx.z, hz = z & 7, bz = z >> 3;
    Ah += (size_t)hz * oAh;
    Bw += (size_t)bz * oBb + (size_t)hz * oBh;
    const size_t coff = (size_t)z * oC;
    const int nc = K >> 5;

    float c[4][4][4];
    #pragma unroll
    for (int mt = 0; mt < 4; mt++)
        #pragma unroll
        for (int nt = 0; nt < 4; nt++)
            #pragma unroll
            for (int q = 0; q < 4; q++) c[mt][nt][q] = 0.0f;

    uint32_t offA[4][2], offB[2][2];
    {
        const int aR = lane & 15, aKb = lane >> 4;
        const int bR = (lane & 7) | ((lane >> 4) << 3);
        const int bKb = (lane >> 3) & 1;
        #pragma unroll
        for (int mt = 0; mt < 4; mt++)
            #pragma unroll
            for (int ks = 0; ks < 2; ks++)
                offA[mt][ks] = swz_addr(0, wm * 64 + mt * 16 + aR, ks * 2 + aKb);
        #pragma unroll
        for (int p = 0; p < 2; p++)
            #pragma unroll
            for (int ks = 0; ks < 2; ks++)
                offB[p][ks] = 8192u +
                    swz_addr(0, wn * 32 + p * 16 + bR, ks * 2 + bKb);
    }

    #pragma unroll
    for (int s = 0; s < 3; s++)
        load_stage(sb + s * STG_BYTES, Ah, Bw, bm, bn, lda, ldb, s * 32, tid);

    for (int i = 0; i < nc; i++) {
        CP_WAIT(2);
        __syncthreads();
        if (i + 3 < nc)
            load_stage(sb + (uint32_t)((i + 3) & 3) * STG_BYTES, Ah, Bw,
                       bm, bn, lda, ldb, (i + 3) * 32, tid);
        else
            CP_COMMIT();     // keep group count exact (no tail race)
        const uint32_t st = sb + (uint32_t)(i & 3) * STG_BYTES;
        #pragma unroll
        for (int ks = 0; ks < 2; ks++) {
            uint32_t aF[4][4], bf[2][4];
            #pragma unroll
            for (int mt = 0; mt < 4; mt++) LDSM4(aF[mt], st + offA[mt][ks]);
            #pragma unroll
            for (int p = 0; p < 2; p++) LDSM4(bf[p], st + offB[p][ks]);
            #pragma unroll
            for (int mt = 0; mt < 4; mt++)
                #pragma unroll
                for (int nt = 0; nt < 4; nt++)
                    MMAF16(c[mt][nt], aF[mt],
                           bf[nt >> 1][(nt & 1) * 2], bf[nt >> 1][(nt & 1) * 2 + 1]);
        }
    }

    #pragma unroll
    for (int mt = 0; mt < 4; mt++) {
        #pragma unroll
        for (int hh = 0; hh < 2; hh++) {
            const int m = bm + wm * 64 + mt * 16 + (lane >> 2) + hh * 8;
            const float* resRow = (RES == 1) ? (Res + (size_t)m * ldc)
                                : (RES == 2) ? (Res + (size_t)(m % resMod) * ldc)
                                : nullptr;
            #pragma unroll
            for (int nt = 0; nt < 4; nt++) {
                const int n = bn + wn * 32 + nt * 8 + (lane & 3) * 2;
                float vx = c[mt][nt][hh * 2 + 0];
                float vy = c[mt][nt][hh * 2 + 1];
                if (BIAS) { vx += bias[n]; vy += bias[n + 1]; }
                if (RES != 0) { vx += resRow[n]; vy += resRow[n + 1]; }
                if (RELU) { vx = fmaxf(vx, 0.f); vy = fmaxf(vy, 0.f); }
                if (EXP)  { vx = fexp(vx); vy = fexp(vy); }
                if (C) *(float2*)(C + coff + (size_t)m * ldc + n) = make_float2(vx, vy);
                if (Chi)
                    *(__half2*)(Chi + coff + (size_t)m * ldc + n) = __floats2half2_rn(vx, vy);
            }
        }
    }
}

// ============================================================================
// attn_v, 256 threads (2x4 warps, warp tile 64x24, ldmatrix.x2 B):
// ao[b,l,h*96+:] = (exp[bh,l,:] @ V[b,:,h*96+:]) * inv[bh,l]
// ============================================================================
#define AVS_A 8192u
#define AVS_V 6144u
#define AV_SMEM (4u*AVS_A + 2u*AVS_V)   // 45056

__global__ void __launch_bounds__(256, 2)
attn_v_mma(const __half* __restrict__ probs, const __half* __restrict__ kv16,
           const float* __restrict__ inv, __half* __restrict__ aoh)
{
    extern __shared__ char smem[];
    const uint32_t sb = smem_u32(smem);
    const int tid = threadIdx.x, lane = tid & 31, wid = tid >> 5;
    const int wm = wid >> 2, wn = wid & 3;          // 2 x 4, warp tile 64x24
    const int bh = blockIdx.x, b = bh >> 3, h = bh & 7;
    const __half* A = probs + (size_t)bh * LP_ * S_;
    const __half* V = kv16 + (size_t)b * S_ * NKV_ + D_ + h * HD_;

    float c[4][3][4];
    #pragma unroll
    for (int mt = 0; mt < 4; mt++)
        #pragma unroll
        for (int nt = 0; nt < 3; nt++)
            #pragma unroll
            for (int q = 0; q < 4; q++) c[mt][nt][q] = 0.0f;

    uint32_t offA[4][2], offB[3][2];
    {
        const int aR = lane & 15, aKb = lane >> 4;
        #pragma unroll
        for (int mt = 0; mt < 4; mt++)
            #pragma unroll
            for (int ks = 0; ks < 2; ks++)
                offA[mt][ks] = swz_addr(0, wm * 64 + mt * 16 + aR, ks * 2 + aKb);
        // LDSM2: lanes 0-7 -> (n-rows, khalf0); lanes 8-15 -> (n-rows, khalf1)
        const int bR = lane & 7;
        const int bKb = (lane >> 3) & 1;
        #pragma unroll
        for (int nb = 0; nb < 3; nb++)
            #pragma unroll
            for (int ks = 0; ks < 2; ks++)
                offB[nb][ks] = swz_addr(0, wn * 24 + nb * 8 + bR, ks * 2 + bKb);
    }

    // per-thread V quad coordinates: 3 quads of (2 s-rows x 2 hd-cols), 768 total
    int qs[3], qh[3];
    #pragma unroll
    for (int q = 0; q < 3; q++) {
        const int idx = tid + q * 256;            // 0..767
        qs[q] = (idx / 48) * 2;                   // s_local 0..30 even
        qh[q] = (idx % 48) * 2;                   // hd 0..94 even
    }

    uint32_t vlo[3], vhi[3];
    const int nChunks = S_ / 32;                  // 32

    // A staging: 512 CP16/chunk, 2 per thread
    const int arow = tid >> 1, akb0 = (tid & 1) * 2;

    // prologue: A stages 0..2
    #pragma unroll
    for (int s = 0; s < 3; s++) {
        const __half* pa = A + (size_t)arow * S_ + s * 32 + akb0 * 8;
        const uint32_t dst = sb + (uint32_t)s * AVS_A;
        CP16(swz_addr(dst, arow, akb0),     pa);
        CP16(swz_addr(dst, arow, akb0 + 1), pa + 8);
        CP_COMMIT();
    }
    {   // V chunk 0
        #pragma unroll
        for (int q = 0; q < 3; q++) {
            const __half* p = V + (size_t)qs[q] * NKV_ + qh[q];
            const uint32_t v0 = *(const uint32_t*)p;
            const uint32_t v1 = *(const uint32_t*)(p + NKV_);
            vlo[q] = __byte_perm(v0, v1, 0x5410);
            vhi[q] = __byte_perm(v0, v1, 0x7632);
        }
        char* vbuf = smem + 4 * AVS_A;
        #pragma unroll
        for (int q = 0; q < 3; q++) {
            const uint32_t o0 = swz_addr(0, qh[q],     qs[q] >> 3) + ((qs[q] * 2) & 15);
            const uint32_t o1 = swz_addr(0, qh[q] + 1, qs[q] >> 3) + ((qs[q] * 2) & 15);
            *(uint32_t*)(vbuf + o0) = vlo[q];
            *(uint32_t*)(vbuf + o1) = vhi[q];
        }
    }
    CP_WAIT(2);
    __syncthreads();

    for (int i = 0; i < nChunks; i++) {
        // 1. prefetch V regs for chunk i+1
        if (i + 1 < nChunks) {
            const int k0 = (i + 1) * 32;
            #pragma unroll
            for (int q = 0; q < 3; q++) {
                const __half* p = V + (size_t)(k0 + qs[q]) * NKV_ + qh[q];
                const uint32_t v0 = *(const uint32_t*)p;
                const uint32_t v1 = *(const uint32_t*)(p + NKV_);
                vlo[q] = __byte_perm(v0, v1, 0x5410);
                vhi[q] = __byte_perm(v0, v1, 0x7632);
            }
        }
        // 2. MMA chunk i
        const uint32_t stA = sb + (uint32_t)(i & 3) * AVS_A;
        const uint32_t stV = sb + 4u * AVS_A + (uint32_t)(i & 1) * AVS_V;
        #pragma unroll
        for (int ks = 0; ks < 2; ks++) {
            uint32_t aF[4][4], bf[3][2];
            #pragma unroll
            for (int mt = 0; mt < 4; mt++) LDSM4(aF[mt], stA + offA[mt][ks]);
            #pragma unroll
            for (int nb = 0; nb < 3; nb++) LDSM2(bf[nb], stV + offB[nb][ks]);
            #pragma unroll
            for (int mt = 0; mt < 4; mt++)
                #pragma unroll
                for (int nt = 0; nt < 3; nt++)
                    MMAF16(c[mt][nt], aF[mt], bf[nt][0], bf[nt][1]);
        }
        // 3. next A chunk (or empty commit)
        if (i + 3 < nChunks) {
            const __half* pa = A + (size_t)arow * S_ + (i + 3) * 32 + akb0 * 8;
            const uint32_t dst = sb + (uint32_t)((i + 3) & 3) * AVS_A;
            CP16(swz_addr(dst, arow, akb0),     pa);
            CP16(swz_addr(dst, arow, akb0 + 1), pa + 8);
        }
        CP_COMMIT();
        // 4. STS V chunk i+1 into the other buffer; 5. advance
        if (i + 1 < nChunks) {
            char* vbuf = smem + 4 * AVS_A + ((i + 1) & 1) * AVS_V;
            #pragma unroll
            for (int q = 0; q < 3; q++) {
                const uint32_t o0 = swz_addr(0, qh[q],     qs[q] >> 3) + ((qs[q] * 2) & 15);
                const uint32_t o1 = swz_addr(0, qh[q] + 1, qs[q] >> 3) + ((qs[q] * 2) & 15);
                *(uint32_t*)(vbuf + o0) = vlo[q];
                *(uint32_t*)(vbuf + o1) = vhi[q];
            }
            CP_WAIT(2);
            __syncthreads();
        }
    }

    // epilogue: masked rows m<100, n = wn*24 + nb*8 + (lane&3)*2 < 96
    #pragma unroll
    for (int mt = 0; mt < 4; mt++) {
        #pragma unroll
        for (int hh = 0; hh < 2; hh++) {
            const int m = wm * 64 + mt * 16 + (lane >> 2) + hh * 8;
            if (m < L_) {
                const float sc = inv[bh * LP_ + m];
                __half* orow = aoh + ((size_t)b * L_ + m) * D_ + h * HD_;
                #pragma unroll
                for (int nt = 0; nt < 3; nt++) {
                    const int n = wn * 24 + nt * 8 + (lane & 3) * 2;
                    *(__half2*)(orow + n) = __floats2half2_rn(
                        c[mt][nt][hh * 2] * sc, c[mt][nt][hh * 2 + 1] * sc);
                }
            }
        }
    }
}

// ---------------- converters ----------------
__global__ void cvt_x16(const float* __restrict__ in, __half* __restrict__ out)
{
    const size_t base = (size_t)blockIdx.x * 256 + threadIdx.x;
    #pragma unroll
    for (int j = 0; j < 8; j++) {
        const size_t i = base + (size_t)j * 2097152;
        float4 f = ((const float4*)in)[i];
        ((__half2*)out)[2 * i]     = __floats2half2_rn(f.x, f.y);
        ((__half2*)out)[2 * i + 1] = __floats2half2_rn(f.z, f.w);
    }
}
__global__ void cvt_h16(const float* __restrict__ in, __half* __restrict__ out, int n4)
{
    int i = blockIdx.x * 256 + threadIdx.x;
    if (i >= n4) return;
    float4 f = ((const float4*)in)[i];
    ((__half2*)out)[i * 2 + 0] = __floats2half2_rn(f.x, f.y);
    ((__half2*)out)[i * 2 + 1] = __floats2half2_rn(f.z, f.w);
}
__global__ void cvt5(const float* __restrict__ s0, const float* __restrict__ s1,
                     const float* __restrict__ s2, const float* __restrict__ s3,
                     const float* __restrict__ s4,
                     __half* __restrict__ d0, __half* __restrict__ d1,
                     __half* __restrict__ d2, __half* __restrict__ d3,
                     __half* __restrict__ d4)
{
    const int m = blockIdx.y;
    const float* src = (m == 0) ? s0 : (m == 1) ? s1 : (m == 2) ? s2 : (m == 3) ? s3 : s4;
    __half* dst      = (m == 0) ? d0 : (m == 1) ? d1 : (m == 2) ? d2 : (m == 3) ? d3 : d4;
    const int base = blockIdx.x * 256 + threadIdx.x;
    #pragma unroll
    for (int j = 0; j < 4; j++) {
        const int i = base + j * 36864;
        float4 f = ((const float4*)src)[i];
        ((__half2*)dst)[2 * i]     = __floats2half2_rn(f.x, f.y);
        ((__half2*)dst)[2 * i + 1] = __floats2half2_rn(f.z, f.w);
    }
}
__global__ void concat_bias(const float* __restrict__ bk, const float* __restrict__ bv,
                            float* __restrict__ bkv)
{
    int i = blockIdx.x * 256 + threadIdx.x;
    if (i < D_) bkv[i] = bk[i];
    else if (i < NKV_) bkv[i] = bv[i - D_];
}
__global__ void transpose_dp(const float* __restrict__ dp, float* __restrict__ dpT)
{
    __shared__ float sm[384 * DF_];
    const int l = blockIdx.x, d0 = blockIdx.y * 384;
    const float* src = dp + (size_t)l * (2 * D_) * DF_ + (size_t)d0 * DF_;
    for (int i = threadIdx.x; i < 384 * DF_; i += 256) sm[i] = src[i];
    __syncthreads();
    for (int i = threadIdx.x; i < 384 * DF_; i += 256) {
        const int f = i / 384, d = i - f * 384;
        dpT[(size_t)(l * DF_ + f) * (2 * D_) + d0 + d] = sm[d * DF_ + f];
    }
}

// ---------------- block reduction ----------------
__device__ __forceinline__ float blockSum256(float v, float* sm) {
    #pragma unroll
    for (int o = 16; o > 0; o >>= 1) v += __shfl_xor_sync(0xffffffffu, v, o);
    const int w = threadIdx.x >> 5, lane = threadIdx.x & 31;
    if (lane == 0) sm[w] = v;
    __syncthreads();
    float r = (lane < 8) ? sm[lane] : 0.0f;
    #pragma unroll
    for (int o = 4; o > 0; o >>= 1) r += __shfl_xor_sync(0xffffffffu, r, o);
    r = __shfl_sync(0xffffffffu, r, 0);
    __syncthreads();
    return r;
}

// ---------------- row LayerNorm; optional fp16 output ----------------
__global__ void ln_rows(const float* __restrict__ X, const float* __restrict__ gg,
                        const float* __restrict__ bb, float* __restrict__ O, float alpha,
                        __half* __restrict__ Oh)
{
    __shared__ float sm[8];
    const int row = blockIdx.x;
    const float* x = X + (size_t)row * D_;
    float v[3];
    float s = 0.0f, sq = 0.0f;
    #pragma unroll
    for (int j = 0; j < 3; j++) {
        v[j] = alpha * x[threadIdx.x + j * 256];
        s += v[j]; sq += v[j] * v[j];
    }
    s  = blockSum256(s, sm);
    sq = blockSum256(sq, sm);
    const float mean = s * (1.0f / D_);
    const float var  = sq * (1.0f / D_) - mean * mean;
    const float inv  = rsqrtf(var + 1e-5f);
    float* o = O + (size_t)row * D_;
    #pragma unroll
    for (int j = 0; j < 3; j++) {
        const int i = threadIdx.x + j * 256;
        const float ov = (v[j] - mean) * inv * gg[i] + bb[i];
        o[i] = ov;
        if (Oh) Oh[(size_t)row * D_ + i] = __float2half_rn(ov);
    }
}

// ---------------- q projection -> fp16 padded [H][128][96], scale folded ----------------
__global__ void qproj(const float* __restrict__ t, const float* __restrict__ Wq,
                      const float* __restrict__ bq, __half* __restrict__ q16)
{
    const int l = blockIdx.x;
    const int e = blockIdx.y * 128 + threadIdx.x;
    __shared__ float ts[D_];
    for (int i = threadIdx.x; i < D_; i += 128) ts[i] = t[(size_t)l * D_ + i];
    __syncthreads();
    const float* w = Wq + (size_t)e * D_;
    float acc = 0.0f;
    #pragma unroll 8
    for (int d = 0; d < D_; d++) acc = fmaf(ts[d], w[d], acc);
    const float val = (acc + bq[e]) * 0.10206207261596575f;   // 1/sqrt(96)
    const int hh = e / HD_, eh = e - hh * HD_;
    q16[(size_t)hh * LP_ * HD_ + (size_t)l * HD_ + eh] = __float2half_rn(val);
}

// ---------------- sum_mean, warp-per-head (1 sync)  [UNCHANGED] ----------------
__global__ void __launch_bounds__(256)
sum_mean(const __half* __restrict__ s16, float* __restrict__ invO,
         float* __restrict__ ascore)
{
    __shared__ float shf[8 * 1025];
    const int l = blockIdx.x, b = blockIdx.y;
    const int w = threadIdx.x >> 5, lane = threadIdx.x & 31;
    const int bh = b * H_ + w;

    const int4* r4 = (const int4*)(s16 + ((size_t)bh * LP_ + l) * S_);
    int4 t[4];
    #pragma unroll
    for (int j = 0; j < 4; j++) t[j] = r4[lane + j * 32];

    float vals[32];
    float ssum = 0.0f;
    #pragma unroll
    for (int j = 0; j < 4; j++) {
        const __half2* hp = (const __half2*)&t[j];
        #pragma unroll
        for (int k = 0; k < 4; k++) {
            float2 f = __half22float2(hp[k]);
            vals[j * 8 + k * 2]     = f.x;
            vals[j * 8 + k * 2 + 1] = f.y;
            ssum += f.x + f.y;
        }
    }
    #pragma unroll
    for (int o = 16; o > 0; o >>= 1) ssum += __shfl_xor_sync(0xffffffffu, ssum, o);
    const float inv = 1.0f / ssum;
    if (lane == 0) invO[bh * LP_ + l] = inv;
    const float inv8 = inv * 0.125f;

    float* rowm = &shf[w * 1025];
    #pragma unroll
    for (int j = 0; j < 4; j++) {
        const int p0 = 8 * (lane + j * 32);
        #pragma unroll
        for (int k = 0; k < 8; k++) rowm[p0 + k] = vals[j * 8 + k] * inv8;
    }
    __syncthreads();

    float* ao = ascore + ((size_t)b * L_ + l) * S_;
    #pragma unroll
    for (int j = 0; j < 4; j++) {
        const int sp = threadIdx.x + j * 256;
        float a = 0.0f;
        #pragma unroll
        for (int hh = 0; hh < 8; hh++) a += shf[hh * 1025 + sp];
        ao[sp] = a;
    }
}

// ---------------- GroupFC terms (float4 loads on transposed pool) ----------------
__global__ void yterm_kernel(const float* __restrict__ y, const float* __restrict__ dpT,
                             const float* __restrict__ dbias, float* __restrict__ yt)
{
    const int l = blockIdx.x;
    const int w = threadIdx.x >> 5, lane = threadIdx.x & 31;    // 10 warps
    const float4* row = (const float4*)(dpT + (size_t)(l * DF_ + w) * (2 * D_) + D_);
    const float4* yr  = (const float4*)(y + (size_t)l * D_);
    float acc = 0.0f;
    #pragma unroll
    for (int it = 0; it < 6; it++) {
        const float4 a = yr[lane + it * 32];
        const float4 bb = row[lane + it * 32];
        acc = fmaf(a.x, bb.x, acc); acc = fmaf(a.y, bb.y, acc);
        acc = fmaf(a.z, bb.z, acc); acc = fmaf(a.w, bb.w, acc);
    }
    #pragma unroll
    for (int o = 16; o > 0; o >>= 1) acc += __shfl_xor_sync(0xffffffffu, acc, o);
    if (lane == 0) yt[l * DF_ + w] = acc + dbias[l * DF_ + w];
}

__global__ void logits_kernel(const float* __restrict__ hh, const float* __restrict__ dpT,
                              const float* __restrict__ yt, float* __restrict__ out)
{
    const int l = blockIdx.x, b = blockIdx.y;
    const int w = threadIdx.x >> 5, lane = threadIdx.x & 31;    // 10 warps
    __shared__ float hs[D_];
    for (int i = threadIdx.x; i < D_; i += 320) hs[i] = hh[((size_t)b * L_ + l) * D_ + i];
    __syncthreads();
    const float4* row = (const float4*)(dpT + (size_t)(l * DF_ + w) * (2 * D_));
    const float4* hv  = (const float4*)hs;
    float acc = 0.0f;
    #pragma unroll
    for (int it = 0; it < 6; it++) {
        const float4 a = hv[lane + it * 32];
        const float4 bb = row[lane + it * 32];
        acc = fmaf(a.x, bb.x, acc); acc = fmaf(a.y, bb.y, acc);
        acc = fmaf(a.z, bb.z, acc); acc = fmaf(a.w, bb.w, acc);
    }
    #pragma unroll
    for (int o = 16; o > 0; o >>= 1) acc += __shfl_xor_sync(0xffffffffu, acc, o);
    if (lane == 0) out[(size_t)b * C_ + l * DF_ + w] = acc + yt[l * DF_ + w];
}

// ---------------- host launch ----------------
extern "C" void kernel_launch(void* const* d_in, const int* in_sizes, int n_in,
                              void* d_out, int out_size)
{
    const float* x       = (const float*)d_in[0];
    const float* y       = (const float*)d_in[1];
    const float* embed_W = (const float*)d_in[2];
    const float* embed_b = (const float*)d_in[3];
    const float* Wq      = (const float*)d_in[4];
    const float* Wk      = (const float*)d_in[5];
    const float* Wv      = (const float*)d_in[6];
    const float* bq      = (const float*)d_in[7];
    const float* bk      = (const float*)d_in[8];
    const float* bv      = (const float*)d_in[9];
    const float* Wo      = (const float*)d_in[10];
    const float* bo      = (const float*)d_in[11];
    const float* ln1_g   = (const float*)d_in[12];
    const float* ln1_b   = (const float*)d_in[13];
    const float* ln2_g   = (const float*)d_in[14];
    const float* ln2_b   = (const float*)d_in[15];
    const float* ln3_g   = (const float*)d_in[16];
    const float* ln3_b   = (const float*)d_in[17];
    const float* W1      = (const float*)d_in[18];
    const float* b1      = (const float*)d_in[19];
    const float* W2      = (const float*)d_in[20];
    const float* b2      = (const float*)d_in[21];
    const float* dp      = (const float*)d_in[22];
    const float* dbias   = (const float*)d_in[23];
    float* out = (float*)d_out;

    float *pt, *px2, *pt2, *px3, *ph, *pyt, *pbkv, *pinv, *pdpT, *pdump;
    __half *pq16, *ps16, *pkv16, *pxh, *pmemh, *paoh, *pt2h, *pf1h;
    __half *pwemb, *pwkv, *pwo, *pw1, *pw2;
    cudaGetSymbolAddress((void**)&pt,    g_t);
    cudaGetSymbolAddress((void**)&px2,   g_x2);
    cudaGetSymbolAddress((void**)&pt2,   g_t2);
    cudaGetSymbolAddress((void**)&px3,   g_x3);
    cudaGetSymbolAddress((void**)&ph,    g_h);
    cudaGetSymbolAddress((void**)&pyt,   g_yt);
    cudaGetSymbolAddress((void**)&pbkv,  g_bkv);
    cudaGetSymbolAddress((void**)&pinv,  g_inv);
    cudaGetSymbolAddress((void**)&pdpT,  g_dpT);
    cudaGetSymbolAddress((void**)&pdump, g_ascdump);
    cudaGetSymbolAddress((void**)&pq16,  g_q16);
    cudaGetSymbolAddress((void**)&ps16,  g_s16);
    cudaGetSymbolAddress((void**)&pkv16, g_kv16);
    cudaGetSymbolAddress((void**)&pxh,   g_xh);
    cudaGetSymbolAddress((void**)&pmemh, g_memh);
    cudaGetSymbolAddress((void**)&paoh,  g_aoh);
    cudaGetSymbolAddress((void**)&pt2h,  g_t2h);
    cudaGetSymbolAddress((void**)&pf1h,  g_f1h);
    cudaGetSymbolAddress((void**)&pwemb, g_wemb);
    cudaGetSymbolAddress((void**)&pwkv,  g_wkv);
    cudaGetSymbolAddress((void**)&pwo,   g_wo);
    cudaGetSymbolAddress((void**)&pw1,   g_w1);
    cudaGetSymbolAddress((void**)&pw2,   g_w2);

    cudaFuncSetAttribute(gemm16<true, 0, true, false>,  cudaFuncAttributeMaxDynamicSharedMemorySize, GM_SMEM);
    cudaFuncSetAttribute(gemm16<false, 0, true, false>, cudaFuncAttributeMaxDynamicSharedMemorySize, GM_SMEM);
    cudaFuncSetAttribute(gemm16<false, 0, false, true>, cudaFuncAttributeMaxDynamicSharedMemorySize, GM_SMEM);
    cudaFuncSetAttribute(gemm16<false, 2, true, false>, cudaFuncAttributeMaxDynamicSharedMemorySize, GM_SMEM);
    cudaFuncSetAttribute(gemm16<false, 1, true, false>, cudaFuncAttributeMaxDynamicSharedMemorySize, GM_SMEM);
    cudaFuncSetAttribute(attn_v_mma, cudaFuncAttributeMaxDynamicSharedMemorySize, AV_SMEM);

    float* asc = (out_size >= B_ * C_ + B_ * L_ * S_) ? (out + B_ * C_) : pdump;

    static cudaStream_t sS = nullptr;
    static cudaEvent_t evF = nullptr, evJ = nullptr;
    if (sS == nullptr) {
        cudaStreamCreateWithFlags(&sS, cudaStreamNonBlocking);
        cudaEventCreateWithFlags(&evF, cudaEventDisableTiming);
        cudaEventCreateWithFlags(&evJ, cudaEventDisableTiming);
    }

    // ---- fork: preamble on side stream ----
    cudaEventRecord(evF, 0);
    cudaStreamWaitEvent(sS, evF, 0);
    cvt5<<<dim3(144, 5), 256, 0, sS>>>(Wk, Wv, Wo, W1, W2,
                                       pwkv, pwkv + (size_t)D_ * D_, pwo, pw1, pw2);
    concat_bias<<<(NKV_ + 255) / 256, 256, 0, sS>>>(bk, bv, pbkv);
    transpose_dp<<<dim3(L_, 4), 256, 0, sS>>>(dp, pdpT);
    ln_rows<<<L_, 256, 0, sS>>>(y, ln1_g, ln1_b, pt, 2.0f, nullptr);       // t = LN(2y)
    qproj<<<dim3(L_, D_ / 128), 128, 0, sS>>>(pt, Wq, bq, pq16);
    yterm_kernel<<<L_, 320, 0, sS>>>(y, pdpT, dbias, pyt);
    cudaEventRecord(evJ, sS);

    // ---- main stream: embed critical path ----
    cvt_x16<<<8192, 256>>>(x, pxh);
    cvt_h16<<<(D_ * F0_ / 4 + 255) / 256, 256>>>(embed_W, pwemb, D_ * F0_ / 4);
    gemm16<true, 0, true, false><<<dim3(D_ / 128, BS_ / 128, 1), 256, GM_SMEM>>>(
        pxh, pwemb, embed_b, nullptr, nullptr, pmemh,
        F0_, F0_, F0_, D_, 0, 0, 0, 0, 0);

    // ---- join ----
    cudaStreamWaitEvent(0, evJ, 0);

    // ---- fused K|V GEMM -> fp16 kv (pitch 1536) ----
    gemm16<false, 0, true, false><<<dim3(NKV_ / 128, BS_ / 128, 1), 256, GM_SMEM>>>(
        pmemh, pwkv, pbkv, nullptr, nullptr, pkv16,
        D_, D_, D_, NKV_, 0, 0, 0, 0, 0);

    // ---- scores + fused exp ----
    gemm16<false, 0, false, true><<<dim3(S_ / 128, 1, B_ * H_), 256, GM_SMEM>>>(
        pq16, pkv16, nullptr, nullptr, nullptr, ps16,
        HD_, HD_, NKV_, S_, 0,
        (size_t)LP_ * HD_, (size_t)S_ * NKV_, (size_t)HD_, (size_t)LP_ * S_);

    // ---- row sums + head-mean a_score ----
    sum_mean<<<dim3(L_, B_), 256>>>(ps16, pinv, asc);

    // ---- (exp @ V) * inv -> ao fp16 (256-thread version) ----
    attn_v_mma<<<B_ * H_, 256, AV_SMEM>>>(ps16, pkv16, pinv, paoh);

    // ---- out-proj + residual t[l], LN2 ----
    gemm16<false, 2, true, false><<<dim3(D_ / 128, BL_ / 128, 1), 256, GM_SMEM>>>(
        paoh, pwo, bo, pt, px2, nullptr,
        D_, D_, D_, D_, L_, 0, 0, 0, 0);
    ln_rows<<<BL_, 256>>>(px2, ln2_g, ln2_b, pt2, 1.0f, pt2h);

    // ---- FFN ----
    gemm16<true, 0, true, false><<<dim3(D_ / 128, BL_ / 128, 1), 256, GM_SMEM>>>(
        pt2h, pw1, b1, nullptr, nullptr, pf1h,
        D_, D_, D_, D_, 0, 0, 0, 0, 0);
    gemm16<false, 1, true, false><<<dim3(D_ / 128, BL_ / 128, 1), 256, GM_SMEM>>>(
        pf1h, pw2, b2, pt2, px3, nullptr,
        D_, D_, D_, D_, 0, 0, 0, 0, 0);
    ln_rows<<<BL_, 256>>>(px3, ln3_g, ln3_b, ph, 1.0f, nullptr);

    // ---- GroupFC logits ----
    logits_kernel<<<dim3(L_, B_), 320>>>(ph, pdpT, pyt, out);
}

// round 15
// speedup vs baseline: 1.2485x; 1.0206x over previous
#include <cuda_runtime.h>
#include <cuda_fp16.h>
#include <math.h>
#include <stdint.h>

#define B_  32
#define S_  1024
#define F0_ 2048
#define D_  768
#define L_  100
#define H_  8
#define HD_ 96
#define DF_ 10
#define C_  1000
#define BL_ (B_*L_)   // 3200
#define BS_ (B_*S_)   // 32768
#define NKV_ 1536
#define LP_ 128       // L padded to 128

// ---------------- scratch (static __device__, zero-initialized) ----------------
static __device__ __align__(128) float g_t  [L_*D_];
static __device__ __align__(128) float g_x2 [(size_t)BL_*D_];
static __device__ __align__(128) float g_t2 [(size_t)BL_*D_];
static __device__ __align__(128) float g_x3 [(size_t)BL_*D_];
static __device__ __align__(128) float g_h  [(size_t)BL_*D_];
static __device__ __align__(128) float g_yt [C_];
static __device__ __align__(128) float g_bkv[NKV_];
static __device__ __align__(128) float g_inv[B_*H_*LP_];          // 1/rowsum of exp
static __device__ __align__(128) float g_dpT[(size_t)C_*2*D_];    // transposed dup_pool
static __device__ __align__(128) float g_ascdump[(size_t)B_*L_*S_];

// fp16 planes
static __device__ __align__(128) __half g_q16 [H_*LP_*HD_];
static __device__ __align__(128) __half g_s16 [(size_t)B_*H_*LP_*S_];  // exp(scores)
static __device__ __align__(128) __half g_kv16[(size_t)BS_*NKV_];      // k | v fp16, pitch 1536
static __device__ __align__(128) __half g_xh  [(size_t)BS_*F0_];
static __device__ __align__(128) __half g_memh[(size_t)BS_*D_];
static __device__ __align__(128) __half g_aoh [(size_t)BL_*D_];
static __device__ __align__(128) __half g_t2h [(size_t)BL_*D_];
static __device__ __align__(128) __half g_f1h [(size_t)BL_*D_];
static __device__ __align__(128) __half g_wemb[(size_t)D_*F0_];
static __device__ __align__(128) __half g_wkv [(size_t)NKV_*D_];
static __device__ __align__(128) __half g_wo  [(size_t)D_*D_];
static __device__ __align__(128) __half g_w1  [(size_t)D_*D_];
static __device__ __align__(128) __half g_w2  [(size_t)D_*D_];

// ============================================================================
// PTX helpers (sm_80-era baseline; safe on non-'a' compute_103 PTX target)
// ============================================================================
__device__ __forceinline__ uint32_t smem_u32(const void* p) {
    uint32_t a;
    asm("{ .reg .u64 t; cvta.to.shared.u64 t, %1; cvt.u32.u64 %0, t; }" : "=r"(a) : "l"(p));
    return a;
}
#define LDSM4(r, addr)                                                            \
    asm volatile("ldmatrix.sync.aligned.m8n8.x4.shared.b16 {%0,%1,%2,%3}, [%4];"  \
        : "=r"((r)[0]), "=r"((r)[1]), "=r"((r)[2]), "=r"((r)[3]) : "r"(addr))
#define LDSM2(r, addr)                                                            \
    asm volatile("ldmatrix.sync.aligned.m8n8.x2.shared.b16 {%0,%1}, [%2];"        \
        : "=r"((r)[0]), "=r"((r)[1]) : "r"(addr))
#define MMAF16(c, a, b0, b1)                                                      \
    asm volatile("mma.sync.aligned.m16n8k16.row.col.f32.f16.f16.f32 "             \
        "{%0,%1,%2,%3}, {%4,%5,%6,%7}, {%8,%9}, {%0,%1,%2,%3};"                   \
        : "+f"((c)[0]), "+f"((c)[1]), "+f"((c)[2]), "+f"((c)[3])                  \
        : "r"((a)[0]), "r"((a)[1]), "r"((a)[2]), "r"((a)[3]), "r"(b0), "r"(b1))
#define CP16(dst, src)                                                            \
    asm volatile("cp.async.cg.shared.global [%0], [%1], 16;" :: "r"(dst), "l"(src))
#define CP_COMMIT() asm volatile("cp.async.commit_group;" ::: "memory")
#define CP_WAIT(n)  asm volatile("cp.async.wait_group %0;" :: "n"(n) : "memory")

// swizzle for 64B logical rows packed 2-per-128B line (conflict-free ldmatrix)
__device__ __forceinline__ uint32_t swz_addr(uint32_t base, int r, int kb) {
    uint32_t line = (uint32_t)r >> 1;
    uint32_t slot = ((((uint32_t)r & 1u) << 2) | (uint32_t)kb) ^ (line & 7u);
    return base + line * 128u + slot * 16u;
}

// fast exp on FMA pipe; clamped so fp16 store cannot overflow
__device__ __forceinline__ float fexp(float x) {
    float p = x * 1.4426950408889634f;
    p = fmaxf(fminf(p, 15.5f), -120.0f);
    float nf = rintf(p);
    float f = p - nf;
    float r = 0.0013333558146428443f;
    r = fmaf(r, f, 0.009618129107628477f);
    r = fmaf(r, f, 0.05550410866482158f);
    r = fmaf(r, f, 0.2402265069591007f);
    r = fmaf(r, f, 0.6931471805599453f);
    r = fmaf(r, f, 1.0f);
    return r * __int_as_float(((int)nf + 127) << 23);
}

// ============================================================================
// 1-pass fp16 HMMA GEMM, 256 threads (2x4 warps), 2 CTAs/SM (16 warps/SM).
// MT: CTA M-tile 128 (warp tile 64x32) or 64 (warp tile 32x32, full-wave grids).
// 4-stage cp.async. C = act(A * B^T + bias [+ res]); strided; z-offsets.
// ============================================================================
template<int MT>
__device__ __forceinline__ void load_stage(uint32_t sbase,
    const __half* __restrict__ Ah, const __half* __restrict__ Bw,
    int bm, int bn, int lda, int ldb, int k0, int tid)
{
    if (MT == 128) {
        const int row = tid >> 1, kb0 = (tid & 1) * 2;
        const __half* pa = Ah + (size_t)(bm + row) * lda + k0 + kb0 * 8;
        CP16(swz_addr(sbase, row, kb0),     pa);
        CP16(swz_addr(sbase, row, kb0 + 1), pa + 8);
    } else {                       // MT == 64: 256 CP16, one per thread
        const int row = tid >> 2, kb = tid & 3;
        CP16(swz_addr(sbase, row, kb),
             Ah + (size_t)(bm + row) * lda + k0 + kb * 8);
    }
    const int brow = tid >> 1, bkb0 = (tid & 1) * 2;
    const __half* pb = Bw + (size_t)(bn + brow) * ldb + k0 + bkb0 * 8;
    CP16(swz_addr(sbase + (uint32_t)MT * 64u, brow, bkb0),     pb);
    CP16(swz_addr(sbase + (uint32_t)MT * 64u, brow, bkb0 + 1), pb + 8);
    CP_COMMIT();
}

template<int MT, bool RELU, int RES, bool BIAS, bool EXP>
__global__ void __launch_bounds__(256, 2)
gemm16(const __half* __restrict__ Ah, const __half* __restrict__ Bw,
       const float* __restrict__ bias, const float* __restrict__ Res,
       float* __restrict__ C, __half* __restrict__ Chi,
       int K, int lda, int ldb, int ldc, int resMod,
       size_t oAh, size_t oBb, size_t oBh, size_t oC)
{
    constexpr int NMT = MT / 32;
    constexpr uint32_t STG = (uint32_t)MT * 64u + 8192u;
    extern __shared__ char smem[];
    const uint32_t sb = smem_u32(smem);
    const int tid = threadIdx.x, lane = tid & 31, wid = tid >> 5;
    const int wm = wid >> 2, wn = wid & 3;          // 2 x 4 warps
    const int bm = blockIdx.y * MT, bn = blockIdx.x * 128;
    const int z = blockIdx.z, hz = z & 7, bz = z >> 3;
    Ah += (size_t)hz * oAh;
    Bw += (size_t)bz * oBb + (size_t)hz * oBh;
    const size_t coff = (size_t)z * oC;
    const int nc = K >> 5;

    float c[NMT][4][4];
    #pragma unroll
    for (int mt = 0; mt < NMT; mt++)
        #pragma unroll
        for (int nt = 0; nt < 4; nt++)
            #pragma unroll
            for (int q = 0; q < 4; q++) c[mt][nt][q] = 0.0f;

    uint32_t offA[NMT][2], offB[2][2];
    {
        const int aR = lane & 15, aKb = lane >> 4;
        const int bR = (lane & 7) | ((lane >> 4) << 3);
        const int bKb = (lane >> 3) & 1;
        #pragma unroll
        for (int mt = 0; mt < NMT; mt++)
            #pragma unroll
            for (int ks = 0; ks < 2; ks++)
                offA[mt][ks] = swz_addr(0, wm * (MT / 2) + mt * 16 + aR, ks * 2 + aKb);
        #pragma unroll
        for (int p = 0; p < 2; p++)
            #pragma unroll
            for (int ks = 0; ks < 2; ks++)
                offB[p][ks] = (uint32_t)MT * 64u +
                    swz_addr(0, wn * 32 + p * 16 + bR, ks * 2 + bKb);
    }

    #pragma unroll
    for (int s = 0; s < 3; s++)
        load_stage<MT>(sb + s * STG, Ah, Bw, bm, bn, lda, ldb, s * 32, tid);

    for (int i = 0; i < nc; i++) {
        CP_WAIT(2);
        __syncthreads();
        if (i + 3 < nc)
            load_stage<MT>(sb + (uint32_t)((i + 3) & 3) * STG, Ah, Bw,
                           bm, bn, lda, ldb, (i + 3) * 32, tid);
        else
            CP_COMMIT();     // keep group count exact (no tail race)
        const uint32_t st = sb + (uint32_t)(i & 3) * STG;
        #pragma unroll
        for (int ks = 0; ks < 2; ks++) {
            uint32_t aF[NMT][4], bf[2][4];
            #pragma unroll
            for (int mt = 0; mt < NMT; mt++) LDSM4(aF[mt], st + offA[mt][ks]);
            #pragma unroll
            for (int p = 0; p < 2; p++) LDSM4(bf[p], st + offB[p][ks]);
            #pragma unroll
            for (int mt = 0; mt < NMT; mt++)
                #pragma unroll
                for (int nt = 0; nt < 4; nt++)
                    MMAF16(c[mt][nt], aF[mt],
                           bf[nt >> 1][(nt & 1) * 2], bf[nt >> 1][(nt & 1) * 2 + 1]);
        }
    }

    #pragma unroll
    for (int mt = 0; mt < NMT; mt++) {
        #pragma unroll
        for (int hh = 0; hh < 2; hh++) {
            const int m = bm + wm * (MT / 2) + mt * 16 + (lane >> 2) + hh * 8;
            const float* resRow = (RES == 1) ? (Res + (size_t)m * ldc)
                                : (RES == 2) ? (Res + (size_t)(m % resMod) * ldc)
                                : nullptr;
            #pragma unroll
            for (int nt = 0; nt < 4; nt++) {
                const int n = bn + wn * 32 + nt * 8 + (lane & 3) * 2;
                float vx = c[mt][nt][hh * 2 + 0];
                float vy = c[mt][nt][hh * 2 + 1];
                if (BIAS) { vx += bias[n]; vy += bias[n + 1]; }
                if (RES != 0) { vx += resRow[n]; vy += resRow[n + 1]; }
                if (RELU) { vx = fmaxf(vx, 0.f); vy = fmaxf(vy, 0.f); }
                if (EXP)  { vx = fexp(vx); vy = fexp(vy); }
                if (C) *(float2*)(C + coff + (size_t)m * ldc + n) = make_float2(vx, vy);
                if (Chi)
                    *(__half2*)(Chi + coff + (size_t)m * ldc + n) = __floats2half2_rn(vx, vy);
            }
        }
    }
}

// ============================================================================
// attn_v, 256 threads (2x4 warps, warp tile 64x24, ldmatrix.x2 B)  [UNCHANGED]
// ============================================================================
#define AVS_A 8192u
#define AVS_V 6144u
#define AV_SMEM (4u*AVS_A + 2u*AVS_V)   // 45056

__global__ void __launch_bounds__(256, 2)
attn_v_mma(const __half* __restrict__ probs, const __half* __restrict__ kv16,
           const float* __restrict__ inv, __half* __restrict__ aoh)
{
    extern __shared__ char smem[];
    const uint32_t sb = smem_u32(smem);
    const int tid = threadIdx.x, lane = tid & 31, wid = tid >> 5;
    const int wm = wid >> 2, wn = wid & 3;
    const int bh = blockIdx.x, b = bh >> 3, h = bh & 7;
    const __half* A = probs + (size_t)bh * LP_ * S_;
    const __half* V = kv16 + (size_t)b * S_ * NKV_ + D_ + h * HD_;

    float c[4][3][4];
    #pragma unroll
    for (int mt = 0; mt < 4; mt++)
        #pragma unroll
        for (int nt = 0; nt < 3; nt++)
            #pragma unroll
            for (int q = 0; q < 4; q++) c[mt][nt][q] = 0.0f;

    uint32_t offA[4][2], offB[3][2];
    {
        const int aR = lane & 15, aKb = lane >> 4;
        #pragma unroll
        for (int mt = 0; mt < 4; mt++)
            #pragma unroll
            for (int ks = 0; ks < 2; ks++)
                offA[mt][ks] = swz_addr(0, wm * 64 + mt * 16 + aR, ks * 2 + aKb);
        const int bR = lane & 7;
        const int bKb = (lane >> 3) & 1;
        #pragma unroll
        for (int nb = 0; nb < 3; nb++)
            #pragma unroll
            for (int ks = 0; ks < 2; ks++)
                offB[nb][ks] = swz_addr(0, wn * 24 + nb * 8 + bR, ks * 2 + bKb);
    }

    int qs[3], qh[3];
    #pragma unroll
    for (int q = 0; q < 3; q++) {
        const int idx = tid + q * 256;
        qs[q] = (idx / 48) * 2;
        qh[q] = (idx % 48) * 2;
    }

    uint32_t vlo[3], vhi[3];
    const int nChunks = S_ / 32;
    const int arow = tid >> 1, akb0 = (tid & 1) * 2;

    #pragma unroll
    for (int s = 0; s < 3; s++) {
        const __half* pa = A + (size_t)arow * S_ + s * 32 + akb0 * 8;
        const uint32_t dst = sb + (uint32_t)s * AVS_A;
        CP16(swz_addr(dst, arow, akb0),     pa);
        CP16(swz_addr(dst, arow, akb0 + 1), pa + 8);
        CP_COMMIT();
    }
    {
        #pragma unroll
        for (int q = 0; q < 3; q++) {
            const __half* p = V + (size_t)qs[q] * NKV_ + qh[q];
            const uint32_t v0 = *(const uint32_t*)p;
            const uint32_t v1 = *(const uint32_t*)(p + NKV_);
            vlo[q] = __byte_perm(v0, v1, 0x5410);
            vhi[q] = __byte_perm(v0, v1, 0x7632);
        }
        char* vbuf = smem + 4 * AVS_A;
        #pragma unroll
        for (int q = 0; q < 3; q++) {
            const uint32_t o0 = swz_addr(0, qh[q],     qs[q] >> 3) + ((qs[q] * 2) & 15);
            const uint32_t o1 = swz_addr(0, qh[q] + 1, qs[q] >> 3) + ((qs[q] * 2) & 15);
            *(uint32_t*)(vbuf + o0) = vlo[q];
            *(uint32_t*)(vbuf + o1) = vhi[q];
        }
    }
    CP_WAIT(2);
    __syncthreads();

    for (int i = 0; i < nChunks; i++) {
        if (i + 1 < nChunks) {
            const int k0 = (i + 1) * 32;
            #pragma unroll
            for (int q = 0; q < 3; q++) {
                const __half* p = V + (size_t)(k0 + qs[q]) * NKV_ + qh[q];
                const uint32_t v0 = *(const uint32_t*)p;
                const uint32_t v1 = *(const uint32_t*)(p + NKV_);
                vlo[q] = __byte_perm(v0, v1, 0x5410);
                vhi[q] = __byte_perm(v0, v1, 0x7632);
            }
        }
        const uint32_t stA = sb + (uint32_t)(i & 3) * AVS_A;
        const uint32_t stV = sb + 4u * AVS_A + (uint32_t)(i & 1) * AVS_V;
        #pragma unroll
        for (int ks = 0; ks < 2; ks++) {
            uint32_t aF[4][4], bf[3][2];
            #pragma unroll
            for (int mt = 0; mt < 4; mt++) LDSM4(aF[mt], stA + offA[mt][ks]);
            #pragma unroll
            for (int nb = 0; nb < 3; nb++) LDSM2(bf[nb], stV + offB[nb][ks]);
            #pragma unroll
            for (int mt = 0; mt < 4; mt++)
                #pragma unroll
                for (int nt = 0; nt < 3; nt++)
                    MMAF16(c[mt][nt], aF[mt], bf[nt][0], bf[nt][1]);
        }
        if (i + 3 < nChunks) {
            const __half* pa = A + (size_t)arow * S_ + (i + 3) * 32 + akb0 * 8;
            const uint32_t dst = sb + (uint32_t)((i + 3) & 3) * AVS_A;
            CP16(swz_addr(dst, arow, akb0),     pa);
            CP16(swz_addr(dst, arow, akb0 + 1), pa + 8);
        }
        CP_COMMIT();
        if (i + 1 < nChunks) {
            char* vbuf = smem + 4 * AVS_A + ((i + 1) & 1) * AVS_V;
            #pragma unroll
            for (int q = 0; q < 3; q++) {
                const uint32_t o0 = swz_addr(0, qh[q],     qs[q] >> 3) + ((qs[q] * 2) & 15);
                const uint32_t o1 = swz_addr(0, qh[q] + 1, qs[q] >> 3) + ((qs[q] * 2) & 15);
                *(uint32_t*)(vbuf + o0) = vlo[q];
                *(uint32_t*)(vbuf + o1) = vhi[q];
            }
            CP_WAIT(2);
            __syncthreads();
        }
    }

    #pragma unroll
    for (int mt = 0; mt < 4; mt++) {
        #pragma unroll
        for (int hh = 0; hh < 2; hh++) {
            const int m = wm * 64 + mt * 16 + (lane >> 2) + hh * 8;
            if (m < L_) {
                const float sc = inv[bh * LP_ + m];
                __half* orow = aoh + ((size_t)b * L_ + m) * D_ + h * HD_;
                #pragma unroll
                for (int nt = 0; nt < 3; nt++) {
                    const int n = wn * 24 + nt * 8 + (lane & 3) * 2;
                    *(__half2*)(orow + n) = __floats2half2_rn(
                        c[mt][nt][hh * 2] * sc, c[mt][nt][hh * 2 + 1] * sc);
                }
            }
        }
    }
}

// ---------------- converters ----------------
__global__ void cvt_x16(const float* __restrict__ in, __half* __restrict__ out)
{
    const size_t base = (size_t)blockIdx.x * 256 + threadIdx.x;
    #pragma unroll
    for (int j = 0; j < 8; j++) {
        const size_t i = base + (size_t)j * 2097152;
        float4 f = ((const float4*)in)[i];
        ((__half2*)out)[2 * i]     = __floats2half2_rn(f.x, f.y);
        ((__half2*)out)[2 * i + 1] = __floats2half2_rn(f.z, f.w);
    }
}
__global__ void cvt_h16(const float* __restrict__ in, __half* __restrict__ out, int n4)
{
    int i = blockIdx.x * 256 + threadIdx.x;
    if (i >= n4) return;
    float4 f = ((const float4*)in)[i];
    ((__half2*)out)[i * 2 + 0] = __floats2half2_rn(f.x, f.y);
    ((__half2*)out)[i * 2 + 1] = __floats2half2_rn(f.z, f.w);
}
__global__ void cvt5(const float* __restrict__ s0, const float* __restrict__ s1,
                     const float* __restrict__ s2, const float* __restrict__ s3,
                     const float* __restrict__ s4,
                     __half* __restrict__ d0, __half* __restrict__ d1,
                     __half* __restrict__ d2, __half* __restrict__ d3,
                     __half* __restrict__ d4)
{
    const int m = blockIdx.y;
    const float* src = (m == 0) ? s0 : (m == 1) ? s1 : (m == 2) ? s2 : (m == 3) ? s3 : s4;
    __half* dst      = (m == 0) ? d0 : (m == 1) ? d1 : (m == 2) ? d2 : (m == 3) ? d3 : d4;
    const int base = blockIdx.x * 256 + threadIdx.x;
    #pragma unroll
    for (int j = 0; j < 4; j++) {
        const int i = base + j * 36864;
        float4 f = ((const float4*)src)[i];
        ((__half2*)dst)[2 * i]     = __floats2half2_rn(f.x, f.y);
        ((__half2*)dst)[2 * i + 1] = __floats2half2_rn(f.z, f.w);
    }
}
__global__ void concat_bias(const float* __restrict__ bk, const float* __restrict__ bv,
                            float* __restrict__ bkv)
{
    int i = blockIdx.x * 256 + threadIdx.x;
    if (i < D_) bkv[i] = bk[i];
    else if (i < NKV_) bkv[i] = bv[i - D_];
}
__global__ void transpose_dp(const float* __restrict__ dp, float* __restrict__ dpT)
{
    __shared__ float sm[384 * DF_];
    const int l = blockIdx.x, d0 = blockIdx.y * 384;
    const float* src = dp + (size_t)l * (2 * D_) * DF_ + (size_t)d0 * DF_;
    for (int i = threadIdx.x; i < 384 * DF_; i += 256) sm[i] = src[i];
    __syncthreads();
    for (int i = threadIdx.x; i < 384 * DF_; i += 256) {
        const int f = i / 384, d = i - f * 384;
        dpT[(size_t)(l * DF_ + f) * (2 * D_) + d0 + d] = sm[d * DF_ + f];
    }
}

// ---------------- block reduction ----------------
__device__ __forceinline__ float blockSum256(float v, float* sm) {
    #pragma unroll
    for (int o = 16; o > 0; o >>= 1) v += __shfl_xor_sync(0xffffffffu, v, o);
    const int w = threadIdx.x >> 5, lane = threadIdx.x & 31;
    if (lane == 0) sm[w] = v;
    __syncthreads();
    float r = (lane < 8) ? sm[lane] : 0.0f;
    #pragma unroll
    for (int o = 4; o > 0; o >>= 1) r += __shfl_xor_sync(0xffffffffu, r, o);
    r = __shfl_sync(0xffffffffu, r, 0);
    __syncthreads();
    return r;
}

// ---------------- row LayerNorm; optional fp16 output ----------------
__global__ void ln_rows(const float* __restrict__ X, const float* __restrict__ gg,
                        const float* __restrict__ bb, float* __restrict__ O, float alpha,
                        __half* __restrict__ Oh)
{
    __shared__ float sm[8];
    const int row = blockIdx.x;
    const float* x = X + (size_t)row * D_;
    float v[3];
    float s = 0.0f, sq = 0.0f;
    #pragma unroll
    for (int j = 0; j < 3; j++) {
        v[j] = alpha * x[threadIdx.x + j * 256];
        s += v[j]; sq += v[j] * v[j];
    }
    s  = blockSum256(s, sm);
    sq = blockSum256(sq, sm);
    const float mean = s * (1.0f / D_);
    const float var  = sq * (1.0f / D_) - mean * mean;
    const float inv  = rsqrtf(var + 1e-5f);
    float* o = O + (size_t)row * D_;
    #pragma unroll
    for (int j = 0; j < 3; j++) {
        const int i = threadIdx.x + j * 256;
        const float ov = (v[j] - mean) * inv * gg[i] + bb[i];
        o[i] = ov;
        if (Oh) Oh[(size_t)row * D_ + i] = __float2half_rn(ov);
    }
}

// ---------------- q projection -> fp16 padded [H][128][96], scale folded ----------------
__global__ void qproj(const float* __restrict__ t, const float* __restrict__ Wq,
                      const float* __restrict__ bq, __half* __restrict__ q16)
{
    const int l = blockIdx.x;
    const int e = blockIdx.y * 128 + threadIdx.x;
    __shared__ float ts[D_];
    for (int i = threadIdx.x; i < D_; i += 128) ts[i] = t[(size_t)l * D_ + i];
    __syncthreads();
    const float* w = Wq + (size_t)e * D_;
    float acc = 0.0f;
    #pragma unroll 8
    for (int d = 0; d < D_; d++) acc = fmaf(ts[d], w[d], acc);
    const float val = (acc + bq[e]) * 0.10206207261596575f;   // 1/sqrt(96)
    const int hh = e / HD_, eh = e - hh * HD_;
    q16[(size_t)hh * LP_ * HD_ + (size_t)l * HD_ + eh] = __float2half_rn(val);
}

// ---------------- inv only (critical path): warp-per-head row sums ----------------
__global__ void __launch_bounds__(256)
inv_kernel(const __half* __restrict__ s16, float* __restrict__ invO)
{
    const int l = blockIdx.x, b = blockIdx.y;
    const int w = threadIdx.x >> 5, lane = threadIdx.x & 31;
    const int bh = b * H_ + w;
    const int4* r4 = (const int4*)(s16 + ((size_t)bh * LP_ + l) * S_);
    float ssum = 0.0f;
    #pragma unroll
    for (int j = 0; j < 4; j++) {
        const int4 t = r4[lane + j * 32];
        const __half2* hp = (const __half2*)&t;
        #pragma unroll
        for (int k = 0; k < 4; k++) {
            float2 f = __half22float2(hp[k]);
            ssum += f.x + f.y;
        }
    }
    #pragma unroll
    for (int o = 16; o > 0; o >>= 1) ssum += __shfl_xor_sync(0xffffffffu, ssum, o);
    if (lane == 0) invO[bh * LP_ + l] = 1.0f / ssum;
}

// ---------------- a_score (side stream, overlapped): head-mean of normalized exp ----
__global__ void __launch_bounds__(256)
ascore_kernel(const __half* __restrict__ s16, const float* __restrict__ inv,
              float* __restrict__ ascore)
{
    const int l = blockIdx.x, b = blockIdx.y;
    const int tid = threadIdx.x;
    float w8[H_];
    #pragma unroll
    for (int h = 0; h < H_; h++) w8[h] = inv[(b * H_ + h) * LP_ + l] * 0.125f;
    float2* ao = (float2*)(ascore + ((size_t)b * L_ + l) * S_);
    #pragma unroll
    for (int j = 0; j < 2; j++) {
        const int sp2 = tid + j * 256;          // half2 index, covers 512*2=1024
        float ax = 0.0f, ay = 0.0f;
        #pragma unroll
        for (int h = 0; h < H_; h++) {
            const __half2 v = ((const __half2*)(s16 +
                ((size_t)(b * H_ + h) * LP_ + l) * S_))[sp2];
            const float2 f = __half22float2(v);
            ax = fmaf(f.x, w8[h], ax);
            ay = fmaf(f.y, w8[h], ay);
        }
        ao[sp2] = make_float2(ax, ay);
    }
}

// ---------------- GroupFC terms (float4 loads on transposed pool) ----------------
__global__ void yterm_kernel(const float* __restrict__ y, const float* __restrict__ dpT,
                             const float* __restrict__ dbias, float* __restrict__ yt)
{
    const int l = blockIdx.x;
    const int w = threadIdx.x >> 5, lane = threadIdx.x & 31;    // 10 warps
    const float4* row = (const float4*)(dpT + (size_t)(l * DF_ + w) * (2 * D_) + D_);
    const float4* yr  = (const float4*)(y + (size_t)l * D_);
    float acc = 0.0f;
    #pragma unroll
    for (int it = 0; it < 6; it++) {
        const float4 a = yr[lane + it * 32];
        const float4 bb = row[lane + it * 32];
        acc = fmaf(a.x, bb.x, acc); acc = fmaf(a.y, bb.y, acc);
        acc = fmaf(a.z, bb.z, acc); acc = fmaf(a.w, bb.w, acc);
    }
    #pragma unroll
    for (int o = 16; o > 0; o >>= 1) acc += __shfl_xor_sync(0xffffffffu, acc, o);
    if (lane == 0) yt[l * DF_ + w] = acc + dbias[l * DF_ + w];
}

__global__ void logits_kernel(const float* __restrict__ hh, const float* __restrict__ dpT,
                              const float* __restrict__ yt, float* __restrict__ out)
{
    const int l = blockIdx.x, b = blockIdx.y;
    const int w = threadIdx.x >> 5, lane = threadIdx.x & 31;    // 10 warps
    __shared__ float hs[D_];
    for (int i = threadIdx.x; i < D_; i += 320) hs[i] = hh[((size_t)b * L_ + l) * D_ + i];
    __syncthreads();
    const float4* row = (const float4*)(dpT + (size_t)(l * DF_ + w) * (2 * D_));
    const float4* hv  = (const float4*)hs;
    float acc = 0.0f;
    #pragma unroll
    for (int it = 0; it < 6; it++) {
        const float4 a = hv[lane + it * 32];
        const float4 bb = row[lane + it * 32];
        acc = fmaf(a.x, bb.x, acc); acc = fmaf(a.y, bb.y, acc);
        acc = fmaf(a.z, bb.z, acc); acc = fmaf(a.w, bb.w, acc);
    }
    #pragma unroll
    for (int o = 16; o > 0; o >>= 1) acc += __shfl_xor_sync(0xffffffffu, acc, o);
    if (lane == 0) out[(size_t)b * C_ + l * DF_ + w] = acc + yt[l * DF_ + w];
}

// ---------------- host launch ----------------
#define GM_SMEM_128 65536u
#define GM_SMEM_64  49152u

extern "C" void kernel_launch(void* const* d_in, const int* in_sizes, int n_in,
                              void* d_out, int out_size)
{
    const float* x       = (const float*)d_in[0];
    const float* y       = (const float*)d_in[1];
    const float* embed_W = (const float*)d_in[2];
    const float* embed_b = (const float*)d_in[3];
    const float* Wq      = (const float*)d_in[4];
    const float* Wk      = (const float*)d_in[5];
    const float* Wv      = (const float*)d_in[6];
    const float* bq      = (const float*)d_in[7];
    const float* bk      = (const float*)d_in[8];
    const float* bv      = (const float*)d_in[9];
    const float* Wo      = (const float*)d_in[10];
    const float* bo      = (const float*)d_in[11];
    const float* ln1_g   = (const float*)d_in[12];
    const float* ln1_b   = (const float*)d_in[13];
    const float* ln2_g   = (const float*)d_in[14];
    const float* ln2_b   = (const float*)d_in[15];
    const float* ln3_g   = (const float*)d_in[16];
    const float* ln3_b   = (const float*)d_in[17];
    const float* W1      = (const float*)d_in[18];
    const float* b1      = (const float*)d_in[19];
    const float* W2      = (const float*)d_in[20];
    const float* b2      = (const float*)d_in[21];
    const float* dp      = (const float*)d_in[22];
    const float* dbias   = (const float*)d_in[23];
    float* out = (float*)d_out;

    float *pt, *px2, *pt2, *px3, *ph, *pyt, *pbkv, *pinv, *pdpT, *pdump;
    __half *pq16, *ps16, *pkv16, *pxh, *pmemh, *paoh, *pt2h, *pf1h;
    __half *pwemb, *pwkv, *pwo, *pw1, *pw2;
    cudaGetSymbolAddress((void**)&pt,    g_t);
    cudaGetSymbolAddress((void**)&px2,   g_x2);
    cudaGetSymbolAddress((void**)&pt2,   g_t2);
    cudaGetSymbolAddress((void**)&px3,   g_x3);
    cudaGetSymbolAddress((void**)&ph,    g_h);
    cudaGetSymbolAddress((void**)&pyt,   g_yt);
    cudaGetSymbolAddress((void**)&pbkv,  g_bkv);
    cudaGetSymbolAddress((void**)&pinv,  g_inv);
    cudaGetSymbolAddress((void**)&pdpT,  g_dpT);
    cudaGetSymbolAddress((void**)&pdump, g_ascdump);
    cudaGetSymbolAddress((void**)&pq16,  g_q16);
    cudaGetSymbolAddress((void**)&ps16,  g_s16);
    cudaGetSymbolAddress((void**)&pkv16, g_kv16);
    cudaGetSymbolAddress((void**)&pxh,   g_xh);
    cudaGetSymbolAddress((void**)&pmemh, g_memh);
    cudaGetSymbolAddress((void**)&paoh,  g_aoh);
    cudaGetSymbolAddress((void**)&pt2h,  g_t2h);
    cudaGetSymbolAddress((void**)&pf1h,  g_f1h);
    cudaGetSymbolAddress((void**)&pwemb, g_wemb);
    cudaGetSymbolAddress((void**)&pwkv,  g_wkv);
    cudaGetSymbolAddress((void**)&pwo,   g_wo);
    cudaGetSymbolAddress((void**)&pw1,   g_w1);
    cudaGetSymbolAddress((void**)&pw2,   g_w2);

    cudaFuncSetAttribute(gemm16<128, true, 0, true, false>,  cudaFuncAttributeMaxDynamicSharedMemorySize, GM_SMEM_128);
    cudaFuncSetAttribute(gemm16<128, false, 0, true, false>, cudaFuncAttributeMaxDynamicSharedMemorySize, GM_SMEM_128);
    cudaFuncSetAttribute(gemm16<128, false, 0, false, true>, cudaFuncAttributeMaxDynamicSharedMemorySize, GM_SMEM_128);
    cudaFuncSetAttribute(gemm16<64, false, 2, true, false>,  cudaFuncAttributeMaxDynamicSharedMemorySize, GM_SMEM_64);
    cudaFuncSetAttribute(gemm16<64, true, 0, true, false>,   cudaFuncAttributeMaxDynamicSharedMemorySize, GM_SMEM_64);
    cudaFuncSetAttribute(gemm16<64, false, 1, true, false>,  cudaFuncAttributeMaxDynamicSharedMemorySize, GM_SMEM_64);
    cudaFuncSetAttribute(attn_v_mma, cudaFuncAttributeMaxDynamicSharedMemorySize, AV_SMEM);

    float* asc = (out_size >= B_ * C_ + B_ * L_ * S_) ? (out + B_ * C_) : pdump;

    static cudaStream_t sS = nullptr;
    static cudaEvent_t evF = nullptr, evJ = nullptr, evF2 = nullptr, evJ2 = nullptr;
    if (sS == nullptr) {
        cudaStreamCreateWithFlags(&sS, cudaStreamNonBlocking);
        cudaEventCreateWithFlags(&evF,  cudaEventDisableTiming);
        cudaEventCreateWithFlags(&evJ,  cudaEventDisableTiming);
        cudaEventCreateWithFlags(&evF2, cudaEventDisableTiming);
        cudaEventCreateWithFlags(&evJ2, cudaEventDisableTiming);
    }

    // ---- fork 1: preamble on side stream ----
    cudaEventRecord(evF, 0);
    cudaStreamWaitEvent(sS, evF, 0);
    cvt5<<<dim3(144, 5), 256, 0, sS>>>(Wk, Wv, Wo, W1, W2,
                                       pwkv, pwkv + (size_t)D_ * D_, pwo, pw1, pw2);
    concat_bias<<<(NKV_ + 255) / 256, 256, 0, sS>>>(bk, bv, pbkv);
    transpose_dp<<<dim3(L_, 4), 256, 0, sS>>>(dp, pdpT);
    ln_rows<<<L_, 256, 0, sS>>>(y, ln1_g, ln1_b, pt, 2.0f, nullptr);       // t = LN(2y)
    qproj<<<dim3(L_, D_ / 128), 128, 0, sS>>>(pt, Wq, bq, pq16);
    yterm_kernel<<<L_, 320, 0, sS>>>(y, pdpT, dbias, pyt);
    cudaEventRecord(evJ, sS);

    // ---- main: embed critical path ----
    cvt_x16<<<8192, 256>>>(x, pxh);
    cvt_h16<<<(D_ * F0_ / 4 + 255) / 256, 256>>>(embed_W, pwemb, D_ * F0_ / 4);
    gemm16<128, true, 0, true, false><<<dim3(D_ / 128, BS_ / 128, 1), 256, GM_SMEM_128>>>(
        pxh, pwemb, embed_b, nullptr, nullptr, pmemh,
        F0_, F0_, F0_, D_, 0, 0, 0, 0, 0);

    cudaStreamWaitEvent(0, evJ, 0);    // join 1

    // ---- fused K|V GEMM -> fp16 kv (pitch 1536) ----
    gemm16<128, false, 0, true, false><<<dim3(NKV_ / 128, BS_ / 128, 1), 256, GM_SMEM_128>>>(
        pmemh, pwkv, pbkv, nullptr, nullptr, pkv16,
        D_, D_, D_, NKV_, 0, 0, 0, 0, 0);

    // ---- scores + fused exp ----
    gemm16<128, false, 0, false, true><<<dim3(S_ / 128, 1, B_ * H_), 256, GM_SMEM_128>>>(
        pq16, pkv16, nullptr, nullptr, nullptr, ps16,
        HD_, HD_, NKV_, S_, 0,
        (size_t)LP_ * HD_, (size_t)S_ * NKV_, (size_t)HD_, (size_t)LP_ * S_);

    // ---- row sums only (critical path) ----
    inv_kernel<<<dim3(L_, B_), 256>>>(ps16, pinv);

    // ---- fork 2: a_score on side stream, overlapped with attn_v + small GEMMs ----
    cudaEventRecord(evF2, 0);
    cudaStreamWaitEvent(sS, evF2, 0);
    ascore_kernel<<<dim3(L_, B_), 256, 0, sS>>>(ps16, pinv, asc);
    cudaEventRecord(evJ2, sS);

    // ---- (exp @ V) * inv -> ao fp16 ----
    attn_v_mma<<<B_ * H_, 256, AV_SMEM>>>(ps16, pkv16, pinv, paoh);

    // ---- out-proj + residual t[l], LN2 (MT=64 -> 300-CTA full wave) ----
    gemm16<64, false, 2, true, false><<<dim3(D_ / 128, BL_ / 64, 1), 256, GM_SMEM_64>>>(
        paoh, pwo, bo, pt, px2, nullptr,
        D_, D_, D_, D_, L_, 0, 0, 0, 0);
    ln_rows<<<BL_, 256>>>(px2, ln2_g, ln2_b, pt2, 1.0f, pt2h);

    // ---- FFN (MT=64) ----
    gemm16<64, true, 0, true, false><<<dim3(D_ / 128, BL_ / 64, 1), 256, GM_SMEM_64>>>(
        pt2h, pw1, b1, nullptr, nullptr, pf1h,
        D_, D_, D_, D_, 0, 0, 0, 0, 0);
    gemm16<64, false, 1, true, false><<<dim3(D_ / 128, BL_ / 64, 1), 256, GM_SMEM_64>>>(
        pf1h, pw2, b2, pt2, px3, nullptr,
        D_, D_, D_, D_, 0, 0, 0, 0, 0);
    ln_rows<<<BL_, 256>>>(px3, ln3_g, ln3_b, ph, 1.0f, nullptr);

    cudaStreamWaitEvent(0, evJ2, 0);   // join 2 (before final output kernel)

    // ---- GroupFC logits ----
    logits_kernel<<<dim3(L_, B_), 320>>>(ph, pdpT, pyt, out);
}

// round 16
// speedup vs baseline: 1.2952x; 1.0374x over previous
#include <cuda_runtime.h>
#include <cuda_fp16.h>
#include <math.h>
#include <stdint.h>

#define B_  32
#define S_  1024
#define F0_ 2048
#define D_  768
#define L_  100
#define H_  8
#define HD_ 96
#define DF_ 10
#define C_  1000
#define BL_ (B_*L_)   // 3200
#define BS_ (B_*S_)   // 32768
#define NKV_ 1536
#define LP_ 128       // L padded to 128
#define MHALF_ 16384  // embed M-split

// ---------------- scratch (static __device__, zero-initialized) ----------------
static __device__ __align__(128) float g_t  [L_*D_];
static __device__ __align__(128) float g_x2 [(size_t)BL_*D_];
static __device__ __align__(128) float g_t2 [(size_t)BL_*D_];
static __device__ __align__(128) float g_x3 [(size_t)BL_*D_];
static __device__ __align__(128) float g_h  [(size_t)BL_*D_];
static __device__ __align__(128) float g_yt [C_];
static __device__ __align__(128) float g_bkv[NKV_];
static __device__ __align__(128) float g_sums[B_*H_*LP_];         // rowsum of exp (atomic)
static __device__ __align__(128) float g_dpT[(size_t)C_*2*D_];    // transposed dup_pool
static __device__ __align__(128) float g_ascdump[(size_t)B_*L_*S_];

// fp16 planes
static __device__ __align__(128) __half g_q16 [H_*LP_*HD_];
static __device__ __align__(128) __half g_s16 [(size_t)B_*H_*LP_*S_];  // exp(scores)
static __device__ __align__(128) __half g_kv16[(size_t)BS_*NKV_];      // k | v fp16, pitch 1536
static __device__ __align__(128) __half g_xh  [(size_t)BS_*F0_];
static __device__ __align__(128) __half g_memh[(size_t)BS_*D_];
static __device__ __align__(128) __half g_aoh [(size_t)BL_*D_];
static __device__ __align__(128) __half g_t2h [(size_t)BL_*D_];
static __device__ __align__(128) __half g_f1h [(size_t)BL_*D_];
static __device__ __align__(128) __half g_wemb[(size_t)D_*F0_];
static __device__ __align__(128) __half g_wkv [(size_t)NKV_*D_];
static __device__ __align__(128) __half g_wo  [(size_t)D_*D_];
static __device__ __align__(128) __half g_w1  [(size_t)D_*D_];
static __device__ __align__(128) __half g_w2  [(size_t)D_*D_];

// ============================================================================
// PTX helpers (sm_80-era baseline; safe on non-'a' compute_103 PTX target)
// ============================================================================
__device__ __forceinline__ uint32_t smem_u32(const void* p) {
    uint32_t a;
    asm("{ .reg .u64 t; cvta.to.shared.u64 t, %1; cvt.u32.u64 %0, t; }" : "=r"(a) : "l"(p));
    return a;
}
#define LDSM4(r, addr)                                                            \
    asm volatile("ldmatrix.sync.aligned.m8n8.x4.shared.b16 {%0,%1,%2,%3}, [%4];"  \
        : "=r"((r)[0]), "=r"((r)[1]), "=r"((r)[2]), "=r"((r)[3]) : "r"(addr))
#define LDSM2(r, addr)                                                            \
    asm volatile("ldmatrix.sync.aligned.m8n8.x2.shared.b16 {%0,%1}, [%2];"        \
        : "=r"((r)[0]), "=r"((r)[1]) : "r"(addr))
#define MMAF16(c, a, b0, b1)                                                      \
    asm volatile("mma.sync.aligned.m16n8k16.row.col.f32.f16.f16.f32 "             \
        "{%0,%1,%2,%3}, {%4,%5,%6,%7}, {%8,%9}, {%0,%1,%2,%3};"                   \
        : "+f"((c)[0]), "+f"((c)[1]), "+f"((c)[2]), "+f"((c)[3])                  \
        : "r"((a)[0]), "r"((a)[1]), "r"((a)[2]), "r"((a)[3]), "r"(b0), "r"(b1))
#define CP16(dst, src)                                                            \
    asm volatile("cp.async.cg.shared.global [%0], [%1], 16;" :: "r"(dst), "l"(src))
#define CP_COMMIT() asm volatile("cp.async.commit_group;" ::: "memory")
#define CP_WAIT(n)  asm volatile("cp.async.wait_group %0;" :: "n"(n) : "memory")

// swizzle for 64B logical rows packed 2-per-128B line (conflict-free ldmatrix)
__device__ __forceinline__ uint32_t swz_addr(uint32_t base, int r, int kb) {
    uint32_t line = (uint32_t)r >> 1;
    uint32_t slot = ((((uint32_t)r & 1u) << 2) | (uint32_t)kb) ^ (line & 7u);
    return base + line * 128u + slot * 16u;
}

// fast exp on FMA pipe; clamped so fp16 store cannot overflow
__device__ __forceinline__ float fexp(float x) {
    float p = x * 1.4426950408889634f;
    p = fmaxf(fminf(p, 15.5f), -120.0f);
    float nf = rintf(p);
    float f = p - nf;
    float r = 0.0013333558146428443f;
    r = fmaf(r, f, 0.009618129107628477f);
    r = fmaf(r, f, 0.05550410866482158f);
    r = fmaf(r, f, 0.2402265069591007f);
    r = fmaf(r, f, 0.6931471805599453f);
    r = fmaf(r, f, 1.0f);
    return r * __int_as_float(((int)nf + 127) << 23);
}

// ============================================================================
// 1-pass fp16 HMMA GEMM, 256 threads (2x4 warps), 2 CTAs/SM (16 warps/SM).
// MT: CTA M-tile 128 or 64. 4-stage cp.async. EXP epilogue optionally
// accumulates per-row sums of exp into Sums[z*LP + m] via atomicAdd.
// ============================================================================
template<int MT>
__device__ __forceinline__ void load_stage(uint32_t sbase,
    const __half* __restrict__ Ah, const __half* __restrict__ Bw,
    int bm, int bn, int lda, int ldb, int k0, int tid)
{
    if (MT == 128) {
        const int row = tid >> 1, kb0 = (tid & 1) * 2;
        const __half* pa = Ah + (size_t)(bm + row) * lda + k0 + kb0 * 8;
        CP16(swz_addr(sbase, row, kb0),     pa);
        CP16(swz_addr(sbase, row, kb0 + 1), pa + 8);
    } else {                       // MT == 64
        const int row = tid >> 2, kb = tid & 3;
        CP16(swz_addr(sbase, row, kb),
             Ah + (size_t)(bm + row) * lda + k0 + kb * 8);
    }
    const int brow = tid >> 1, bkb0 = (tid & 1) * 2;
    const __half* pb = Bw + (size_t)(bn + brow) * ldb + k0 + bkb0 * 8;
    CP16(swz_addr(sbase + (uint32_t)MT * 64u, brow, bkb0),     pb);
    CP16(swz_addr(sbase + (uint32_t)MT * 64u, brow, bkb0 + 1), pb + 8);
    CP_COMMIT();
}

template<int MT, bool RELU, int RES, bool BIAS, bool EXP>
__global__ void __launch_bounds__(256, 2)
gemm16(const __half* __restrict__ Ah, const __half* __restrict__ Bw,
       const float* __restrict__ bias, const float* __restrict__ Res,
       float* __restrict__ C, __half* __restrict__ Chi,
       int K, int lda, int ldb, int ldc, int resMod,
       size_t oAh, size_t oBb, size_t oBh, size_t oC, float* Sums)
{
    constexpr int NMT = MT / 32;
    constexpr uint32_t STG = (uint32_t)MT * 64u + 8192u;
    extern __shared__ char smem[];
    const uint32_t sb = smem_u32(smem);
    const int tid = threadIdx.x, lane = tid & 31, wid = tid >> 5;
    const int wm = wid >> 2, wn = wid & 3;          // 2 x 4 warps
    const int bm = blockIdx.y * MT, bn = blockIdx.x * 128;
    const int z = blockIdx.z, hz = z & 7, bz = z >> 3;
    Ah += (size_t)hz * oAh;
    Bw += (size_t)bz * oBb + (size_t)hz * oBh;
    const size_t coff = (size_t)z * oC;
    const int nc = K >> 5;

    float c[NMT][4][4];
    #pragma unroll
    for (int mt = 0; mt < NMT; mt++)
        #pragma unroll
        for (int nt = 0; nt < 4; nt++)
            #pragma unroll
            for (int q = 0; q < 4; q++) c[mt][nt][q] = 0.0f;

    uint32_t offA[NMT][2], offB[2][2];
    {
        const int aR = lane & 15, aKb = lane >> 4;
        const int bR = (lane & 7) | ((lane >> 4) << 3);
        const int bKb = (lane >> 3) & 1;
        #pragma unroll
        for (int mt = 0; mt < NMT; mt++)
            #pragma unroll
            for (int ks = 0; ks < 2; ks++)
                offA[mt][ks] = swz_addr(0, wm * (MT / 2) + mt * 16 + aR, ks * 2 + aKb);
        #pragma unroll
        for (int p = 0; p < 2; p++)
            #pragma unroll
            for (int ks = 0; ks < 2; ks++)
                offB[p][ks] = (uint32_t)MT * 64u +
                    swz_addr(0, wn * 32 + p * 16 + bR, ks * 2 + bKb);
    }

    #pragma unroll
    for (int s = 0; s < 3; s++)
        load_stage<MT>(sb + s * STG, Ah, Bw, bm, bn, lda, ldb, s * 32, tid);

    for (int i = 0; i < nc; i++) {
        CP_WAIT(2);
        __syncthreads();
        if (i + 3 < nc)
            load_stage<MT>(sb + (uint32_t)((i + 3) & 3) * STG, Ah, Bw,
                           bm, bn, lda, ldb, (i + 3) * 32, tid);
        else
            CP_COMMIT();     // keep group count exact (no tail race)
        const uint32_t st = sb + (uint32_t)(i & 3) * STG;
        #pragma unroll
        for (int ks = 0; ks < 2; ks++) {
            uint32_t aF[NMT][4], bf[2][4];
            #pragma unroll
            for (int mt = 0; mt < NMT; mt++) LDSM4(aF[mt], st + offA[mt][ks]);
            #pragma unroll
            for (int p = 0; p < 2; p++) LDSM4(bf[p], st + offB[p][ks]);
            #pragma unroll
            for (int mt = 0; mt < NMT; mt++)
                #pragma unroll
                for (int nt = 0; nt < 4; nt++)
                    MMAF16(c[mt][nt], aF[mt],
                           bf[nt >> 1][(nt & 1) * 2], bf[nt >> 1][(nt & 1) * 2 + 1]);
        }
    }

    #pragma unroll
    for (int mt = 0; mt < NMT; mt++) {
        #pragma unroll
        for (int hh = 0; hh < 2; hh++) {
            const int m = bm + wm * (MT / 2) + mt * 16 + (lane >> 2) + hh * 8;
            const float* resRow = (RES == 1) ? (Res + (size_t)m * ldc)
                                : (RES == 2) ? (Res + (size_t)(m % resMod) * ldc)
                                : nullptr;
            float rowp = 0.0f;
            #pragma unroll
            for (int nt = 0; nt < 4; nt++) {
                const int n = bn + wn * 32 + nt * 8 + (lane & 3) * 2;
                float vx = c[mt][nt][hh * 2 + 0];
                float vy = c[mt][nt][hh * 2 + 1];
                if (BIAS) { vx += bias[n]; vy += bias[n + 1]; }
                if (RES != 0) { vx += resRow[n]; vy += resRow[n + 1]; }
                if (RELU) { vx = fmaxf(vx, 0.f); vy = fmaxf(vy, 0.f); }
                if (EXP)  { vx = fexp(vx); vy = fexp(vy); rowp += vx + vy; }
                if (C) *(float2*)(C + coff + (size_t)m * ldc + n) = make_float2(vx, vy);
                if (Chi)
                    *(__half2*)(Chi + coff + (size_t)m * ldc + n) = __floats2half2_rn(vx, vy);
            }
            if (EXP) {
                // reduce across the 4 quad lanes that share row m
                rowp += __shfl_xor_sync(0xffffffffu, rowp, 1);
                rowp += __shfl_xor_sync(0xffffffffu, rowp, 2);
                if ((lane & 3) == 0)
                    atomicAdd(Sums + (size_t)z * LP_ + m, rowp);
            }
        }
    }
}

// ============================================================================
// attn_v, 256 threads (2x4 warps, warp tile 64x24, ldmatrix.x2 B)
// scale by 1/sums in epilogue
// ============================================================================
#define AVS_A 8192u
#define AVS_V 6144u
#define AV_SMEM (4u*AVS_A + 2u*AVS_V)   // 45056

__global__ void __launch_bounds__(256, 2)
attn_v_mma(const __half* __restrict__ probs, const __half* __restrict__ kv16,
           const float* __restrict__ sums, __half* __restrict__ aoh)
{
    extern __shared__ char smem[];
    const uint32_t sb = smem_u32(smem);
    const int tid = threadIdx.x, lane = tid & 31, wid = tid >> 5;
    const int wm = wid >> 2, wn = wid & 3;
    const int bh = blockIdx.x, b = bh >> 3, h = bh & 7;
    const __half* A = probs + (size_t)bh * LP_ * S_;
    const __half* V = kv16 + (size_t)b * S_ * NKV_ + D_ + h * HD_;

    float c[4][3][4];
    #pragma unroll
    for (int mt = 0; mt < 4; mt++)
        #pragma unroll
        for (int nt = 0; nt < 3; nt++)
            #pragma unroll
            for (int q = 0; q < 4; q++) c[mt][nt][q] = 0.0f;

    uint32_t offA[4][2], offB[3][2];
    {
        const int aR = lane & 15, aKb = lane >> 4;
        #pragma unroll
        for (int mt = 0; mt < 4; mt++)
            #pragma unroll
            for (int ks = 0; ks < 2; ks++)
                offA[mt][ks] = swz_addr(0, wm * 64 + mt * 16 + aR, ks * 2 + aKb);
        const int bR = lane & 7;
        const int bKb = (lane >> 3) & 1;
        #pragma unroll
        for (int nb = 0; nb < 3; nb++)
            #pragma unroll
            for (int ks = 0; ks < 2; ks++)
                offB[nb][ks] = swz_addr(0, wn * 24 + nb * 8 + bR, ks * 2 + bKb);
    }

    int qs[3], qh[3];
    #pragma unroll
    for (int q = 0; q < 3; q++) {
        const int idx = tid + q * 256;
        qs[q] = (idx / 48) * 2;
        qh[q] = (idx % 48) * 2;
    }

    uint32_t vlo[3], vhi[3];
    const int nChunks = S_ / 32;
    const int arow = tid >> 1, akb0 = (tid & 1) * 2;

    #pragma unroll
    for (int s = 0; s < 3; s++) {
        const __half* pa = A + (size_t)arow * S_ + s * 32 + akb0 * 8;
        const uint32_t dst = sb + (uint32_t)s * AVS_A;
        CP16(swz_addr(dst, arow, akb0),     pa);
        CP16(swz_addr(dst, arow, akb0 + 1), pa + 8);
        CP_COMMIT();
    }
    {
        #pragma unroll
        for (int q = 0; q < 3; q++) {
            const __half* p = V + (size_t)qs[q] * NKV_ + qh[q];
            const uint32_t v0 = *(const uint32_t*)p;
            const uint32_t v1 = *(const uint32_t*)(p + NKV_);
            vlo[q] = __byte_perm(v0, v1, 0x5410);
            vhi[q] = __byte_perm(v0, v1, 0x7632);
        }
        char* vbuf = smem + 4 * AVS_A;
        #pragma unroll
        for (int q = 0; q < 3; q++) {
            const uint32_t o0 = swz_addr(0, qh[q],     qs[q] >> 3) + ((qs[q] * 2) & 15);
            const uint32_t o1 = swz_addr(0, qh[q] + 1, qs[q] >> 3) + ((qs[q] * 2) & 15);
            *(uint32_t*)(vbuf + o0) = vlo[q];
            *(uint32_t*)(vbuf + o1) = vhi[q];
        }
    }
    CP_WAIT(2);
    __syncthreads();

    for (int i = 0; i < nChunks; i++) {
        if (i + 1 < nChunks) {
            const int k0 = (i + 1) * 32;
            #pragma unroll
            for (int q = 0; q < 3; q++) {
                const __half* p = V + (size_t)(k0 + qs[q]) * NKV_ + qh[q];
                const uint32_t v0 = *(const uint32_t*)p;
                const uint32_t v1 = *(const uint32_t*)(p + NKV_);
                vlo[q] = __byte_perm(v0, v1, 0x5410);
                vhi[q] = __byte_perm(v0, v1, 0x7632);
            }
        }
        const uint32_t stA = sb + (uint32_t)(i & 3) * AVS_A;
        const uint32_t stV = sb + 4u * AVS_A + (uint32_t)(i & 1) * AVS_V;
        #pragma unroll
        for (int ks = 0; ks < 2; ks++) {
            uint32_t aF[4][4], bf[3][2];
            #pragma unroll
            for (int mt = 0; mt < 4; mt++) LDSM4(aF[mt], stA + offA[mt][ks]);
            #pragma unroll
            for (int nb = 0; nb < 3; nb++) LDSM2(bf[nb], stV + offB[nb][ks]);
            #pragma unroll
            for (int mt = 0; mt < 4; mt++)
                #pragma unroll
                for (int nt = 0; nt < 3; nt++)
                    MMAF16(c[mt][nt], aF[mt], bf[nt][0], bf[nt][1]);
        }
        if (i + 3 < nChunks) {
            const __half* pa = A + (size_t)arow * S_ + (i + 3) * 32 + akb0 * 8;
            const uint32_t dst = sb + (uint32_t)((i + 3) & 3) * AVS_A;
            CP16(swz_addr(dst, arow, akb0),     pa);
            CP16(swz_addr(dst, arow, akb0 + 1), pa + 8);
        }
        CP_COMMIT();
        if (i + 1 < nChunks) {
            char* vbuf = smem + 4 * AVS_A + ((i + 1) & 1) * AVS_V;
            #pragma unroll
            for (int q = 0; q < 3; q++) {
                const uint32_t o0 = swz_addr(0, qh[q],     qs[q] >> 3) + ((qs[q] * 2) & 15);
                const uint32_t o1 = swz_addr(0, qh[q] + 1, qs[q] >> 3) + ((qs[q] * 2) & 15);
                *(uint32_t*)(vbuf + o0) = vlo[q];
                *(uint32_t*)(vbuf + o1) = vhi[q];
            }
            CP_WAIT(2);
            __syncthreads();
        }
    }

    #pragma unroll
    for (int mt = 0; mt < 4; mt++) {
        #pragma unroll
        for (int hh = 0; hh < 2; hh++) {
            const int m = wm * 64 + mt * 16 + (lane >> 2) + hh * 8;
            if (m < L_) {
                const float sc = 1.0f / sums[bh * LP_ + m];
                __half* orow = aoh + ((size_t)b * L_ + m) * D_ + h * HD_;
                #pragma unroll
                for (int nt = 0; nt < 3; nt++) {
                    const int n = wn * 24 + nt * 8 + (lane & 3) * 2;
                    *(__half2*)(orow + n) = __floats2half2_rn(
                        c[mt][nt][hh * 2] * sc, c[mt][nt][hh * 2 + 1] * sc);
                }
            }
        }
    }
}

// ---------------- converters ----------------
// converts nblk*256*8 float4 starting at float4 index off
__global__ void cvt_x16(const float* __restrict__ in, __half* __restrict__ out, size_t off)
{
    const size_t base = off + (size_t)blockIdx.x * 256 + threadIdx.x;
    const size_t stride = (size_t)gridDim.x * 256;
    #pragma unroll
    for (int j = 0; j < 8; j++) {
        const size_t i = base + (size_t)j * stride;
        float4 f = ((const float4*)in)[i];
        ((__half2*)out)[2 * i]     = __floats2half2_rn(f.x, f.y);
        ((__half2*)out)[2 * i + 1] = __floats2half2_rn(f.z, f.w);
    }
}
__global__ void cvt_h16(const float* __restrict__ in, __half* __restrict__ out, int n4)
{
    int i = blockIdx.x * 256 + threadIdx.x;
    if (i >= n4) return;
    float4 f = ((const float4*)in)[i];
    ((__half2*)out)[i * 2 + 0] = __floats2half2_rn(f.x, f.y);
    ((__half2*)out)[i * 2 + 1] = __floats2half2_rn(f.z, f.w);
}
__global__ void cvt5(const float* __restrict__ s0, const float* __restrict__ s1,
                     const float* __restrict__ s2, const float* __restrict__ s3,
                     const float* __restrict__ s4,
                     __half* __restrict__ d0, __half* __restrict__ d1,
                     __half* __restrict__ d2, __half* __restrict__ d3,
                     __half* __restrict__ d4)
{
    const int m = blockIdx.y;
    const float* src = (m == 0) ? s0 : (m == 1) ? s1 : (m == 2) ? s2 : (m == 3) ? s3 : s4;
    __half* dst      = (m == 0) ? d0 : (m == 1) ? d1 : (m == 2) ? d2 : (m == 3) ? d3 : d4;
    const int base = blockIdx.x * 256 + threadIdx.x;
    #pragma unroll
    for (int j = 0; j < 4; j++) {
        const int i = base + j * 36864;
        float4 f = ((const float4*)src)[i];
        ((__half2*)dst)[2 * i]     = __floats2half2_rn(f.x, f.y);
        ((__half2*)dst)[2 * i + 1] = __floats2half2_rn(f.z, f.w);
    }
}
__global__ void concat_bias(const float* __restrict__ bk, const float* __restrict__ bv,
                            float* __restrict__ bkv)
{
    int i = blockIdx.x * 256 + threadIdx.x;
    if (i < D_) bkv[i] = bk[i];
    else if (i < NKV_) bkv[i] = bv[i - D_];
}
__global__ void zero_sums(float* __restrict__ s)
{
    s[blockIdx.x * 256 + threadIdx.x] = 0.0f;   // grid 128 x 256 = 32768
}
__global__ void transpose_dp(const float* __restrict__ dp, float* __restrict__ dpT)
{
    __shared__ float sm[384 * DF_];
    const int l = blockIdx.x, d0 = blockIdx.y * 384;
    const float* src = dp + (size_t)l * (2 * D_) * DF_ + (size_t)d0 * DF_;
    for (int i = threadIdx.x; i < 384 * DF_; i += 256) sm[i] = src[i];
    __syncthreads();
    for (int i = threadIdx.x; i < 384 * DF_; i += 256) {
        const int f = i / 384, d = i - f * 384;
        dpT[(size_t)(l * DF_ + f) * (2 * D_) + d0 + d] = sm[d * DF_ + f];
    }
}

// ---------------- block reduction ----------------
__device__ __forceinline__ float blockSum256(float v, float* sm) {
    #pragma unroll
    for (int o = 16; o > 0; o >>= 1) v += __shfl_xor_sync(0xffffffffu, v, o);
    const int w = threadIdx.x >> 5, lane = threadIdx.x & 31;
    if (lane == 0) sm[w] = v;
    __syncthreads();
    float r = (lane < 8) ? sm[lane] : 0.0f;
    #pragma unroll
    for (int o = 4; o > 0; o >>= 1) r += __shfl_xor_sync(0xffffffffu, r, o);
    r = __shfl_sync(0xffffffffu, r, 0);
    __syncthreads();
    return r;
}

// ---------------- row LayerNorm; optional fp16 output ----------------
__global__ void ln_rows(const float* __restrict__ X, const float* __restrict__ gg,
                        const float* __restrict__ bb, float* __restrict__ O, float alpha,
                        __half* __restrict__ Oh)
{
    __shared__ float sm[8];
    const int row = blockIdx.x;
    const float* x = X + (size_t)row * D_;
    float v[3];
    float s = 0.0f, sq = 0.0f;
    #pragma unroll
    for (int j = 0; j < 3; j++) {
        v[j] = alpha * x[threadIdx.x + j * 256];
        s += v[j]; sq += v[j] * v[j];
    }
    s  = blockSum256(s, sm);
    sq = blockSum256(sq, sm);
    const float mean = s * (1.0f / D_);
    const float var  = sq * (1.0f / D_) - mean * mean;
    const float inv  = rsqrtf(var + 1e-5f);
    float* o = O + (size_t)row * D_;
    #pragma unroll
    for (int j = 0; j < 3; j++) {
        const int i = threadIdx.x + j * 256;
        const float ov = (v[j] - mean) * inv * gg[i] + bb[i];
        o[i] = ov;
        if (Oh) Oh[(size_t)row * D_ + i] = __float2half_rn(ov);
    }
}

// ---------------- q projection -> fp16 padded [H][128][96], scale folded ----------------
__global__ void qproj(const float* __restrict__ t, const float* __restrict__ Wq,
                      const float* __restrict__ bq, __half* __restrict__ q16)
{
    const int l = blockIdx.x;
    const int e = blockIdx.y * 128 + threadIdx.x;
    __shared__ float ts[D_];
    for (int i = threadIdx.x; i < D_; i += 128) ts[i] = t[(size_t)l * D_ + i];
    __syncthreads();
    const float* w = Wq + (size_t)e * D_;
    float acc = 0.0f;
    #pragma unroll 8
    for (int d = 0; d < D_; d++) acc = fmaf(ts[d], w[d], acc);
    const float val = (acc + bq[e]) * 0.10206207261596575f;   // 1/sqrt(96)
    const int hh = e / HD_, eh = e - hh * HD_;
    q16[(size_t)hh * LP_ * HD_ + (size_t)l * HD_ + eh] = __float2half_rn(val);
}

// ---------------- a_score (side stream): head-mean of normalized exp ----------------
__global__ void __launch_bounds__(256)
ascore_kernel(const __half* __restrict__ s16, const float* __restrict__ sums,
              float* __restrict__ ascore)
{
    const int l = blockIdx.x, b = blockIdx.y;
    const int tid = threadIdx.x;
    float w8[H_];
    #pragma unroll
    for (int h = 0; h < H_; h++) w8[h] = 0.125f / sums[(b * H_ + h) * LP_ + l];
    float2* ao = (float2*)(ascore + ((size_t)b * L_ + l) * S_);
    #pragma unroll
    for (int j = 0; j < 2; j++) {
        const int sp2 = tid + j * 256;
        float ax = 0.0f, ay = 0.0f;
        #pragma unroll
        for (int h = 0; h < H_; h++) {
            const __half2 v = ((const __half2*)(s16 +
                ((size_t)(b * H_ + h) * LP_ + l) * S_))[sp2];
            const float2 f = __half22float2(v);
            ax = fmaf(f.x, w8[h], ax);
            ay = fmaf(f.y, w8[h], ay);
        }
        ao[sp2] = make_float2(ax, ay);
    }
}

// ---------------- GroupFC terms (float4 loads on transposed pool) ----------------
__global__ void yterm_kernel(const float* __restrict__ y, const float* __restrict__ dpT,
                             const float* __restrict__ dbias, float* __restrict__ yt)
{
    const int l = blockIdx.x;
    const int w = threadIdx.x >> 5, lane = threadIdx.x & 31;    // 10 warps
    const float4* row = (const float4*)(dpT + (size_t)(l * DF_ + w) * (2 * D_) + D_);
    const float4* yr  = (const float4*)(y + (size_t)l * D_);
    float acc = 0.0f;
    #pragma unroll
    for (int it = 0; it < 6; it++) {
        const float4 a = yr[lane + it * 32];
        const float4 bb = row[lane + it * 32];
        acc = fmaf(a.x, bb.x, acc); acc = fmaf(a.y, bb.y, acc);
        acc = fmaf(a.z, bb.z, acc); acc = fmaf(a.w, bb.w, acc);
    }
    #pragma unroll
    for (int o = 16; o > 0; o >>= 1) acc += __shfl_xor_sync(0xffffffffu, acc, o);
    if (lane == 0) yt[l * DF_ + w] = acc + dbias[l * DF_ + w];
}

__global__ void logits_kernel(const float* __restrict__ hh, const float* __restrict__ dpT,
                              const float* __restrict__ yt, float* __restrict__ out)
{
    const int l = blockIdx.x, b = blockIdx.y;
    const int w = threadIdx.x >> 5, lane = threadIdx.x & 31;    // 10 warps
    __shared__ float hs[D_];
    for (int i = threadIdx.x; i < D_; i += 320) hs[i] = hh[((size_t)b * L_ + l) * D_ + i];
    __syncthreads();
    const float4* row = (const float4*)(dpT + (size_t)(l * DF_ + w) * (2 * D_));
    const float4* hv  = (const float4*)hs;
    float acc = 0.0f;
    #pragma unroll
    for (int it = 0; it < 6; it++) {
        const float4 a = hv[lane + it * 32];
        const float4 bb = row[lane + it * 32];
        acc = fmaf(a.x, bb.x, acc); acc = fmaf(a.y, bb.y, acc);
        acc = fmaf(a.z, bb.z, acc); acc = fmaf(a.w, bb.w, acc);
    }
    #pragma unroll
    for (int o = 16; o > 0; o >>= 1) acc += __shfl_xor_sync(0xffffffffu, acc, o);
    if (lane == 0) out[(size_t)b * C_ + l * DF_ + w] = acc + yt[l * DF_ + w];
}

// ---------------- host launch ----------------
#define GM_SMEM_128 65536u
#define GM_SMEM_64  49152u

extern "C" void kernel_launch(void* const* d_in, const int* in_sizes, int n_in,
                              void* d_out, int out_size)
{
    const float* x       = (const float*)d_in[0];
    const float* y       = (const float*)d_in[1];
    const float* embed_W = (const float*)d_in[2];
    const float* embed_b = (const float*)d_in[3];
    const float* Wq      = (const float*)d_in[4];
    const float* Wk      = (const float*)d_in[5];
    const float* Wv      = (const float*)d_in[6];
    const float* bq      = (const float*)d_in[7];
    const float* bk      = (const float*)d_in[8];
    const float* bv      = (const float*)d_in[9];
    const float* Wo      = (const float*)d_in[10];
    const float* bo      = (const float*)d_in[11];
    const float* ln1_g   = (const float*)d_in[12];
    const float* ln1_b   = (const float*)d_in[13];
    const float* ln2_g   = (const float*)d_in[14];
    const float* ln2_b   = (const float*)d_in[15];
    const float* ln3_g   = (const float*)d_in[16];
    const float* ln3_b   = (const float*)d_in[17];
    const float* W1      = (const float*)d_in[18];
    const float* b1      = (const float*)d_in[19];
    const float* W2      = (const float*)d_in[20];
    const float* b2      = (const float*)d_in[21];
    const float* dp      = (const float*)d_in[22];
    const float* dbias   = (const float*)d_in[23];
    float* out = (float*)d_out;

    float *pt, *px2, *pt2, *px3, *ph, *pyt, *pbkv, *psums, *pdpT, *pdump;
    __half *pq16, *ps16, *pkv16, *pxh, *pmemh, *paoh, *pt2h, *pf1h;
    __half *pwemb, *pwkv, *pwo, *pw1, *pw2;
    cudaGetSymbolAddress((void**)&pt,    g_t);
    cudaGetSymbolAddress((void**)&px2,   g_x2);
    cudaGetSymbolAddress((void**)&pt2,   g_t2);
    cudaGetSymbolAddress((void**)&px3,   g_x3);
    cudaGetSymbolAddress((void**)&ph,    g_h);
    cudaGetSymbolAddress((void**)&pyt,   g_yt);
    cudaGetSymbolAddress((void**)&pbkv,  g_bkv);
    cudaGetSymbolAddress((void**)&psums, g_sums);
    cudaGetSymbolAddress((void**)&pdpT,  g_dpT);
    cudaGetSymbolAddress((void**)&pdump, g_ascdump);
    cudaGetSymbolAddress((void**)&pq16,  g_q16);
    cudaGetSymbolAddress((void**)&ps16,  g_s16);
    cudaGetSymbolAddress((void**)&pkv16, g_kv16);
    cudaGetSymbolAddress((void**)&pxh,   g_xh);
    cudaGetSymbolAddress((void**)&pmemh, g_memh);
    cudaGetSymbolAddress((void**)&paoh,  g_aoh);
    cudaGetSymbolAddress((void**)&pt2h,  g_t2h);
    cudaGetSymbolAddress((void**)&pf1h,  g_f1h);
    cudaGetSymbolAddress((void**)&pwemb, g_wemb);
    cudaGetSymbolAddress((void**)&pwkv,  g_wkv);
    cudaGetSymbolAddress((void**)&pwo,   g_wo);
    cudaGetSymbolAddress((void**)&pw1,   g_w1);
    cudaGetSymbolAddress((void**)&pw2,   g_w2);

    cudaFuncSetAttribute(gemm16<128, true, 0, true, false>,  cudaFuncAttributeMaxDynamicSharedMemorySize, GM_SMEM_128);
    cudaFuncSetAttribute(gemm16<128, false, 0, true, false>, cudaFuncAttributeMaxDynamicSharedMemorySize, GM_SMEM_128);
    cudaFuncSetAttribute(gemm16<128, false, 0, false, true>, cudaFuncAttributeMaxDynamicSharedMemorySize, GM_SMEM_128);
    cudaFuncSetAttribute(gemm16<64, false, 2, true, false>,  cudaFuncAttributeMaxDynamicSharedMemorySize, GM_SMEM_64);
    cudaFuncSetAttribute(gemm16<64, true, 0, true, false>,   cudaFuncAttributeMaxDynamicSharedMemorySize, GM_SMEM_64);
    cudaFuncSetAttribute(gemm16<64, false, 1, true, false>,  cudaFuncAttributeMaxDynamicSharedMemorySize, GM_SMEM_64);
    cudaFuncSetAttribute(attn_v_mma, cudaFuncAttributeMaxDynamicSharedMemorySize, AV_SMEM);

    float* asc = (out_size >= B_ * C_ + B_ * L_ * S_) ? (out + B_ * C_) : pdump;

    static cudaStream_t sS = nullptr, sX = nullptr;
    static cudaEvent_t evF = nullptr, evJ = nullptr, evF2 = nullptr, evJ2 = nullptr;
    static cudaEvent_t evX = nullptr, evJX = nullptr;
    if (sS == nullptr) {
        cudaStreamCreateWithFlags(&sS, cudaStreamNonBlocking);
        cudaStreamCreateWithFlags(&sX, cudaStreamNonBlocking);
        cudaEventCreateWithFlags(&evF,  cudaEventDisableTiming);
        cudaEventCreateWithFlags(&evJ,  cudaEventDisableTiming);
        cudaEventCreateWithFlags(&evF2, cudaEventDisableTiming);
        cudaEventCreateWithFlags(&evJ2, cudaEventDisableTiming);
        cudaEventCreateWithFlags(&evX,  cudaEventDisableTiming);
        cudaEventCreateWithFlags(&evJX, cudaEventDisableTiming);
    }

    // ---- fork 1: preamble on side stream sS ----
    cudaEventRecord(evF, 0);
    cudaStreamWaitEvent(sS, evF, 0);
    zero_sums<<<128, 256, 0, sS>>>(psums);
    cvt5<<<dim3(144, 5), 256, 0, sS>>>(Wk, Wv, Wo, W1, W2,
                                       pwkv, pwkv + (size_t)D_ * D_, pwo, pw1, pw2);
    concat_bias<<<(NKV_ + 255) / 256, 256, 0, sS>>>(bk, bv, pbkv);
    transpose_dp<<<dim3(L_, 4), 256, 0, sS>>>(dp, pdpT);
    ln_rows<<<L_, 256, 0, sS>>>(y, ln1_g, ln1_b, pt, 2.0f, nullptr);       // t = LN(2y)
    qproj<<<dim3(L_, D_ / 128), 128, 0, sS>>>(pt, Wq, bq, pq16);
    yterm_kernel<<<L_, 320, 0, sS>>>(y, pdpT, dbias, pyt);
    cudaEventRecord(evJ, sS);

    // ---- main: embed critical path, M-split pipelined with x conversion ----
    cvt_h16<<<(D_ * F0_ / 4 + 255) / 256, 256>>>(embed_W, pwemb, D_ * F0_ / 4);
    cvt_x16<<<4096, 256>>>(x, pxh, 0);                       // half 0
    cudaEventRecord(evX, 0);
    // side stream sX converts half 1 while embed(half 0) runs
    cudaStreamWaitEvent(sX, evX, 0);
    cvt_x16<<<4096, 256, 0, sX>>>(x, pxh, (size_t)MHALF_ * F0_ / 4);
    cudaEventRecord(evJX, sX);

    gemm16<128, true, 0, true, false><<<dim3(D_ / 128, MHALF_ / 128, 1), 256, GM_SMEM_128>>>(
        pxh, pwemb, embed_b, nullptr, nullptr, pmemh,
        F0_, F0_, F0_, D_, 0, 0, 0, 0, 0, nullptr);

    cudaStreamWaitEvent(0, evJX, 0);
    gemm16<128, true, 0, true, false><<<dim3(D_ / 128, MHALF_ / 128, 1), 256, GM_SMEM_128>>>(
        pxh + (size_t)MHALF_ * F0_, pwemb, embed_b, nullptr, nullptr,
        pmemh + (size_t)MHALF_ * D_,
        F0_, F0_, F0_, D_, 0, 0, 0, 0, 0, nullptr);

    cudaStreamWaitEvent(0, evJ, 0);    // join 1

    // ---- fused K|V GEMM -> fp16 kv (pitch 1536) ----
    gemm16<128, false, 0, true, false><<<dim3(NKV_ / 128, BS_ / 128, 1), 256, GM_SMEM_128>>>(
        pmemh, pwkv, pbkv, nullptr, nullptr, pkv16,
        D_, D_, D_, NKV_, 0, 0, 0, 0, 0, nullptr);

    // ---- scores + fused exp + fused row sums (atomic) ----
    gemm16<128, false, 0, false, true><<<dim3(S_ / 128, 1, B_ * H_), 256, GM_SMEM_128>>>(
        pq16, pkv16, nullptr, nullptr, nullptr, ps16,
        HD_, HD_, NKV_, S_, 0,
        (size_t)LP_ * HD_, (size_t)S_ * NKV_, (size_t)HD_, (size_t)LP_ * S_, psums);

    // ---- fork 2: a_score on side stream, overlapped with attn_v + small GEMMs ----
    cudaEventRecord(evF2, 0);
    cudaStreamWaitEvent(sS, evF2, 0);
    ascore_kernel<<<dim3(L_, B_), 256, 0, sS>>>(ps16, psums, asc);
    cudaEventRecord(evJ2, sS);

    // ---- (exp @ V) / sums -> ao fp16 ----
    attn_v_mma<<<B_ * H_, 256, AV_SMEM>>>(ps16, pkv16, psums, paoh);

    // ---- out-proj + residual t[l], LN2 (MT=64 full wave) ----
    gemm16<64, false, 2, true, false><<<dim3(D_ / 128, BL_ / 64, 1), 256, GM_SMEM_64>>>(
        paoh, pwo, bo, pt, px2, nullptr,
        D_, D_, D_, D_, L_, 0, 0, 0, 0, nullptr);
    ln_rows<<<BL_, 256>>>(px2, ln2_g, ln2_b, pt2, 1.0f, pt2h);

    // ---- FFN (MT=64) ----
    gemm16<64, true, 0, true, false><<<dim3(D_ / 128, BL_ / 64, 1), 256, GM_SMEM_64>>>(
        pt2h, pw1, b1, nullptr, nullptr, pf1h,
        D_, D_, D_, D_, 0, 0, 0, 0, 0, nullptr);
    gemm16<64, false, 1, true, false><<<dim3(D_ / 128, BL_ / 64, 1), 256, GM_SMEM_64>>>(
        pf1h, pw2, b2, pt2, px3, nullptr,
        D_, D_, D_, D_, 0, 0, 0, 0, 0, nullptr);
    ln_rows<<<BL_, 256>>>(px3, ln3_g, ln3_b, ph, 1.0f, nullptr);

    cudaStreamWaitEvent(0, evJ2, 0);   // join 2

    // ---- GroupFC logits ----
    logits_kernel<<<dim3(L_, B_), 320>>>(ph, pdpT, pyt, out);
}